// round 3
// baseline (speedup 1.0000x reference)
#include <cuda_runtime.h>
#include <math.h>
#include <stdint.h>

#define BB 8
#define NSEQ 1024
#define CDIM 768
#define NH 12
#define HD 64
#define SCALE 0.125f
#define BNEPS 1e-5f
#define OUT_OFF (BB*NSEQ*CDIM)
#define NN ((size_t)NSEQ*NSEQ)

// ---------------- scratch (device globals) -----------------------------------
__device__ float  g_q[BB*NH*NSEQ*HD];          // scaled by SCALE
__device__ float  g_k[BB*NH*NSEQ*HD];
__device__ float  g_vt[BB*NH*HD*NSEQ];         // transposed: [bh][d][m]
__device__ float  g_logits[BB*NH*NSEQ*NSEQ];   // 402 MB
__device__ double g_s1[NH];
__device__ double g_s2[NH];
__device__ float  g_bna[NH];
__device__ float  g_bnc[NH];
__device__ float  g_t[BB*NSEQ*CDIM];           // attn@v in (B,N,C) layout

// ---------------- helpers -----------------------------------------------------
__device__ __forceinline__ uint32_t f2tf(float x){
    uint32_t r; asm("cvt.rna.tf32.f32 %0, %1;" : "=r"(r) : "f"(x)); return r;
}
__device__ __forceinline__ void mma8(float* c, const uint32_t* a, const uint32_t* b){
    asm volatile("mma.sync.aligned.m16n8k8.row.col.f32.tf32.tf32.f32 "
        "{%0,%1,%2,%3}, {%4,%5,%6,%7}, {%8,%9}, {%0,%1,%2,%3};"
        : "+f"(c[0]), "+f"(c[1]), "+f"(c[2]), "+f"(c[3])
        : "r"(a[0]), "r"(a[1]), "r"(a[2]), "r"(a[3]), "r"(b[0]), "r"(b[1]));
}

// convert float4 (4 consecutive k of one row) to tf32 hi/lo, exchange halves
// with partner lane (tid^1), store 2 x STS.128 into S[row] at kstep ks.
// parity: 0 = this thread holds k'=0..3 of the kstep, 1 = k'=4..7.
// layout: S row base (uint4*), entry [ks*4 + tig] = {h(tig), h(tig+4), l(tig), l(tig+4)}
__device__ __forceinline__ void cvt_store(float4 v, uint4* rowbase, int ks, int parity){
    uint32_t h0=f2tf(v.x), h1=f2tf(v.y), h2=f2tf(v.z), h3=f2tf(v.w);
    uint32_t l0=f2tf(v.x-__uint_as_float(h0));
    uint32_t l1=f2tf(v.y-__uint_as_float(h1));
    uint32_t l2=f2tf(v.z-__uint_as_float(h2));
    uint32_t l3=f2tf(v.w-__uint_as_float(h3));
    uint32_t sa = parity ? h0 : h2;
    uint32_t sb = parity ? h1 : h3;
    uint32_t sc = parity ? l0 : l2;
    uint32_t sd = parity ? l1 : l3;
    uint32_t ra = __shfl_xor_sync(0xffffffffu, sa, 1);
    uint32_t rb = __shfl_xor_sync(0xffffffffu, sb, 1);
    uint32_t rc = __shfl_xor_sync(0xffffffffu, sc, 1);
    uint32_t rd = __shfl_xor_sync(0xffffffffu, sd, 1);
    uint4* p = rowbase + ks*4 + parity*2;
    uint4 q0, q1;
    if (!parity) {
        q0.x=h0; q0.y=ra; q0.z=l0; q0.w=rc;
        q1.x=h1; q1.y=rb; q1.z=l1; q1.w=rd;
    } else {
        q0.x=ra; q0.y=h2; q0.z=rc; q0.w=l2;
        q1.x=rb; q1.y=h3; q1.z=rd; q1.w=l3;
    }
    p[0] = q0; p[1] = q1;
}

__global__ void k_init(){ int t = threadIdx.x; if (t < NH){ g_s1[t]=0.0; g_s2[t]=0.0; } }

// ---------------- unified tf32x3 GEMM: C[M,N] = A[M,K] * B[N,K]^T -------------
// MODE 0: qkv   A=x[8192,768]      B=w_qkv[2304,768]  -> scatter q/k/vt (+bias, q*SCALE)
// MODE 1: qk    A=g_q[bh]          B=g_k[bh]  K=64    -> g_logits[bh]
// MODE 2: av    A=attn[bh] (raw!)  B=g_vt[bh] K=1024  -> g_t ; normalizes A on load + writeback
// MODE 3: proj  A=g_t[8192,768]    B=w_proj[768,768]  -> d_out (+bias)
template<int BN, int MODE>
__global__ __launch_bounds__(256, 2) void gemm_k(
    const float* __restrict__ pA, const float* __restrict__ pB,
    const float* __restrict__ bias, float* __restrict__ pC)
{
    constexpr int BM = 128, LDR = 12;                  // row stride in uint4
    constexpr int NT = (BN/2)/8, MT = 2;
    constexpr int K     = (MODE==1) ? 64 : (MODE==2) ? 1024 : 768;
    constexpr int LD_G  = (MODE==1) ? 64 : (MODE==2) ? 1024 : 768;

    __shared__ __align__(16) uint4 As[BM*LDR];
    __shared__ __align__(16) uint4 Bs[BN*LDR];

    const int tid  = threadIdx.x;
    const int lane = tid & 31, warp = tid >> 5;
    const int wm = warp >> 1, wn = warp & 1;          // 4 x 2 warp grid
    const int gid = lane >> 2, tig = lane & 3;
    const int Mblk = blockIdx.y * BM;
    const int Nblk = blockIdx.x * BN;
    const int bh   = blockIdx.z;

    const float* Asrc; const float* Bsrc;
    if constexpr (MODE == 0)      { Asrc = pA; Bsrc = pB; }
    else if constexpr (MODE == 1) { Asrc = g_q + (size_t)bh*NSEQ*HD; Bsrc = g_k + (size_t)bh*NSEQ*HD; }
    else if constexpr (MODE == 2) { Asrc = pA + (size_t)bh*NN; Bsrc = g_vt + (size_t)bh*HD*NSEQ; }
    else                          { Asrc = g_t; Bsrc = pB; }

    float na = 0.f, nc = 0.f;
    if constexpr (MODE == 2) { int g = bh % NH; na = g_bna[g]; nc = g_bnc[g]; }

    const int ar = tid >> 2;            // 0..63
    const int ac = (tid & 3) << 2;      // 0,4,8,12
    const int sks = (tid & 3) >> 1;     // kstep of my slice
    const int spar = tid & 1;           // parity (k' 0-3 vs 4-7)
    const float* agp0 = Asrc + (size_t)(Mblk + ar) * LD_G + ac;
    const float* agp1 = agp0 + (size_t)64 * LD_G;
    const float* bgp0 = Bsrc + (size_t)(Nblk + ar) * LD_G + ac;
    const float* bgp1 = bgp0 + (size_t)64 * LD_G;   // only used when BN==128

    float4 ra0, ra1, rb0, rb1;
    ra0 = *(const float4*)agp0;
    ra1 = *(const float4*)agp1;
    rb0 = *(const float4*)bgp0;
    if constexpr (BN == 128) rb1 = *(const float4*)bgp1;

    float acc[MT][NT][4] = {};

    for (int k0 = 0; k0 < K; k0 += 16) {
        if constexpr (MODE == 2) {
            // normalize + stream writeback (each attn element touched exactly once)
            ra0.x = fmaf(na, ra0.x, nc); ra0.y = fmaf(na, ra0.y, nc);
            ra0.z = fmaf(na, ra0.z, nc); ra0.w = fmaf(na, ra0.w, nc);
            ra1.x = fmaf(na, ra1.x, nc); ra1.y = fmaf(na, ra1.y, nc);
            ra1.z = fmaf(na, ra1.z, nc); ra1.w = fmaf(na, ra1.w, nc);
            __stcs((float4*)(agp0 + k0), ra0);
            __stcs((float4*)(agp1 + k0), ra1);
        }
        cvt_store(ra0, &As[(size_t)ar*LDR],       sks, spar);
        cvt_store(ra1, &As[(size_t)(ar+64)*LDR],  sks, spar);
        cvt_store(rb0, &Bs[(size_t)ar*LDR],       sks, spar);
        if constexpr (BN == 128)
            cvt_store(rb1, &Bs[(size_t)(ar+64)*LDR], sks, spar);
        __syncthreads();
        if (k0 + 16 < K) {
            ra0 = *(const float4*)(agp0 + k0 + 16);
            ra1 = *(const float4*)(agp1 + k0 + 16);
            rb0 = *(const float4*)(bgp0 + k0 + 16);
            if constexpr (BN == 128) rb1 = *(const float4*)(bgp1 + k0 + 16);
        }
        #pragma unroll
        for (int ks = 0; ks < 2; ks++) {
            uint4 a0[MT], a1[MT];
            #pragma unroll
            for (int i = 0; i < MT; i++) {
                int mb = wm*32 + i*16 + gid;
                a0[i] = As[mb*LDR + ks*4 + tig];
                a1[i] = As[(mb+8)*LDR + ks*4 + tig];
            }
            #pragma unroll
            for (int j = 0; j < NT; j++) {
                int nb = wn*(BN/2) + j*8 + gid;
                uint4 bv = Bs[nb*LDR + ks*4 + tig];
                uint32_t bhh[2] = {bv.x, bv.y};
                uint32_t bll[2] = {bv.z, bv.w};
                #pragma unroll
                for (int i = 0; i < MT; i++) {
                    uint32_t ah[4] = {a0[i].x, a1[i].x, a0[i].y, a1[i].y};
                    uint32_t al[4] = {a0[i].z, a1[i].z, a0[i].w, a1[i].w};
                    mma8(acc[i][j], ah, bhh);
                    mma8(acc[i][j], al, bhh);
                    mma8(acc[i][j], ah, bll);
                }
            }
        }
        __syncthreads();
    }

    // ----------------- epilogue -----------------
    #pragma unroll
    for (int i = 0; i < MT; i++) {
        #pragma unroll
        for (int j = 0; j < NT; j++) {
            const float* c = acc[i][j];
            int r0 = Mblk + wm*32 + i*16 + gid;
            int c0 = Nblk + wn*(BN/2) + j*8 + tig*2;
            #pragma unroll
            for (int p = 0; p < 2; p++) {
                int row = r0 + p*8;
                float v0 = c[p*2+0], v1 = c[p*2+1];
                if constexpr (MODE == 0) {
                    int t3 = c0 / CDIM; int rem = c0 - t3*CDIM;
                    int h = rem >> 6, d = rem & 63;
                    int b = row >> 10, n = row & (NSEQ-1);
                    float b0 = bias[c0], b1 = bias[c0+1];
                    if (t3 == 0) {
                        float2 s = make_float2((v0+b0)*SCALE, (v1+b1)*SCALE);
                        *(float2*)(g_q + ((((size_t)(b*NH+h))*NSEQ + n)<<6) + d) = s;
                    } else if (t3 == 1) {
                        float2 s = make_float2(v0+b0, v1+b1);
                        *(float2*)(g_k + ((((size_t)(b*NH+h))*NSEQ + n)<<6) + d) = s;
                    } else {
                        size_t base = (((size_t)(b*NH+h))*HD + d)*NSEQ + n;
                        g_vt[base]        = v0+b0;
                        g_vt[base + NSEQ] = v1+b1;
                    }
                } else if constexpr (MODE == 1) {
                    float2 s = make_float2(v0, v1);
                    __stcs((float2*)(g_logits + (size_t)bh*NN + (size_t)row*NSEQ + c0), s);
                } else if constexpr (MODE == 2) {
                    int b = bh / NH, g = bh % NH;
                    float2 s = make_float2(v0, v1);
                    *(float2*)(g_t + ((size_t)b*NSEQ + row)*CDIM + g*HD + c0) = s;
                } else {
                    float2 s = make_float2(v0 + bias[c0], v1 + bias[c0+1]);
                    *(float2*)(pC + (size_t)row*CDIM + c0) = s;
                }
            }
        }
    }
}

// ---------------- fused softmax + 12x12 head mix + BN stats ------------------
// one block per (b,n); 512 threads; thread t owns float2 at m = 2t; RAW mixed out
__global__ __launch_bounds__(512) void k_mix(const float* __restrict__ w_re,
                      const float* __restrict__ b_re, float* __restrict__ dout) {
    __shared__ float wre[NH][NH];
    __shared__ float bre[NH], smax[NH], sinv[NH];
    __shared__ float red[NH][16];
    __shared__ float sm1[NH], sm2[NH];
    const int b = blockIdx.x >> 10;
    const int n = blockIdx.x & 1023;
    const int t = threadIdx.x;               // 512
    const int lane = t & 31, warp = t >> 5;  // 16 warps
    if (t < NH*NH) wre[t/NH][t%NH] = w_re[t];
    if (t < NH) { bre[t] = b_re[t]; sm1[t]=0.f; sm2[t]=0.f; }
    const int m = t << 1;
    float L[NH][2];
    #pragma unroll
    for (int h = 0; h < NH; h++) {
        float2 v = __ldcs((const float2*)(g_logits + (((size_t)(b*NH+h))*NSEQ + n)*NSEQ + m));
        L[h][0]=v.x; L[h][1]=v.y;
        float mx = fmaxf(v.x, v.y);
        #pragma unroll
        for (int o = 16; o; o >>= 1) mx = fmaxf(mx, __shfl_xor_sync(0xffffffffu, mx, o));
        if (lane == 0) red[h][warp] = mx;
    }
    __syncthreads();
    if (t < NH) {
        float mx = red[t][0];
        #pragma unroll
        for (int w = 1; w < 16; w++) mx = fmaxf(mx, red[t][w]);
        smax[t] = mx;
    }
    __syncthreads();
    #pragma unroll
    for (int h = 0; h < NH; h++) {
        float mh = smax[h];
        L[h][0]=__expf(L[h][0]-mh); L[h][1]=__expf(L[h][1]-mh);
        float s = L[h][0]+L[h][1];
        #pragma unroll
        for (int o = 16; o; o >>= 1) s += __shfl_xor_sync(0xffffffffu, s, o);
        if (lane == 0) red[h][warp] = s;
    }
    __syncthreads();
    if (t < NH) {
        float s = 0.f;
        #pragma unroll
        for (int w = 0; w < 16; w++) s += red[t][w];
        sinv[t] = 1.0f / s;
    }
    __syncthreads();
    #pragma unroll
    for (int h = 0; h < NH; h++) {
        float si = sinv[h];
        L[h][0]*=si; L[h][1]*=si;
    }
    float* attn = dout + OUT_OFF;
    #pragma unroll
    for (int g = 0; g < NH; g++) {
        float o0=bre[g], o1=bre[g];
        #pragma unroll
        for (int h = 0; h < NH; h++) {
            float w = wre[g][h];
            o0 = fmaf(w, L[h][0], o0); o1 = fmaf(w, L[h][1], o1);
        }
        float2 st = {o0, o1};
        __stcs((float2*)(attn + (((size_t)(b*NH+g))*NSEQ + n)*NSEQ + m), st);
        float a = o0+o1;
        float c = fmaf(o0,o0,o1*o1);
        #pragma unroll
        for (int o = 16; o; o >>= 1) {
            a += __shfl_xor_sync(0xffffffffu, a, o);
            c += __shfl_xor_sync(0xffffffffu, c, o);
        }
        if (lane == 0) { atomicAdd(&sm1[g], a); atomicAdd(&sm2[g], c); }
    }
    __syncthreads();
    if (t < NH) {
        atomicAdd(&g_s1[t], (double)sm1[t]);
        atomicAdd(&g_s2[t], (double)sm2[t]);
    }
}

// ---------------- BN finalize (double precision) -----------------------------
__global__ void k_bnfin(const float* __restrict__ gamma, const float* __restrict__ beta) {
    int g = threadIdx.x;
    if (g < NH) {
        double cnt = (double)BB * NSEQ * NSEQ;
        double mean = g_s1[g] / cnt;
        double var  = g_s2[g] / cnt - mean * mean;
        float a = (float)((double)gamma[g] / sqrt(var + (double)BNEPS));
        g_bna[g] = a;
        g_bnc[g] = beta[g] - a * (float)mean;
    }
}

// ---------------- launcher ----------------------------------------------------
extern "C" void kernel_launch(void* const* d_in, const int* in_sizes, int n_in,
                              void* d_out, int out_size) {
    const float* x    = (const float*)d_in[0];
    const float* wqkv = (const float*)d_in[1];
    const float* bqkv = (const float*)d_in[2];
    const float* wre  = (const float*)d_in[3];
    const float* bre  = (const float*)d_in[4];
    const float* gam  = (const float*)d_in[5];
    const float* bet  = (const float*)d_in[6];
    const float* wp   = (const float*)d_in[7];
    const float* bp   = (const float*)d_in[8];
    float* out = (float*)d_out;

    k_init<<<1, 32>>>();
    gemm_k<128,0><<<dim3(18, 64, 1), 256>>>(x, wqkv, bqkv, nullptr);       // qkv
    gemm_k<128,1><<<dim3(8, 8, 96), 256>>>(nullptr, nullptr, nullptr, nullptr); // qk
    k_mix<<<8192, 512>>>(wre, bre, out);
    k_bnfin<<<1, 32>>>(gam, bet);
    gemm_k<64,2><<<dim3(1, 8, 96), 256>>>(out + OUT_OFF, nullptr, nullptr, nullptr); // av + norm
    gemm_k<128,3><<<dim3(6, 64, 1), 256>>>(nullptr, wp, bp, out);          // proj
}

// round 5
// speedup vs baseline: 1.1306x; 1.1306x over previous
#include <cuda_runtime.h>
#include <cuda_fp16.h>
#include <math.h>
#include <stdint.h>

#define BB 8
#define NSEQ 1024
#define CDIM 768
#define NH 12
#define HD 64
#define SCALE 0.125f
#define BNEPS 1e-5f
#define OUT_OFF (BB*NSEQ*CDIM)
#define NN ((size_t)NSEQ*NSEQ)

// ---------------- scratch (device globals) -----------------------------------
// split planes: uint2 = { half2(hi0,hi1), half2(lo0,lo1) } for 2 consecutive k
__device__ uint2 g_xs [BB*NSEQ*CDIM/2];        // x * 16
__device__ uint2 g_wqs[3*CDIM*CDIM/2];         // w_qkv * 1024
__device__ uint2 g_wps[CDIM*CDIM/2];           // w_proj * 1024
__device__ uint2 g_qs [BB*NH*NSEQ*HD/2];       // q * 32 (raw, no SCALE)
__device__ uint2 g_ks [BB*NH*NSEQ*HD/2];       // k * 32
__device__ uint2 g_vts[BB*NH*HD*NSEQ/2];       // v^T * 32, [bh][d][m]
__device__ uint2 g_gts[BB*NSEQ*CDIM/2];        // (attn_n @ v) * 1, [b*N+n][c]
__device__ float g_vt [BB*NH*HD*NSEQ];         // raw v^T
__device__ float g_logits[BB*NH*NSEQ*NSEQ];    // raw q.k (SCALE applied in k_mix)
__device__ double g_s1[NH];
__device__ double g_s2[NH];
__device__ float  g_bna[NH];
__device__ float  g_bnc[NH];

// ---------------- helpers -----------------------------------------------------
__device__ __forceinline__ uint2 split2(float x0, float x1, float s){
    x0 *= s; x1 *= s;
    __half h0 = __float2half_rn(x0), h1 = __float2half_rn(x1);
    __half g0 = __float2half_rn(x0 - __half2float(h0));
    __half g1 = __float2half_rn(x1 - __half2float(h1));
    __half2 hh = __halves2half2(h0, h1), ll = __halves2half2(g0, g1);
    uint2 r;
    r.x = *(uint32_t*)&hh; r.y = *(uint32_t*)&ll;
    return r;
}

__device__ __forceinline__ void mma16(float* c, const uint32_t* a, const uint32_t* b){
    asm volatile("mma.sync.aligned.m16n8k16.row.col.f32.f16.f16.f32 "
        "{%0,%1,%2,%3}, {%4,%5,%6,%7}, {%8,%9}, {%0,%1,%2,%3};"
        : "+f"(c[0]), "+f"(c[1]), "+f"(c[2]), "+f"(c[3])
        : "r"(a[0]), "r"(a[1]), "r"(a[2]), "r"(a[3]), "r"(b[0]), "r"(b[1]));
}

__global__ void k_init(){ int t = threadIdx.x; if (t < NH){ g_s1[t]=0.0; g_s2[t]=0.0; } }

// ---------------- pre-split kernels -------------------------------------------
// sel: 0=x(*16), 1=wqkv(*1024), 2=wproj(*1024), 3=g_vt(*32)
__global__ void k_split(const float* __restrict__ src, int n2, float s, int sel){
    int i = blockIdx.x * blockDim.x + threadIdx.x;
    if (i >= n2) return;
    const float* p = (sel == 3) ? g_vt : src;
    float2 v = *(const float2*)(p + 2*(size_t)i);
    uint2 r = split2(v.x, v.y, s);
    uint2* d = (sel==0) ? g_xs : (sel==1) ? g_wqs : (sel==2) ? g_wps : g_vts;
    d[i] = r;
}

// ---------------- fp16x3 GEMM: C[M,N] = A[M,K] * B[N,K]^T ---------------------
// MODE 0: qkv  A=g_xs  B=g_wqs  K=768  -> q,k splits + raw v^T (unscale 2^-14, +bias)
// MODE 1: qk   A=g_qs  B=g_ks   K=64   -> g_logits (unscale 2^-10)
// MODE 2: av   A=attn raw fp32 (normalize+writeback+split*16) B=g_vts K=1024
//              -> g_gts (unscale 2^-9)
// MODE 3: proj A=g_gts B=g_wps  K=768  -> d_out (unscale 2^-10, +bias)
template<int BN, int MODE>
__global__ __launch_bounds__(256, 2) void gemm_h(
    const float* __restrict__ pA, const float* __restrict__ bias,
    float* __restrict__ pC)
{
    constexpr int BM = 128, LDU = 20;                 // row stride in uint2
    constexpr int NT = (BN/2)/8, MT = 2;
    constexpr int K   = (MODE==1) ? 64 : (MODE==2) ? 1024 : 768;
    constexpr int NC  = K / 32;
    constexpr int LD2 = K / 2;                        // uint2 row stride in gmem
    constexpr int NB  = BN / 32;                      // B prefetch uint4 count

    __shared__ __align__(16) uint2 As[BM*LDU];
    __shared__ __align__(16) uint2 Bs[BN*LDU];

    const int tid  = threadIdx.x;
    const int lane = tid & 31, warp = tid >> 5;
    const int wm = warp >> 1, wn = warp & 1;          // 4 x 2 warp grid
    const int gid = lane >> 2, tig = lane & 3;
    const int Mblk = blockIdx.y * BM;
    const int Nblk = blockIdx.x * BN;
    const int bh   = blockIdx.z;

    const uint2* A2 = nullptr; const uint2* B2;
    const float* Araw = nullptr;
    if constexpr (MODE == 0)      { A2 = g_xs; B2 = g_wqs; }
    else if constexpr (MODE == 1) { A2 = g_qs + (size_t)bh*NSEQ*(HD/2); B2 = g_ks + (size_t)bh*NSEQ*(HD/2); }
    else if constexpr (MODE == 2) { Araw = pA + (size_t)bh*NN; B2 = g_vts + (size_t)bh*HD*(NSEQ/2); }
    else                          { A2 = g_gts; B2 = g_wps; }

    float na = 0.f, ncs = 0.f;
    if constexpr (MODE == 2) { int g = bh % NH; na = g_bna[g]; ncs = g_bnc[g]; }

    const int pr = tid >> 3;      // base row of this thread's prefetch slice
    const int pq = tid & 7;       // uint4 (or float4) slot within row

    // -------- prefetch chunk 0 --------
    uint4  pa[4]; float4 fa[4]; uint4 pb[NB];
    #pragma unroll
    for (int i = 0; i < 4; i++) {
        int r = pr + i*32;
        if constexpr (MODE == 2) {
            float* p = (float*)(Araw + (size_t)(Mblk + r)*1024 + pq*4);
            float4 v = *(const float4*)p;
            v.x = fmaf(na, v.x, ncs); v.y = fmaf(na, v.y, ncs);
            v.z = fmaf(na, v.z, ncs); v.w = fmaf(na, v.w, ncs);
            __stcs((float4*)p, v);
            fa[i] = v;
        } else {
            pa[i] = *(const uint4*)(A2 + (size_t)(Mblk + r)*LD2 + pq*2);
        }
    }
    #pragma unroll
    for (int i = 0; i < NB; i++) {
        int r = pr + i*32;
        pb[i] = *(const uint4*)(B2 + (size_t)(Nblk + r)*LD2 + pq*2);
    }

    float acc[MT][NT][4] = {};

    for (int ch = 0; ch < NC; ch++) {
        // -------- STS --------
        #pragma unroll
        for (int i = 0; i < 4; i++) {
            int r = pr + i*32;
            if constexpr (MODE == 2) {
                uint2 u01 = split2(fa[i].x, fa[i].y, 16.f);
                uint2 u23 = split2(fa[i].z, fa[i].w, 16.f);
                uint4 st = {u01.x, u01.y, u23.x, u23.y};
                *(uint4*)&As[r*LDU + pq*2] = st;
            } else {
                *(uint4*)&As[r*LDU + pq*2] = pa[i];
            }
        }
        #pragma unroll
        for (int i = 0; i < NB; i++) {
            int r = pr + i*32;
            *(uint4*)&Bs[r*LDU + pq*2] = pb[i];
        }
        __syncthreads();
        // -------- prefetch next (overlaps MMA) --------
        if (ch + 1 < NC) {
            const int k2 = (ch + 1) * 16;     // uint2 offset
            #pragma unroll
            for (int i = 0; i < 4; i++) {
                int r = pr + i*32;
                if constexpr (MODE == 2) {
                    float* p = (float*)(Araw + (size_t)(Mblk + r)*1024 + k2*2 + pq*4);
                    float4 v = *(const float4*)p;
                    v.x = fmaf(na, v.x, ncs); v.y = fmaf(na, v.y, ncs);
                    v.z = fmaf(na, v.z, ncs); v.w = fmaf(na, v.w, ncs);
                    __stcs((float4*)p, v);
                    fa[i] = v;
                } else {
                    pa[i] = *(const uint4*)(A2 + (size_t)(Mblk + r)*LD2 + k2 + pq*2);
                }
            }
            #pragma unroll
            for (int i = 0; i < NB; i++) {
                int r = pr + i*32;
                pb[i] = *(const uint4*)(B2 + (size_t)(Nblk + r)*LD2 + k2 + pq*2);
            }
        }
        // -------- MMA: 2 x k16 steps, 3 passes (hh, lh, hl) --------
        #pragma unroll
        for (int ks = 0; ks < 2; ks++) {
            const int kb = ks * 8;
            uint32_t ah[MT][4], al[MT][4];
            #pragma unroll
            for (int i = 0; i < MT; i++) {
                int mb = wm*32 + i*16 + gid;
                uint2 a0 = As[mb*LDU + kb + tig];
                uint2 a1 = As[(mb+8)*LDU + kb + tig];
                uint2 a2 = As[mb*LDU + kb + tig + 4];
                uint2 a3 = As[(mb+8)*LDU + kb + tig + 4];
                ah[i][0]=a0.x; ah[i][1]=a1.x; ah[i][2]=a2.x; ah[i][3]=a3.x;
                al[i][0]=a0.y; al[i][1]=a1.y; al[i][2]=a2.y; al[i][3]=a3.y;
            }
            #pragma unroll
            for (int j = 0; j < NT; j++) {
                int nb = wn*(BN/2) + j*8 + gid;
                uint2 b0 = Bs[nb*LDU + kb + tig];
                uint2 b1 = Bs[nb*LDU + kb + tig + 4];
                uint32_t bh2[2] = {b0.x, b1.x};
                uint32_t bl2[2] = {b0.y, b1.y};
                #pragma unroll
                for (int i = 0; i < MT; i++) {
                    mma16(acc[i][j], ah[i], bh2);
                    mma16(acc[i][j], al[i], bh2);
                    mma16(acc[i][j], ah[i], bl2);
                }
            }
        }
        __syncthreads();
    }

    // ----------------- epilogue -----------------
    constexpr float UN = (MODE==0) ? (1.f/16384.f) : (MODE==2) ? (1.f/512.f) : (1.f/1024.f);
    #pragma unroll
    for (int i = 0; i < MT; i++) {
        #pragma unroll
        for (int j = 0; j < NT; j++) {
            const float* c = acc[i][j];
            int r0 = Mblk + wm*32 + i*16 + gid;
            int c0 = Nblk + wn*(BN/2) + j*8 + tig*2;
            #pragma unroll
            for (int p = 0; p < 2; p++) {
                int row = r0 + p*8;
                float v0 = c[p*2+0] * UN, v1 = c[p*2+1] * UN;
                if constexpr (MODE == 0) {
                    int t3 = c0 / CDIM; int rem = c0 - t3*CDIM;
                    int h = rem >> 6, d = rem & 63;
                    int b = row >> 10, n = row & (NSEQ - 1);
                    v0 += bias[c0]; v1 += bias[c0+1];
                    if (t3 == 0) {
                        g_qs[((((size_t)(b*NH+h))*NSEQ + n) << 5) + (d >> 1)] = split2(v0, v1, 32.f);
                    } else if (t3 == 1) {
                        g_ks[((((size_t)(b*NH+h))*NSEQ + n) << 5) + (d >> 1)] = split2(v0, v1, 32.f);
                    } else {
                        size_t base = (((size_t)(b*NH+h))*HD + d)*NSEQ + n;
                        g_vt[base]        = v0;
                        g_vt[base + NSEQ] = v1;
                    }
                } else if constexpr (MODE == 1) {
                    float2 s = make_float2(v0, v1);
                    __stcs((float2*)(g_logits + (size_t)bh*NN + (size_t)row*NSEQ + c0), s);
                } else if constexpr (MODE == 2) {
                    int b = bh / NH, g = bh % NH;
                    g_gts[((size_t)(b*NSEQ + row))*(CDIM/2) + ((g*HD + c0) >> 1)] = split2(v0, v1, 1.f);
                } else {
                    float2 s = make_float2(v0 + bias[c0], v1 + bias[c0+1]);
                    *(float2*)(pC + (size_t)row*CDIM + c0) = s;
                }
            }
        }
    }
}

// ---------------- fused softmax + head mix + BN stats (1024 threads) ---------
// one block per (b,n); thread t owns column m = t; SCALE folded into exp
__global__ __launch_bounds__(1024) void k_mix(const float* __restrict__ w_re,
                      const float* __restrict__ b_re, float* __restrict__ dout) {
    __shared__ float wre[NH][NH];
    __shared__ float bre[NH], smax[NH], sinv[NH];
    __shared__ float red[NH][32];
    __shared__ float sm1[NH], sm2[NH];
    const int b = blockIdx.x >> 10;
    const int n = blockIdx.x & 1023;
    const int t = threadIdx.x;               // 1024
    const int lane = t & 31, warp = t >> 5;  // 32 warps
    if (t < NH*NH) wre[t/NH][t%NH] = w_re[t];
    if (t < NH) { bre[t] = b_re[t]; sm1[t]=0.f; sm2[t]=0.f; }
    float L[NH];
    #pragma unroll
    for (int h = 0; h < NH; h++) {
        float v = g_logits[(((size_t)(b*NH+h))*NSEQ + n)*NSEQ + t];
        L[h] = v;
        #pragma unroll
        for (int o = 16; o; o >>= 1) v = fmaxf(v, __shfl_xor_sync(0xffffffffu, v, o));
        if (lane == 0) red[h][warp] = v;
    }
    __syncthreads();
    if (warp < NH) {
        float v = red[warp][lane];
        #pragma unroll
        for (int o = 16; o; o >>= 1) v = fmaxf(v, __shfl_xor_sync(0xffffffffu, v, o));
        if (lane == 0) smax[warp] = v;
    }
    __syncthreads();
    #pragma unroll
    for (int h = 0; h < NH; h++) {
        float e = __expf(SCALE * (L[h] - smax[h]));
        L[h] = e;
        #pragma unroll
        for (int o = 16; o; o >>= 1) e += __shfl_xor_sync(0xffffffffu, e, o);
        if (lane == 0) red[h][warp] = e;
    }
    __syncthreads();
    if (warp < NH) {
        float v = red[warp][lane];
        #pragma unroll
        for (int o = 16; o; o >>= 1) v += __shfl_xor_sync(0xffffffffu, v, o);
        if (lane == 0) sinv[warp] = 1.0f / v;
    }
    __syncthreads();
    #pragma unroll
    for (int h = 0; h < NH; h++) L[h] *= sinv[h];
    float* attn = dout + OUT_OFF;
    #pragma unroll
    for (int g = 0; g < NH; g++) {
        float o0 = bre[g];
        #pragma unroll
        for (int h = 0; h < NH; h++) o0 = fmaf(wre[g][h], L[h], o0);
        attn[(((size_t)(b*NH+g))*NSEQ + n)*NSEQ + t] = o0;
        float a = o0, c = o0*o0;
        #pragma unroll
        for (int o = 16; o; o >>= 1) {
            a += __shfl_xor_sync(0xffffffffu, a, o);
            c += __shfl_xor_sync(0xffffffffu, c, o);
        }
        if (lane == 0) { atomicAdd(&sm1[g], a); atomicAdd(&sm2[g], c); }
    }
    __syncthreads();
    if (t < NH) {
        atomicAdd(&g_s1[t], (double)sm1[t]);
        atomicAdd(&g_s2[t], (double)sm2[t]);
    }
}

// ---------------- BN finalize (double precision) -----------------------------
__global__ void k_bnfin(const float* __restrict__ gamma, const float* __restrict__ beta) {
    int g = threadIdx.x;
    if (g < NH) {
        double cnt = (double)BB * NSEQ * NSEQ;
        double mean = g_s1[g] / cnt;
        double var  = g_s2[g] / cnt - mean * mean;
        float a = (float)((double)gamma[g] / sqrt(var + (double)BNEPS));
        g_bna[g] = a;
        g_bnc[g] = beta[g] - a * (float)mean;
    }
}

// ---------------- launcher ----------------------------------------------------
extern "C" void kernel_launch(void* const* d_in, const int* in_sizes, int n_in,
                              void* d_out, int out_size) {
    const float* x    = (const float*)d_in[0];
    const float* wqkv = (const float*)d_in[1];
    const float* bqkv = (const float*)d_in[2];
    const float* wre  = (const float*)d_in[3];
    const float* bre  = (const float*)d_in[4];
    const float* gam  = (const float*)d_in[5];
    const float* bet  = (const float*)d_in[6];
    const float* wp   = (const float*)d_in[7];
    const float* bp   = (const float*)d_in[8];
    float* out = (float*)d_out;

    k_init<<<1, 32>>>();
    k_split<<<12288, 256>>>(x,    3145728, 16.f,   0);   // x -> g_xs
    k_split<<<3456,  256>>>(wqkv,  884736, 1024.f, 1);   // w_qkv -> g_wqs
    k_split<<<1152,  256>>>(wp,    294912, 1024.f, 2);   // w_proj -> g_wps
    gemm_h<128,0><<<dim3(18, 64, 1), 256>>>(nullptr, bqkv, nullptr);         // qkv
    k_split<<<12288, 256>>>(nullptr, 3145728, 32.f, 3);  // g_vt -> g_vts
    gemm_h<128,1><<<dim3(8, 8, 96),  256>>>(nullptr, nullptr, nullptr);      // qk
    k_mix<<<8192, 1024>>>(wre, bre, out);
    k_bnfin<<<1, 32>>>(gam, bet);
    gemm_h<64,2> <<<dim3(1, 8, 96),  256>>>(out + OUT_OFF, nullptr, nullptr); // av + norm
    gemm_h<128,3><<<dim3(6, 64, 1),  256>>>(nullptr, bp, out);               // proj
}

// round 6
// speedup vs baseline: 1.4381x; 1.2719x over previous
#include <cuda_runtime.h>
#include <cuda_fp16.h>
#include <math.h>
#include <stdint.h>

#define BB 8
#define NSEQ 1024
#define CDIM 768
#define NH 12
#define HD 64
#define SCALE 0.125f
#define BNEPS 1e-5f
#define OUT_OFF (BB*NSEQ*CDIM)
#define NN ((size_t)NSEQ*NSEQ)

// ---------------- scratch (device globals) -----------------------------------
// split planes: uint2 = { half2(hi0,hi1), half2(lo0,lo1) } for 2 consecutive k
__device__ uint2 g_xs [BB*NSEQ*CDIM/2];        // x * 16
__device__ uint2 g_wqs[3*CDIM*CDIM/2];         // w_qkv * 1024
__device__ uint2 g_wps[CDIM*CDIM/2];           // w_proj * 1024
__device__ uint2 g_qs [BB*NH*NSEQ*HD/2];       // q * 32 (raw, no SCALE)
__device__ uint2 g_ks [BB*NH*NSEQ*HD/2];       // k * 32
__device__ uint2 g_vts[BB*NH*HD*NSEQ/2];       // v^T * 32, [bh][d][m]
__device__ uint2 g_gts[BB*NSEQ*CDIM/2];        // (attn_n @ v) * 1, [b*N+n][c]
__device__ float g_vt [BB*NH*HD*NSEQ];         // raw v^T
__device__ float g_logits[BB*NH*NSEQ*NSEQ];    // raw q.k -> overwritten with MIXED by k_mix
__device__ double g_s1[NH];
__device__ double g_s2[NH];
__device__ float  g_bna[NH];
__device__ float  g_bnc[NH];

// ---------------- helpers -----------------------------------------------------
__device__ __forceinline__ uint32_t s2u(const void* p){
    uint32_t a;
    asm("{ .reg .u64 t; cvta.to.shared.u64 t, %1; cvt.u32.u64 %0, t; }" : "=r"(a) : "l"(p));
    return a;
}
__device__ __forceinline__ uint2 split2(float x0, float x1, float s){
    x0 *= s; x1 *= s;
    __half h0 = __float2half_rn(x0), h1 = __float2half_rn(x1);
    __half g0 = __float2half_rn(x0 - __half2float(h0));
    __half g1 = __float2half_rn(x1 - __half2float(h1));
    __half2 hh = __halves2half2(h0, h1), ll = __halves2half2(g0, g1);
    uint2 r;
    r.x = *(uint32_t*)&hh; r.y = *(uint32_t*)&ll;
    return r;
}
__device__ __forceinline__ void mma16f(float* c, const uint32_t* a, const uint32_t* b){
    asm volatile("mma.sync.aligned.m16n8k16.row.col.f32.f16.f16.f32 "
        "{%0,%1,%2,%3}, {%4,%5,%6,%7}, {%8,%9}, {%0,%1,%2,%3};"
        : "+f"(c[0]), "+f"(c[1]), "+f"(c[2]), "+f"(c[3])
        : "r"(a[0]), "r"(a[1]), "r"(a[2]), "r"(a[3]), "r"(b[0]), "r"(b[1]));
}
__device__ __forceinline__ void mma16h(uint32_t* c, const uint32_t* a, const uint32_t* b){
    asm volatile("mma.sync.aligned.m16n8k16.row.col.f16.f16.f16.f16 "
        "{%0,%1}, {%2,%3,%4,%5}, {%6,%7}, {%0,%1};"
        : "+r"(c[0]), "+r"(c[1])
        : "r"(a[0]), "r"(a[1]), "r"(a[2]), "r"(a[3]), "r"(b[0]), "r"(b[1]));
}
__device__ __forceinline__ void cpa16(uint32_t dst, const void* src){
    asm volatile("cp.async.cg.shared.global [%0], [%1], 16;" :: "r"(dst), "l"(src));
}
#define CPA_COMMIT() asm volatile("cp.async.commit_group;" ::: "memory")

__global__ void k_init(){ int t = threadIdx.x; if (t < NH){ g_s1[t]=0.0; g_s2[t]=0.0; } }

// ---------------- pre-split kernels -------------------------------------------
__global__ void k_split(const float* __restrict__ src, int n2, float s, int sel){
    int i = blockIdx.x * blockDim.x + threadIdx.x;
    if (i >= n2) return;
    const float* p = (sel == 3) ? g_vt : src;
    float2 v = *(const float2*)(p + 2*(size_t)i);
    uint2 r = split2(v.x, v.y, s);
    uint2* d = (sel==0) ? g_xs : (sel==1) ? g_wqs : (sel==2) ? g_wps : g_vts;
    d[i] = r;
}

// shared MMA core: one k32 chunk, hh in fp32 acc, (lh + hl) in shared fp16 acc
template<int NT, int MT>
__device__ __forceinline__ void mma_chunk(
    const uint2* __restrict__ As_, const uint2* __restrict__ Bs_,
    float accf[MT][NT][4], uint32_t acch[MT][NT][2],
    int wm, int wn, int gid, int tig)
{
    #pragma unroll
    for (int ks = 0; ks < 2; ks++) {
        const int kb = ks * 8;
        uint32_t ah[MT][4], al[MT][4];
        #pragma unroll
        for (int i = 0; i < MT; i++) {
            int mb = wm*32 + i*16 + gid;
            uint2 a0 = As_[mb*20 + kb + tig];
            uint2 a1 = As_[(mb+8)*20 + kb + tig];
            uint2 a2 = As_[mb*20 + kb + tig + 4];
            uint2 a3 = As_[(mb+8)*20 + kb + tig + 4];
            ah[i][0]=a0.x; ah[i][1]=a1.x; ah[i][2]=a2.x; ah[i][3]=a3.x;
            al[i][0]=a0.y; al[i][1]=a1.y; al[i][2]=a2.y; al[i][3]=a3.y;
        }
        #pragma unroll
        for (int j = 0; j < NT; j++) {
            int nb = wn*(NT*8) + j*8 + gid;
            uint2 b0 = Bs_[nb*20 + kb + tig];
            uint2 b1 = Bs_[nb*20 + kb + tig + 4];
            uint32_t bhh[2] = {b0.x, b1.x};
            uint32_t bll[2] = {b0.y, b1.y};
            #pragma unroll
            for (int i = 0; i < MT; i++) {
                mma16f(accf[i][j], ah[i], bhh);
                mma16h(acch[i][j], al[i], bhh);
                mma16h(acch[i][j], ah[i], bll);
            }
        }
    }
}

// ---------------- fp16x3 GEMM (hh fp32-acc, corrections fp16-acc) -------------
// C[M,64-tile] = A[M,K] * B[N,K]^T
// MODE 0: qkv  A=g_xs  B=g_wqs  K=768  -> q,k splits + raw v^T (UN 2^-14, +bias)
// MODE 1: qk   A=g_qs  B=g_ks   K=64   -> g_logits (UN 2^-10)
// MODE 2: av   A=g_logits (MIXED raw; normalize -> write d_out attn -> split*16)
//              B=g_vts K=1024 -> g_gts (UN 2^-9)
// MODE 3: proj A=g_gts B=g_wps K=768   -> d_out (UN 2^-10, +bias)
template<int MODE>
__global__ __launch_bounds__(256, 2) void gemm_h(
    const float* __restrict__ bias, float* __restrict__ pC)
{
    constexpr int BM = 128, BN = 64, LDU = 20;
    constexpr int NT = 4, MT = 2;
    constexpr int K   = (MODE==1) ? 64 : (MODE==2) ? 1024 : 768;
    constexpr int NC  = K / 32;
    constexpr int LD2 = K / 2;                        // uint2 row stride in gmem
    constexpr int STAGE = (BM + BN) * LDU;            // uint2 per stage

    extern __shared__ __align__(16) uint2 sm[];

    const int tid  = threadIdx.x;
    const int lane = tid & 31, warp = tid >> 5;
    const int wm = warp >> 1, wn = warp & 1;          // 4 x 2 warp grid
    const int gid = lane >> 2, tig = lane & 3;
    const int Mblk = blockIdx.y * BM;
    const int Nblk = blockIdx.x * BN;
    const int bh   = blockIdx.z;

    const uint2* A2 = nullptr; const uint2* B2;
    if constexpr (MODE == 0)      { A2 = g_xs; B2 = g_wqs; }
    else if constexpr (MODE == 1) { A2 = g_qs + (size_t)bh*NSEQ*(HD/2); B2 = g_ks + (size_t)bh*NSEQ*(HD/2); }
    else if constexpr (MODE == 2) { B2 = g_vts + (size_t)bh*HD*(NSEQ/2); }
    else                          { A2 = g_gts; B2 = g_wps; }

    float accf[MT][NT][4] = {};
    uint32_t acch[MT][NT][2] = {};

    const int pr = tid >> 3;      // row slice base
    const int pq = tid & 7;       // 16B chunk within 128B row

    if constexpr (MODE != 2) {
        // ======== cp.async double-buffered path ========
        const uint32_t sb = s2u(sm);
        auto issue = [&](int ch, int s) {
            #pragma unroll
            for (int i = 0; i < 4; i++) {
                int r = pr + i*32;
                cpa16(sb + (uint32_t)((s*STAGE + r*LDU + pq*2) * 8),
                      A2 + (size_t)(Mblk + r)*LD2 + ch*16 + pq*2);
            }
            #pragma unroll
            for (int i = 0; i < 2; i++) {
                int r = pr + i*32;
                cpa16(sb + (uint32_t)((s*STAGE + (BM + r)*LDU + pq*2) * 8),
                      B2 + (size_t)(Nblk + r)*LD2 + ch*16 + pq*2);
            }
            CPA_COMMIT();
        };
        issue(0, 0);
        for (int ch = 0; ch < NC; ch++) {
            if (ch + 1 < NC) {
                issue(ch + 1, (ch + 1) & 1);
                asm volatile("cp.async.wait_group 1;" ::: "memory");
            } else {
                asm volatile("cp.async.wait_group 0;" ::: "memory");
            }
            __syncthreads();
            const uint2* S = sm + (ch & 1) * STAGE;
            mma_chunk<NT, MT>(S, S + BM*LDU, accf, acch, wm, wn, gid, tig);
            __syncthreads();
        }
    } else {
        // ======== AV: raw mixed A -> normalize -> d_out attn -> split ========
        uint2* As_ = sm; uint2* Bs_ = sm + BM*LDU;
        const float* Araw = g_logits + (size_t)bh*NN;
        float* Aout = pC + (size_t)bh*NN;             // pC = d_out + OUT_OFF
        const int g = bh % NH;
        const float na = g_bna[g], ncs = g_bnc[g];

        float4 fa[4]; uint4 pb[2];
        #pragma unroll
        for (int i = 0; i < 4; i++) {
            int r = pr + i*32;
            const float* p = Araw + (size_t)(Mblk + r)*1024 + pq*4;
            float4 v = __ldcs((const float4*)p);
            v.x = fmaf(na, v.x, ncs); v.y = fmaf(na, v.y, ncs);
            v.z = fmaf(na, v.z, ncs); v.w = fmaf(na, v.w, ncs);
            __stcs((float4*)(Aout + (size_t)(Mblk + r)*1024 + pq*4), v);
            fa[i] = v;
        }
        #pragma unroll
        for (int i = 0; i < 2; i++) {
            int r = pr + i*32;
            pb[i] = *(const uint4*)(B2 + (size_t)(Nblk + r)*LD2 + pq*2);
        }
        for (int ch = 0; ch < NC; ch++) {
            #pragma unroll
            for (int i = 0; i < 4; i++) {
                int r = pr + i*32;
                uint2 u01 = split2(fa[i].x, fa[i].y, 16.f);
                uint2 u23 = split2(fa[i].z, fa[i].w, 16.f);
                uint4 st = {u01.x, u01.y, u23.x, u23.y};
                *(uint4*)&As_[r*LDU + pq*2] = st;
            }
            #pragma unroll
            for (int i = 0; i < 2; i++) {
                int r = pr + i*32;
                *(uint4*)&Bs_[r*LDU + pq*2] = pb[i];
            }
            __syncthreads();
            if (ch + 1 < NC) {
                const int kf = (ch + 1) * 32;
                #pragma unroll
                for (int i = 0; i < 4; i++) {
                    int r = pr + i*32;
                    const float* p = Araw + (size_t)(Mblk + r)*1024 + kf + pq*4;
                    float4 v = __ldcs((const float4*)p);
                    v.x = fmaf(na, v.x, ncs); v.y = fmaf(na, v.y, ncs);
                    v.z = fmaf(na, v.z, ncs); v.w = fmaf(na, v.w, ncs);
                    __stcs((float4*)(Aout + (size_t)(Mblk + r)*1024 + kf + pq*4), v);
                    fa[i] = v;
                }
                const int k2 = (ch + 1) * 16;
                #pragma unroll
                for (int i = 0; i < 2; i++) {
                    int r = pr + i*32;
                    pb[i] = *(const uint4*)(B2 + (size_t)(Nblk + r)*LD2 + k2 + pq*2);
                }
            }
            mma_chunk<NT, MT>(As_, Bs_, accf, acch, wm, wn, gid, tig);
            __syncthreads();
        }
    }

    // ----------------- epilogue -----------------
    constexpr float UN = (MODE==0) ? (1.f/16384.f) : (MODE==2) ? (1.f/512.f) : (1.f/1024.f);
    #pragma unroll
    for (int i = 0; i < MT; i++) {
        #pragma unroll
        for (int j = 0; j < NT; j++) {
            __half2 q0 = *(__half2*)&acch[i][j][0];
            __half2 q1 = *(__half2*)&acch[i][j][1];
            float2 c01 = __half22float2(q0);
            float2 c23 = __half22float2(q1);
            float cv[4] = {accf[i][j][0] + c01.x, accf[i][j][1] + c01.y,
                           accf[i][j][2] + c23.x, accf[i][j][3] + c23.y};
            int r0 = Mblk + wm*32 + i*16 + gid;
            int c0 = Nblk + wn*32 + j*8 + tig*2;
            #pragma unroll
            for (int p = 0; p < 2; p++) {
                int row = r0 + p*8;
                float v0 = cv[p*2+0] * UN, v1 = cv[p*2+1] * UN;
                if constexpr (MODE == 0) {
                    int t3 = c0 / CDIM; int rem = c0 - t3*CDIM;
                    int h = rem >> 6, d = rem & 63;
                    int b = row >> 10, n = row & (NSEQ - 1);
                    v0 += bias[c0]; v1 += bias[c0+1];
                    if (t3 == 0) {
                        g_qs[((((size_t)(b*NH+h))*NSEQ + n) << 5) + (d >> 1)] = split2(v0, v1, 32.f);
                    } else if (t3 == 1) {
                        g_ks[((((size_t)(b*NH+h))*NSEQ + n) << 5) + (d >> 1)] = split2(v0, v1, 32.f);
                    } else {
                        size_t base = (((size_t)(b*NH+h))*HD + d)*NSEQ + n;
                        g_vt[base]        = v0;
                        g_vt[base + NSEQ] = v1;
                    }
                } else if constexpr (MODE == 1) {
                    float2 s = make_float2(v0, v1);
                    __stcs((float2*)(g_logits + (size_t)bh*NN + (size_t)row*NSEQ + c0), s);
                } else if constexpr (MODE == 2) {
                    int b = bh / NH, g = bh % NH;
                    g_gts[((size_t)(b*NSEQ + row))*(CDIM/2) + ((g*HD + c0) >> 1)] = split2(v0, v1, 1.f);
                } else {
                    float2 s = make_float2(v0 + bias[c0], v1 + bias[c0+1]);
                    *(float2*)(pC + (size_t)row*CDIM + c0) = s;
                }
            }
        }
    }
}

// ---------------- fused softmax + head mix + BN stats (R2 form) ---------------
// one block per (b,n); thread t owns float4 at m=4t; SCALE folded into exp;
// writes RAW MIXED values in place over g_logits (per-block same addresses).
__global__ void k_mix(const float* __restrict__ w_re, const float* __restrict__ b_re) {
    __shared__ float wre[NH][NH];
    __shared__ float bre[NH], smax[NH], sinv[NH];
    __shared__ float red[NH][8];
    __shared__ float sm1[NH], sm2[NH];
    const int b = blockIdx.x >> 10;
    const int n = blockIdx.x & 1023;
    const int t = threadIdx.x;               // 256
    const int lane = t & 31, warp = t >> 5;
    if (t < NH*NH) wre[t/NH][t%NH] = w_re[t];
    if (t < NH) { bre[t] = b_re[t]; sm1[t]=0.f; sm2[t]=0.f; }
    const int m = t << 2;
    float L[NH][4];
    #pragma unroll
    for (int h = 0; h < NH; h++) {
        float4 v = *(const float4*)(g_logits + (((size_t)(b*NH+h))*NSEQ + n)*NSEQ + m);
        L[h][0]=v.x; L[h][1]=v.y; L[h][2]=v.z; L[h][3]=v.w;
        float mx = fmaxf(fmaxf(v.x, v.y), fmaxf(v.z, v.w));
        #pragma unroll
        for (int o = 16; o; o >>= 1) mx = fmaxf(mx, __shfl_xor_sync(0xffffffffu, mx, o));
        if (lane == 0) red[h][warp] = mx;
    }
    __syncthreads();
    if (t < NH) {
        float mx = red[t][0];
        #pragma unroll
        for (int w = 1; w < 8; w++) mx = fmaxf(mx, red[t][w]);
        smax[t] = mx;
    }
    __syncthreads();
    #pragma unroll
    for (int h = 0; h < NH; h++) {
        float mh = smax[h];
        L[h][0]=__expf(SCALE*(L[h][0]-mh)); L[h][1]=__expf(SCALE*(L[h][1]-mh));
        L[h][2]=__expf(SCALE*(L[h][2]-mh)); L[h][3]=__expf(SCALE*(L[h][3]-mh));
        float s = (L[h][0]+L[h][1]) + (L[h][2]+L[h][3]);
        #pragma unroll
        for (int o = 16; o; o >>= 1) s += __shfl_xor_sync(0xffffffffu, s, o);
        if (lane == 0) red[h][warp] = s;
    }
    __syncthreads();
    if (t < NH) {
        float s = 0.f;
        #pragma unroll
        for (int w = 0; w < 8; w++) s += red[t][w];
        sinv[t] = 1.0f / s;
    }
    __syncthreads();
    #pragma unroll
    for (int h = 0; h < NH; h++) {
        float si = sinv[h];
        L[h][0]*=si; L[h][1]*=si; L[h][2]*=si; L[h][3]*=si;
    }
    #pragma unroll
    for (int g = 0; g < NH; g++) {
        float o0=bre[g], o1=bre[g], o2=bre[g], o3=bre[g];
        #pragma unroll
        for (int h = 0; h < NH; h++) {
            float w = wre[g][h];
            o0 = fmaf(w, L[h][0], o0); o1 = fmaf(w, L[h][1], o1);
            o2 = fmaf(w, L[h][2], o2); o3 = fmaf(w, L[h][3], o3);
        }
        float4 st = {o0, o1, o2, o3};
        *(float4*)(g_logits + (((size_t)(b*NH+g))*NSEQ + n)*NSEQ + m) = st;
        float a = (o0+o1)+(o2+o3);
        float c = o0*o0+o1*o1+o2*o2+o3*o3;
        #pragma unroll
        for (int o = 16; o; o >>= 1) {
            a += __shfl_xor_sync(0xffffffffu, a, o);
            c += __shfl_xor_sync(0xffffffffu, c, o);
        }
        if (lane == 0) { atomicAdd(&sm1[g], a); atomicAdd(&sm2[g], c); }
    }
    __syncthreads();
    if (t < NH) {
        atomicAdd(&g_s1[t], (double)sm1[t]);
        atomicAdd(&g_s2[t], (double)sm2[t]);
    }
}

// ---------------- BN finalize (double precision) -----------------------------
__global__ void k_bnfin(const float* __restrict__ gamma, const float* __restrict__ beta) {
    int g = threadIdx.x;
    if (g < NH) {
        double cnt = (double)BB * NSEQ * NSEQ;
        double mean = g_s1[g] / cnt;
        double var  = g_s2[g] / cnt - mean * mean;
        float a = (float)((double)gamma[g] / sqrt(var + (double)BNEPS));
        g_bna[g] = a;
        g_bnc[g] = beta[g] - a * (float)mean;
    }
}

// ---------------- launcher ----------------------------------------------------
extern "C" void kernel_launch(void* const* d_in, const int* in_sizes, int n_in,
                              void* d_out, int out_size) {
    const float* x    = (const float*)d_in[0];
    const float* wqkv = (const float*)d_in[1];
    const float* bqkv = (const float*)d_in[2];
    const float* wre  = (const float*)d_in[3];
    const float* bre  = (const float*)d_in[4];
    const float* gam  = (const float*)d_in[5];
    const float* bet  = (const float*)d_in[6];
    const float* wp   = (const float*)d_in[7];
    const float* bp   = (const float*)d_in[8];
    float* out = (float*)d_out;

    const int SM2 = 2 * (128 + 64) * 20 * 8;   // 61440 (double-buffer stages)
    const int SM1 = (128 + 64) * 20 * 8;       // 30720 (MODE 2)
    cudaFuncSetAttribute(gemm_h<0>, cudaFuncAttributeMaxDynamicSharedMemorySize, SM2);
    cudaFuncSetAttribute(gemm_h<1>, cudaFuncAttributeMaxDynamicSharedMemorySize, SM2);
    cudaFuncSetAttribute(gemm_h<2>, cudaFuncAttributeMaxDynamicSharedMemorySize, SM1);
    cudaFuncSetAttribute(gemm_h<3>, cudaFuncAttributeMaxDynamicSharedMemorySize, SM2);

    k_init<<<1, 32>>>();
    k_split<<<12288, 256>>>(x,    3145728, 16.f,   0);   // x -> g_xs
    k_split<<<3456,  256>>>(wqkv,  884736, 1024.f, 1);   // w_qkv -> g_wqs
    k_split<<<1152,  256>>>(wp,    294912, 1024.f, 2);   // w_proj -> g_wps
    gemm_h<0><<<dim3(36, 64, 1), 256, SM2>>>(bqkv, nullptr);          // qkv
    k_split<<<12288, 256>>>(nullptr, 3145728, 32.f, 3);  // g_vt -> g_vts
    gemm_h<1><<<dim3(16, 8, 96), 256, SM2>>>(nullptr, nullptr);       // qk
    k_mix<<<8192, 256>>>(wre, bre);
    k_bnfin<<<1, 32>>>(gam, bet);
    gemm_h<2><<<dim3(1, 8, 96),  256, SM1>>>(nullptr, out + OUT_OFF); // av + norm + attn out
    gemm_h<3><<<dim3(12, 64, 1), 256, SM2>>>(bp, out);                // proj
}

// round 7
// speedup vs baseline: 1.5344x; 1.0670x over previous
#include <cuda_runtime.h>
#include <cuda_fp16.h>
#include <math.h>
#include <stdint.h>

#define BB 8
#define NSEQ 1024
#define CDIM 768
#define NH 12
#define HD 64
#define SCALE 0.125f
#define BNEPS 1e-5f
#define OUT_OFF (BB*NSEQ*CDIM)
#define NN ((size_t)NSEQ*NSEQ)

// ---------------- scratch (device globals) -----------------------------------
__device__ uint2 g_xs [BB*NSEQ*CDIM/2];        // x * 16  (half2 hi, half2 lo)
__device__ uint2 g_wqs[3*CDIM*CDIM/2];         // w_qkv * 1024
__device__ uint2 g_wps[CDIM*CDIM/2];           // w_proj * 1024
__device__ uint2 g_qs [BB*NH*NSEQ*HD/2];       // q * 32
__device__ uint2 g_ks [BB*NH*NSEQ*HD/2];       // k * 32
__device__ uint2 g_vts[BB*NH*HD*NSEQ/2];       // v^T * 32, [bh][d][m]
__device__ uint2 g_gts[BB*NSEQ*CDIM/2];        // (attn_n @ v), [b*N+n][c]
__device__ float g_vt [BB*NH*HD*NSEQ];         // raw v^T
__device__ float g_logits[BB*NH*NSEQ*NSEQ];    // exp(SCALE * q.k)
__device__ float g_rs[BB*NH*NSEQ];             // per-row sum of exp
__device__ double g_s1[NH];
__device__ double g_s2[NH];
__device__ float  g_bna[NH];
__device__ float  g_bnc[NH];

// ---------------- helpers -----------------------------------------------------
__device__ __forceinline__ uint32_t s2u(const void* p){
    uint32_t a;
    asm("{ .reg .u64 t; cvta.to.shared.u64 t, %1; cvt.u32.u64 %0, t; }" : "=r"(a) : "l"(p));
    return a;
}
__device__ __forceinline__ uint2 split2(float x0, float x1, float s){
    x0 *= s; x1 *= s;
    __half h0 = __float2half_rn(x0), h1 = __float2half_rn(x1);
    __half g0 = __float2half_rn(x0 - __half2float(h0));
    __half g1 = __float2half_rn(x1 - __half2float(h1));
    __half2 hh = __halves2half2(h0, h1), ll = __halves2half2(g0, g1);
    uint2 r;
    r.x = *(uint32_t*)&hh; r.y = *(uint32_t*)&ll;
    return r;
}
__device__ __forceinline__ void mma16f(float* c, const uint32_t* a, const uint32_t* b){
    asm volatile("mma.sync.aligned.m16n8k16.row.col.f32.f16.f16.f32 "
        "{%0,%1,%2,%3}, {%4,%5,%6,%7}, {%8,%9}, {%0,%1,%2,%3};"
        : "+f"(c[0]), "+f"(c[1]), "+f"(c[2]), "+f"(c[3])
        : "r"(a[0]), "r"(a[1]), "r"(a[2]), "r"(a[3]), "r"(b[0]), "r"(b[1]));
}
__device__ __forceinline__ void mma16h(uint32_t* c, const uint32_t* a, const uint32_t* b){
    asm volatile("mma.sync.aligned.m16n8k16.row.col.f16.f16.f16.f16 "
        "{%0,%1}, {%2,%3,%4,%5}, {%6,%7}, {%0,%1};"
        : "+r"(c[0]), "+r"(c[1])
        : "r"(a[0]), "r"(a[1]), "r"(a[2]), "r"(a[3]), "r"(b[0]), "r"(b[1]));
}
__device__ __forceinline__ void cpa16(uint32_t dst, const void* src){
    asm volatile("cp.async.cg.shared.global [%0], [%1], 16;" :: "r"(dst), "l"(src));
}
#define CPA_COMMIT() asm volatile("cp.async.commit_group;" ::: "memory")

// ---------------- init: zero row sums + BN accumulators ------------------------
__global__ void k_init(){
    int i = blockIdx.x * blockDim.x + threadIdx.x;
    if (i < BB*NH*NSEQ) g_rs[i] = 0.f;
    if (i < NH) { g_s1[i] = 0.0; g_s2[i] = 0.0; }
}

// ---------------- pre-split kernels -------------------------------------------
__global__ void k_split(const float* __restrict__ src, int n2, float s, int sel){
    int i = blockIdx.x * blockDim.x + threadIdx.x;
    if (i >= n2) return;
    const float* p = (sel == 3) ? g_vt : src;
    float2 v = *(const float2*)(p + 2*(size_t)i);
    uint2 r = split2(v.x, v.y, s);
    uint2* d = (sel==0) ? g_xs : (sel==1) ? g_wqs : (sel==2) ? g_wps : g_vts;
    d[i] = r;
}

// shared MMA core: one k32 chunk, hh in fp32 acc, (lh + hl) in fp16 acc
template<int NT, int MT>
__device__ __forceinline__ void mma_chunk(
    const uint2* __restrict__ As_, const uint2* __restrict__ Bs_,
    float accf[MT][NT][4], uint32_t acch[MT][NT][2],
    int wm, int wn, int gid, int tig)
{
    #pragma unroll
    for (int ks = 0; ks < 2; ks++) {
        const int kb = ks * 8;
        uint32_t ah[MT][4], al[MT][4];
        #pragma unroll
        for (int i = 0; i < MT; i++) {
            int mb = wm*32 + i*16 + gid;
            uint2 a0 = As_[mb*20 + kb + tig];
            uint2 a1 = As_[(mb+8)*20 + kb + tig];
            uint2 a2 = As_[mb*20 + kb + tig + 4];
            uint2 a3 = As_[(mb+8)*20 + kb + tig + 4];
            ah[i][0]=a0.x; ah[i][1]=a1.x; ah[i][2]=a2.x; ah[i][3]=a3.x;
            al[i][0]=a0.y; al[i][1]=a1.y; al[i][2]=a2.y; al[i][3]=a3.y;
        }
        #pragma unroll
        for (int j = 0; j < NT; j++) {
            int nb = wn*(NT*8) + j*8 + gid;
            uint2 b0 = Bs_[nb*20 + kb + tig];
            uint2 b1 = Bs_[nb*20 + kb + tig + 4];
            uint32_t bhh[2] = {b0.x, b1.x};
            uint32_t bll[2] = {b0.y, b1.y};
            #pragma unroll
            for (int i = 0; i < MT; i++) {
                mma16f(accf[i][j], ah[i], bhh);
                mma16h(acch[i][j], al[i], bhh);
                mma16h(acch[i][j], ah[i], bll);
            }
        }
    }
}

// ---------------- fp16x3 GEMM (hh fp32-acc, corrections fp16-acc) -------------
// MODE 0: qkv  A=g_xs  B=g_wqs  K=768  -> q,k splits + raw v^T (UN 2^-14, +bias)
// MODE 1: qk   A=g_qs  B=g_ks   K=64   -> exp(SCALE*logit) + row-sum atomics
// MODE 2: av   A=d_out attn (MIXED raw; normalize in place) B=g_vts K=1024 -> g_gts
// MODE 3: proj A=g_gts B=g_wps K=768   -> d_out (UN 2^-10, +bias)
template<int MODE>
__global__ __launch_bounds__(256, 2) void gemm_h(
    const float* __restrict__ bias, float* __restrict__ pC)
{
    constexpr int BM = 128, BN = 64, LDU = 20;
    constexpr int NT = 4, MT = 2;
    constexpr int K   = (MODE==1) ? 64 : (MODE==2) ? 1024 : 768;
    constexpr int NC  = K / 32;
    constexpr int LD2 = K / 2;
    constexpr int STAGE = (BM + BN) * LDU;

    extern __shared__ __align__(16) uint2 sm[];

    const int tid  = threadIdx.x;
    const int lane = tid & 31, warp = tid >> 5;
    const int wm = warp >> 1, wn = warp & 1;
    const int gid = lane >> 2, tig = lane & 3;
    const int Mblk = blockIdx.y * BM;
    const int Nblk = blockIdx.x * BN;
    const int bh   = blockIdx.z;

    const uint2* A2 = nullptr; const uint2* B2;
    if constexpr (MODE == 0)      { A2 = g_xs; B2 = g_wqs; }
    else if constexpr (MODE == 1) { A2 = g_qs + (size_t)bh*NSEQ*(HD/2); B2 = g_ks + (size_t)bh*NSEQ*(HD/2); }
    else if constexpr (MODE == 2) { B2 = g_vts + (size_t)bh*HD*(NSEQ/2); }
    else                          { A2 = g_gts; B2 = g_wps; }

    float accf[MT][NT][4] = {};
    uint32_t acch[MT][NT][2] = {};

    const int pr = tid >> 3;
    const int pq = tid & 7;

    if constexpr (MODE != 2) {
        // ======== cp.async double-buffered path ========
        const uint32_t sb = s2u(sm);
        auto issue = [&](int ch, int s) {
            #pragma unroll
            for (int i = 0; i < 4; i++) {
                int r = pr + i*32;
                cpa16(sb + (uint32_t)((s*STAGE + r*LDU + pq*2) * 8),
                      A2 + (size_t)(Mblk + r)*LD2 + ch*16 + pq*2);
            }
            #pragma unroll
            for (int i = 0; i < 2; i++) {
                int r = pr + i*32;
                cpa16(sb + (uint32_t)((s*STAGE + (BM + r)*LDU + pq*2) * 8),
                      B2 + (size_t)(Nblk + r)*LD2 + ch*16 + pq*2);
            }
            CPA_COMMIT();
        };
        issue(0, 0);
        for (int ch = 0; ch < NC; ch++) {
            if (ch + 1 < NC) {
                issue(ch + 1, (ch + 1) & 1);
                asm volatile("cp.async.wait_group 1;" ::: "memory");
            } else {
                asm volatile("cp.async.wait_group 0;" ::: "memory");
            }
            __syncthreads();
            const uint2* S = sm + (ch & 1) * STAGE;
            mma_chunk<NT, MT>(S, S + BM*LDU, accf, acch, wm, wn, gid, tig);
            __syncthreads();
        }
    } else {
        // ======== AV: mixed A in d_out -> normalize in place -> split ========
        uint2* As_ = sm; uint2* Bs_ = sm + BM*LDU;
        float* Abuf = pC + (size_t)bh*NN;             // pC = d_out + OUT_OFF
        const int g = bh % NH;
        const float na = g_bna[g], ncs = g_bnc[g];

        float4 fa[4]; uint4 pb[2];
        #pragma unroll
        for (int i = 0; i < 4; i++) {
            int r = pr + i*32;
            float* p = Abuf + (size_t)(Mblk + r)*1024 + pq*4;
            float4 v = __ldcs((const float4*)p);
            v.x = fmaf(na, v.x, ncs); v.y = fmaf(na, v.y, ncs);
            v.z = fmaf(na, v.z, ncs); v.w = fmaf(na, v.w, ncs);
            __stcs((float4*)p, v);
            fa[i] = v;
        }
        #pragma unroll
        for (int i = 0; i < 2; i++) {
            int r = pr + i*32;
            pb[i] = *(const uint4*)(B2 + (size_t)(Nblk + r)*LD2 + pq*2);
        }
        for (int ch = 0; ch < NC; ch++) {
            #pragma unroll
            for (int i = 0; i < 4; i++) {
                int r = pr + i*32;
                uint2 u01 = split2(fa[i].x, fa[i].y, 16.f);
                uint2 u23 = split2(fa[i].z, fa[i].w, 16.f);
                uint4 st = {u01.x, u01.y, u23.x, u23.y};
                *(uint4*)&As_[r*LDU + pq*2] = st;
            }
            #pragma unroll
            for (int i = 0; i < 2; i++) {
                int r = pr + i*32;
                *(uint4*)&Bs_[r*LDU + pq*2] = pb[i];
            }
            __syncthreads();
            if (ch + 1 < NC) {
                const int kf = (ch + 1) * 32;
                #pragma unroll
                for (int i = 0; i < 4; i++) {
                    int r = pr + i*32;
                    float* p = Abuf + (size_t)(Mblk + r)*1024 + kf + pq*4;
                    float4 v = __ldcs((const float4*)p);
                    v.x = fmaf(na, v.x, ncs); v.y = fmaf(na, v.y, ncs);
                    v.z = fmaf(na, v.z, ncs); v.w = fmaf(na, v.w, ncs);
                    __stcs((float4*)p, v);
                    fa[i] = v;
                }
                const int k2 = (ch + 1) * 16;
                #pragma unroll
                for (int i = 0; i < 2; i++) {
                    int r = pr + i*32;
                    pb[i] = *(const uint4*)(B2 + (size_t)(Nblk + r)*LD2 + k2 + pq*2);
                }
            }
            mma_chunk<NT, MT>(As_, Bs_, accf, acch, wm, wn, gid, tig);
            __syncthreads();
        }
    }

    // ----------------- epilogue -----------------
    constexpr float UN = (MODE==0) ? (1.f/16384.f) : (MODE==2) ? (1.f/512.f) : (1.f/1024.f);
    if constexpr (MODE == 1) {
        // exp(SCALE * logit) + per-row sum atomics
        #pragma unroll
        for (int i = 0; i < MT; i++) {
            #pragma unroll
            for (int p = 0; p < 2; p++) {
                const int row = Mblk + wm*32 + i*16 + gid + p*8;
                float rsum = 0.f;
                #pragma unroll
                for (int j = 0; j < NT; j++) {
                    __half2 q = *(__half2*)&acch[i][j][p];
                    float2 cc = __half22float2(q);
                    float v0 = (accf[i][j][p*2+0] + cc.x) * UN;
                    float v1 = (accf[i][j][p*2+1] + cc.y) * UN;
                    float e0 = __expf(SCALE * v0);
                    float e1 = __expf(SCALE * v1);
                    int c0 = Nblk + wn*32 + j*8 + tig*2;
                    __stcs((float2*)(g_logits + (size_t)bh*NN + (size_t)row*NSEQ + c0),
                           make_float2(e0, e1));
                    rsum += e0 + e1;
                }
                rsum += __shfl_xor_sync(0xffffffffu, rsum, 1);
                rsum += __shfl_xor_sync(0xffffffffu, rsum, 2);
                if (tig == 0)
                    atomicAdd(&g_rs[(size_t)bh*NSEQ + row], rsum);
            }
        }
    } else {
        #pragma unroll
        for (int i = 0; i < MT; i++) {
            #pragma unroll
            for (int j = 0; j < NT; j++) {
                __half2 q0 = *(__half2*)&acch[i][j][0];
                __half2 q1 = *(__half2*)&acch[i][j][1];
                float2 c01 = __half22float2(q0);
                float2 c23 = __half22float2(q1);
                float cv[4] = {accf[i][j][0] + c01.x, accf[i][j][1] + c01.y,
                               accf[i][j][2] + c23.x, accf[i][j][3] + c23.y};
                int r0 = Mblk + wm*32 + i*16 + gid;
                int c0 = Nblk + wn*32 + j*8 + tig*2;
                #pragma unroll
                for (int p = 0; p < 2; p++) {
                    int row = r0 + p*8;
                    float v0 = cv[p*2+0] * UN, v1 = cv[p*2+1] * UN;
                    if constexpr (MODE == 0) {
                        int t3 = c0 / CDIM; int rem = c0 - t3*CDIM;
                        int h = rem >> 6, d = rem & 63;
                        int b = row >> 10, n = row & (NSEQ - 1);
                        v0 += bias[c0]; v1 += bias[c0+1];
                        if (t3 == 0) {
                            g_qs[((((size_t)(b*NH+h))*NSEQ + n) << 5) + (d >> 1)] = split2(v0, v1, 32.f);
                        } else if (t3 == 1) {
                            g_ks[((((size_t)(b*NH+h))*NSEQ + n) << 5) + (d >> 1)] = split2(v0, v1, 32.f);
                        } else {
                            size_t base = (((size_t)(b*NH+h))*HD + d)*NSEQ + n;
                            g_vt[base]        = v0;
                            g_vt[base + NSEQ] = v1;
                        }
                    } else if constexpr (MODE == 2) {
                        int b = bh / NH, g = bh % NH;
                        g_gts[((size_t)(b*NSEQ + row))*(CDIM/2) + ((g*HD + c0) >> 1)] = split2(v0, v1, 1.f);
                    } else {
                        float2 s = make_float2(v0 + bias[c0], v1 + bias[c0+1]);
                        *(float2*)(pC + (size_t)row*CDIM + c0) = s;
                    }
                }
            }
        }
    }
}

// ---------------- streaming softmax-finish + head mix + BN stats --------------
// one block per (b,n); thread t owns float4 at m=4t; reads exp values and row
// sums (precomputed), writes RAW MIXED straight into d_out's attn slot.
__global__ void k_mix(const float* __restrict__ w_re, const float* __restrict__ b_re,
                      float* __restrict__ dout) {
    __shared__ float wre[NH][NH];
    __shared__ float bre[NH], sinv[NH];
    __shared__ float sm1[NH], sm2[NH];
    const int b = blockIdx.x >> 10;
    const int n = blockIdx.x & 1023;
    const int t = threadIdx.x;               // 256
    const int lane = t & 31;
    if (t < NH*NH) wre[t/NH][t%NH] = w_re[t];
    if (t < NH) {
        bre[t] = b_re[t];
        sinv[t] = 1.0f / g_rs[((size_t)(b*NH + t))*NSEQ + n];
        sm1[t] = 0.f; sm2[t] = 0.f;
    }
    __syncthreads();
    const int m = t << 2;
    float L[NH][4];
    #pragma unroll
    for (int h = 0; h < NH; h++) {
        float4 e = *(const float4*)(g_logits + (((size_t)(b*NH+h))*NSEQ + n)*NSEQ + m);
        float si = sinv[h];
        L[h][0] = e.x*si; L[h][1] = e.y*si; L[h][2] = e.z*si; L[h][3] = e.w*si;
    }
    float* attn = dout + OUT_OFF;
    #pragma unroll
    for (int g = 0; g < NH; g++) {
        float o0=bre[g], o1=bre[g], o2=bre[g], o3=bre[g];
        #pragma unroll
        for (int h = 0; h < NH; h++) {
            float w = wre[g][h];
            o0 = fmaf(w, L[h][0], o0); o1 = fmaf(w, L[h][1], o1);
            o2 = fmaf(w, L[h][2], o2); o3 = fmaf(w, L[h][3], o3);
        }
        float4 st = {o0, o1, o2, o3};
        *(float4*)(attn + (((size_t)(b*NH+g))*NSEQ + n)*NSEQ + m) = st;
        float a = (o0+o1)+(o2+o3);
        float c = o0*o0+o1*o1+o2*o2+o3*o3;
        #pragma unroll
        for (int o = 16; o; o >>= 1) {
            a += __shfl_xor_sync(0xffffffffu, a, o);
            c += __shfl_xor_sync(0xffffffffu, c, o);
        }
        if (lane == 0) { atomicAdd(&sm1[g], a); atomicAdd(&sm2[g], c); }
    }
    __syncthreads();
    if (t < NH) {
        atomicAdd(&g_s1[t], (double)sm1[t]);
        atomicAdd(&g_s2[t], (double)sm2[t]);
    }
}

// ---------------- BN finalize (double precision) -----------------------------
__global__ void k_bnfin(const float* __restrict__ gamma, const float* __restrict__ beta) {
    int g = threadIdx.x;
    if (g < NH) {
        double cnt = (double)BB * NSEQ * NSEQ;
        double mean = g_s1[g] / cnt;
        double var  = g_s2[g] / cnt - mean * mean;
        float a = (float)((double)gamma[g] / sqrt(var + (double)BNEPS));
        g_bna[g] = a;
        g_bnc[g] = beta[g] - a * (float)mean;
    }
}

// ---------------- launcher ----------------------------------------------------
extern "C" void kernel_launch(void* const* d_in, const int* in_sizes, int n_in,
                              void* d_out, int out_size) {
    const float* x    = (const float*)d_in[0];
    const float* wqkv = (const float*)d_in[1];
    const float* bqkv = (const float*)d_in[2];
    const float* wre  = (const float*)d_in[3];
    const float* bre  = (const float*)d_in[4];
    const float* gam  = (const float*)d_in[5];
    const float* bet  = (const float*)d_in[6];
    const float* wp   = (const float*)d_in[7];
    const float* bp   = (const float*)d_in[8];
    float* out = (float*)d_out;

    const int SM2 = 2 * (128 + 64) * 20 * 8;   // 61440
    const int SM1 = (128 + 64) * 20 * 8;       // 30720
    cudaFuncSetAttribute(gemm_h<0>, cudaFuncAttributeMaxDynamicSharedMemorySize, SM2);
    cudaFuncSetAttribute(gemm_h<1>, cudaFuncAttributeMaxDynamicSharedMemorySize, SM2);
    cudaFuncSetAttribute(gemm_h<2>, cudaFuncAttributeMaxDynamicSharedMemorySize, SM1);
    cudaFuncSetAttribute(gemm_h<3>, cudaFuncAttributeMaxDynamicSharedMemorySize, SM2);

    k_init<<<96, 1024>>>();
    k_split<<<12288, 256>>>(x,    3145728, 16.f,   0);   // x -> g_xs
    k_split<<<3456,  256>>>(wqkv,  884736, 1024.f, 1);   // w_qkv -> g_wqs
    k_split<<<1152,  256>>>(wp,    294912, 1024.f, 2);   // w_proj -> g_wps
    gemm_h<0><<<dim3(36, 64, 1), 256, SM2>>>(bqkv, nullptr);          // qkv
    k_split<<<12288, 256>>>(nullptr, 3145728, 32.f, 3);  // g_vt -> g_vts
    gemm_h<1><<<dim3(16, 8, 96), 256, SM2>>>(nullptr, nullptr);       // qk -> exp + rowsums
    k_mix<<<8192, 256>>>(wre, bre, out);                 // mixed -> d_out attn
    k_bnfin<<<1, 32>>>(gam, bet);
    gemm_h<2><<<dim3(1, 8, 96),  256, SM1>>>(nullptr, out + OUT_OFF); // av + in-place norm
    gemm_h<3><<<dim3(12, 64, 1), 256, SM2>>>(bp, out);                // proj
}

// round 8
// speedup vs baseline: 1.5457x; 1.0074x over previous
#include <cuda_runtime.h>
#include <cuda_fp16.h>
#include <math.h>
#include <stdint.h>

#define BB 8
#define NSEQ 1024
#define CDIM 768
#define NH 12
#define HD 64
#define SCALE 0.125f
#define BNEPS 1e-5f
#define OUT_OFF (BB*NSEQ*CDIM)
#define NN ((size_t)NSEQ*NSEQ)

// ---------------- scratch (device globals) -----------------------------------
__device__ uint2 g_xs [BB*NSEQ*CDIM/2];        // x * 16  (half2 hi, half2 lo)
__device__ uint2 g_wqs[3*CDIM*CDIM/2];         // w_qkv * 1024
__device__ uint2 g_wps[CDIM*CDIM/2];           // w_proj * 1024
__device__ uint2 g_qs [BB*NH*NSEQ*HD/2];       // q * 32
__device__ uint2 g_ks [BB*NH*NSEQ*HD/2];       // k * 32
__device__ uint2 g_vts[BB*NH*HD*NSEQ/2];       // v^T * 32, [bh][d][m]
__device__ uint2 g_gts[BB*NSEQ*CDIM/2];        // (attn_n @ v), [b*N+n][c]
__device__ float g_vt [BB*NH*HD*NSEQ];         // raw v^T
__device__ float g_logits[BB*NH*NSEQ*NSEQ];    // exp(SCALE * q.k)
__device__ float g_rs[BB*NH*NSEQ];             // per-row sum of exp
__device__ double g_s1[NH];
__device__ double g_s2[NH];
__device__ float  g_bna[NH];
__device__ float  g_bnc[NH];

// ---------------- helpers -----------------------------------------------------
__device__ __forceinline__ uint32_t s2u(const void* p){
    uint32_t a;
    asm("{ .reg .u64 t; cvta.to.shared.u64 t, %1; cvt.u32.u64 %0, t; }" : "=r"(a) : "l"(p));
    return a;
}
__device__ __forceinline__ uint2 split2(float x0, float x1, float s){
    x0 *= s; x1 *= s;
    __half h0 = __float2half_rn(x0), h1 = __float2half_rn(x1);
    __half g0 = __float2half_rn(x0 - __half2float(h0));
    __half g1 = __float2half_rn(x1 - __half2float(h1));
    __half2 hh = __halves2half2(h0, h1), ll = __halves2half2(g0, g1);
    uint2 r;
    r.x = *(uint32_t*)&hh; r.y = *(uint32_t*)&ll;
    return r;
}
__device__ __forceinline__ void mma16f(float* c, const uint32_t* a, const uint32_t* b){
    asm volatile("mma.sync.aligned.m16n8k16.row.col.f32.f16.f16.f32 "
        "{%0,%1,%2,%3}, {%4,%5,%6,%7}, {%8,%9}, {%0,%1,%2,%3};"
        : "+f"(c[0]), "+f"(c[1]), "+f"(c[2]), "+f"(c[3])
        : "r"(a[0]), "r"(a[1]), "r"(a[2]), "r"(a[3]), "r"(b[0]), "r"(b[1]));
}
__device__ __forceinline__ void mma16h(uint32_t* c, const uint32_t* a, const uint32_t* b){
    asm volatile("mma.sync.aligned.m16n8k16.row.col.f16.f16.f16.f16 "
        "{%0,%1}, {%2,%3,%4,%5}, {%6,%7}, {%0,%1};"
        : "+r"(c[0]), "+r"(c[1])
        : "r"(a[0]), "r"(a[1]), "r"(a[2]), "r"(a[3]), "r"(b[0]), "r"(b[1]));
}
__device__ __forceinline__ void cpa16(uint32_t dst, const void* src){
    asm volatile("cp.async.cg.shared.global [%0], [%1], 16;" :: "r"(dst), "l"(src));
}
#define CPA_COMMIT() asm volatile("cp.async.commit_group;" ::: "memory")

// ---------------- init: zero row sums + BN accumulators ------------------------
__global__ void k_init(){
    int i = blockIdx.x * blockDim.x + threadIdx.x;
    if (i < BB*NH*NSEQ) g_rs[i] = 0.f;
    if (i < NH) { g_s1[i] = 0.0; g_s2[i] = 0.0; }
}

// ---------------- pre-split kernels -------------------------------------------
__global__ void k_split(const float* __restrict__ src, int n2, float s, int sel){
    int i = blockIdx.x * blockDim.x + threadIdx.x;
    if (i >= n2) return;
    const float* p = (sel == 3) ? g_vt : src;
    float2 v = *(const float2*)(p + 2*(size_t)i);
    uint2 r = split2(v.x, v.y, s);
    uint2* d = (sel==0) ? g_xs : (sel==1) ? g_wqs : (sel==2) ? g_wps : g_vts;
    d[i] = r;
}

// shared MMA core: one k32 chunk, hh in fp32 acc, (lh + hl) in fp16 acc
template<int NT, int MT>
__device__ __forceinline__ void mma_chunk(
    const uint2* __restrict__ As_, const uint2* __restrict__ Bs_,
    float accf[MT][NT][4], uint32_t acch[MT][NT][2],
    int wm, int wn, int gid, int tig)
{
    #pragma unroll
    for (int ks = 0; ks < 2; ks++) {
        const int kb = ks * 8;
        uint32_t ah[MT][4], al[MT][4];
        #pragma unroll
        for (int i = 0; i < MT; i++) {
            int mb = wm*32 + i*16 + gid;
            uint2 a0 = As_[mb*20 + kb + tig];
            uint2 a1 = As_[(mb+8)*20 + kb + tig];
            uint2 a2 = As_[mb*20 + kb + tig + 4];
            uint2 a3 = As_[(mb+8)*20 + kb + tig + 4];
            ah[i][0]=a0.x; ah[i][1]=a1.x; ah[i][2]=a2.x; ah[i][3]=a3.x;
            al[i][0]=a0.y; al[i][1]=a1.y; al[i][2]=a2.y; al[i][3]=a3.y;
        }
        #pragma unroll
        for (int j = 0; j < NT; j++) {
            int nb = wn*(NT*8) + j*8 + gid;
            uint2 b0 = Bs_[nb*20 + kb + tig];
            uint2 b1 = Bs_[nb*20 + kb + tig + 4];
            uint32_t bhh[2] = {b0.x, b1.x};
            uint32_t bll[2] = {b0.y, b1.y};
            #pragma unroll
            for (int i = 0; i < MT; i++) {
                mma16f(accf[i][j], ah[i], bhh);
                mma16h(acch[i][j], al[i], bhh);
                mma16h(acch[i][j], ah[i], bll);
            }
        }
    }
}

// ---------------- fp16x3 GEMM (hh fp32-acc, corrections fp16-acc) -------------
// MODE 0: qkv  A=g_xs  B=g_wqs  K=768  -> q,k splits + raw v^T (UN 2^-14, +bias)
// MODE 1: qk   A=g_qs  B=g_ks   K=64   -> exp(SCALE*logit) + row-sum atomics
// MODE 2: av   A=d_out attn (MIXED raw; normalize in place) B=g_vts K=1024 -> g_gts
// MODE 3: proj A=g_gts B=g_wps K=768   -> d_out (UN 2^-10, +bias)
template<int MODE>
__global__ __launch_bounds__(256, 2) void gemm_h(
    const float* __restrict__ bias, float* __restrict__ pC)
{
    constexpr int BM = 128, BN = 64, LDU = 20;
    constexpr int NT = 4, MT = 2;
    constexpr int K   = (MODE==1) ? 64 : (MODE==2) ? 1024 : 768;
    constexpr int NC  = K / 32;
    constexpr int LD2 = K / 2;
    constexpr int STAGE = (BM + BN) * LDU;

    extern __shared__ __align__(16) uint2 sm[];

    const int tid  = threadIdx.x;
    const int lane = tid & 31, warp = tid >> 5;
    const int wm = warp >> 1, wn = warp & 1;
    const int gid = lane >> 2, tig = lane & 3;
    const int Mblk = blockIdx.y * BM;
    const int Nblk = blockIdx.x * BN;
    const int bh   = blockIdx.z;

    const uint2* A2 = nullptr; const uint2* B2;
    if constexpr (MODE == 0)      { A2 = g_xs; B2 = g_wqs; }
    else if constexpr (MODE == 1) { A2 = g_qs + (size_t)bh*NSEQ*(HD/2); B2 = g_ks + (size_t)bh*NSEQ*(HD/2); }
    else if constexpr (MODE == 2) { B2 = g_vts + (size_t)bh*HD*(NSEQ/2); }
    else                          { A2 = g_gts; B2 = g_wps; }

    float accf[MT][NT][4] = {};
    uint32_t acch[MT][NT][2] = {};

    const int pr = tid >> 3;
    const int pq = tid & 7;

    if constexpr (MODE != 2) {
        // ======== 3-stage cp.async pipeline, one barrier per chunk ========
        const uint32_t sb = s2u(sm);
        auto issue = [&](int ch, int s) {
            #pragma unroll
            for (int i = 0; i < 4; i++) {
                int r = pr + i*32;
                cpa16(sb + (uint32_t)((s*STAGE + r*LDU + pq*2) * 8),
                      A2 + (size_t)(Mblk + r)*LD2 + ch*16 + pq*2);
            }
            #pragma unroll
            for (int i = 0; i < 2; i++) {
                int r = pr + i*32;
                cpa16(sb + (uint32_t)((s*STAGE + (BM + r)*LDU + pq*2) * 8),
                      B2 + (size_t)(Nblk + r)*LD2 + ch*16 + pq*2);
            }
            CPA_COMMIT();
        };
        issue(0, 0);
        if (NC > 1) issue(1, 1);
        int s_cur = 0, s_nxt2 = 2;
        for (int ch = 0; ch < NC; ch++) {
            if (ch < NC - 1) {
                asm volatile("cp.async.wait_group 1;" ::: "memory");
            } else {
                asm volatile("cp.async.wait_group 0;" ::: "memory");
            }
            __syncthreads();
            if (ch + 2 < NC) issue(ch + 2, s_nxt2);
            const uint2* S = sm + s_cur * STAGE;
            mma_chunk<NT, MT>(S, S + BM*LDU, accf, acch, wm, wn, gid, tig);
            s_cur = (s_cur == 2) ? 0 : s_cur + 1;
            s_nxt2 = (s_nxt2 == 2) ? 0 : s_nxt2 + 1;
        }
        __syncthreads();   // protect smem reuse across exit (none) / uniformity
    } else {
        // ======== AV: double-buffered manual staging, one barrier per chunk ====
        float* Abuf = pC + (size_t)bh*NN;             // pC = d_out + OUT_OFF
        const int g = bh % NH;
        const float na = g_bna[g], ncs = g_bnc[g];

        float4 fa[4]; uint4 pb[2];
        #pragma unroll
        for (int i = 0; i < 4; i++) {
            int r = pr + i*32;
            float* p = Abuf + (size_t)(Mblk + r)*1024 + pq*4;
            float4 v = __ldcs((const float4*)p);
            v.x = fmaf(na, v.x, ncs); v.y = fmaf(na, v.y, ncs);
            v.z = fmaf(na, v.z, ncs); v.w = fmaf(na, v.w, ncs);
            __stcs((float4*)p, v);
            fa[i] = v;
        }
        #pragma unroll
        for (int i = 0; i < 2; i++) {
            int r = pr + i*32;
            pb[i] = *(const uint4*)(B2 + (size_t)(Nblk + r)*LD2 + pq*2);
        }
        for (int ch = 0; ch < NC; ch++) {
            uint2* As_ = sm + (ch & 1) * STAGE;
            uint2* Bs_ = As_ + BM*LDU;
            #pragma unroll
            for (int i = 0; i < 4; i++) {
                int r = pr + i*32;
                uint2 u01 = split2(fa[i].x, fa[i].y, 16.f);
                uint2 u23 = split2(fa[i].z, fa[i].w, 16.f);
                uint4 st = {u01.x, u01.y, u23.x, u23.y};
                *(uint4*)&As_[r*LDU + pq*2] = st;
            }
            #pragma unroll
            for (int i = 0; i < 2; i++) {
                int r = pr + i*32;
                *(uint4*)&Bs_[r*LDU + pq*2] = pb[i];
            }
            if (ch + 1 < NC) {
                const int kf = (ch + 1) * 32;
                #pragma unroll
                for (int i = 0; i < 4; i++) {
                    int r = pr + i*32;
                    float* p = Abuf + (size_t)(Mblk + r)*1024 + kf + pq*4;
                    float4 v = __ldcs((const float4*)p);
                    v.x = fmaf(na, v.x, ncs); v.y = fmaf(na, v.y, ncs);
                    v.z = fmaf(na, v.z, ncs); v.w = fmaf(na, v.w, ncs);
                    __stcs((float4*)p, v);
                    fa[i] = v;
                }
                const int k2 = (ch + 1) * 16;
                #pragma unroll
                for (int i = 0; i < 2; i++) {
                    int r = pr + i*32;
                    pb[i] = *(const uint4*)(B2 + (size_t)(Nblk + r)*LD2 + k2 + pq*2);
                }
            }
            __syncthreads();
            mma_chunk<NT, MT>(As_, Bs_, accf, acch, wm, wn, gid, tig);
        }
    }

    // ----------------- epilogue -----------------
    constexpr float UN = (MODE==0) ? (1.f/16384.f) : (MODE==2) ? (1.f/512.f) : (1.f/1024.f);
    if constexpr (MODE == 1) {
        #pragma unroll
        for (int i = 0; i < MT; i++) {
            #pragma unroll
            for (int p = 0; p < 2; p++) {
                const int row = Mblk + wm*32 + i*16 + gid + p*8;
                float rsum = 0.f;
                #pragma unroll
                for (int j = 0; j < NT; j++) {
                    __half2 q = *(__half2*)&acch[i][j][p];
                    float2 cc = __half22float2(q);
                    float v0 = (accf[i][j][p*2+0] + cc.x) * UN;
                    float v1 = (accf[i][j][p*2+1] + cc.y) * UN;
                    float e0 = __expf(SCALE * v0);
                    float e1 = __expf(SCALE * v1);
                    int c0 = Nblk + wn*32 + j*8 + tig*2;
                    __stcs((float2*)(g_logits + (size_t)bh*NN + (size_t)row*NSEQ + c0),
                           make_float2(e0, e1));
                    rsum += e0 + e1;
                }
                rsum += __shfl_xor_sync(0xffffffffu, rsum, 1);
                rsum += __shfl_xor_sync(0xffffffffu, rsum, 2);
                if (tig == 0)
                    atomicAdd(&g_rs[(size_t)bh*NSEQ + row], rsum);
            }
        }
    } else {
        #pragma unroll
        for (int i = 0; i < MT; i++) {
            #pragma unroll
            for (int j = 0; j < NT; j++) {
                __half2 q0 = *(__half2*)&acch[i][j][0];
                __half2 q1 = *(__half2*)&acch[i][j][1];
                float2 c01 = __half22float2(q0);
                float2 c23 = __half22float2(q1);
                float cv[4] = {accf[i][j][0] + c01.x, accf[i][j][1] + c01.y,
                               accf[i][j][2] + c23.x, accf[i][j][3] + c23.y};
                int r0 = Mblk + wm*32 + i*16 + gid;
                int c0 = Nblk + wn*32 + j*8 + tig*2;
                #pragma unroll
                for (int p = 0; p < 2; p++) {
                    int row = r0 + p*8;
                    float v0 = cv[p*2+0] * UN, v1 = cv[p*2+1] * UN;
                    if constexpr (MODE == 0) {
                        int t3 = c0 / CDIM; int rem = c0 - t3*CDIM;
                        int h = rem >> 6, d = rem & 63;
                        int b = row >> 10, n = row & (NSEQ - 1);
                        v0 += bias[c0]; v1 += bias[c0+1];
                        if (t3 == 0) {
                            g_qs[((((size_t)(b*NH+h))*NSEQ + n) << 5) + (d >> 1)] = split2(v0, v1, 32.f);
                        } else if (t3 == 1) {
                            g_ks[((((size_t)(b*NH+h))*NSEQ + n) << 5) + (d >> 1)] = split2(v0, v1, 32.f);
                        } else {
                            size_t base = (((size_t)(b*NH+h))*HD + d)*NSEQ + n;
                            g_vt[base]        = v0;
                            g_vt[base + NSEQ] = v1;
                        }
                    } else if constexpr (MODE == 2) {
                        int b = bh / NH, g = bh % NH;
                        g_gts[((size_t)(b*NSEQ + row))*(CDIM/2) + ((g*HD + c0) >> 1)] = split2(v0, v1, 1.f);
                    } else {
                        float2 s = make_float2(v0 + bias[c0], v1 + bias[c0+1]);
                        *(float2*)(pC + (size_t)row*CDIM + c0) = s;
                    }
                }
            }
        }
    }
}

// ---------------- streaming softmax-finish + head mix + BN stats --------------
__global__ void k_mix(const float* __restrict__ w_re, const float* __restrict__ b_re,
                      float* __restrict__ dout) {
    __shared__ float wre[NH][NH];
    __shared__ float bre[NH], sinv[NH];
    __shared__ float sm1[NH], sm2[NH];
    const int b = blockIdx.x >> 10;
    const int n = blockIdx.x & 1023;
    const int t = threadIdx.x;               // 256
    const int lane = t & 31;
    if (t < NH*NH) wre[t/NH][t%NH] = w_re[t];
    if (t < NH) {
        bre[t] = b_re[t];
        sinv[t] = 1.0f / g_rs[((size_t)(b*NH + t))*NSEQ + n];
        sm1[t] = 0.f; sm2[t] = 0.f;
    }
    __syncthreads();
    const int m = t << 2;
    float L[NH][4];
    #pragma unroll
    for (int h = 0; h < NH; h++) {
        float4 e = *(const float4*)(g_logits + (((size_t)(b*NH+h))*NSEQ + n)*NSEQ + m);
        float si = sinv[h];
        L[h][0] = e.x*si; L[h][1] = e.y*si; L[h][2] = e.z*si; L[h][3] = e.w*si;
    }
    float* attn = dout + OUT_OFF;
    #pragma unroll
    for (int g = 0; g < NH; g++) {
        float o0=bre[g], o1=bre[g], o2=bre[g], o3=bre[g];
        #pragma unroll
        for (int h = 0; h < NH; h++) {
            float w = wre[g][h];
            o0 = fmaf(w, L[h][0], o0); o1 = fmaf(w, L[h][1], o1);
            o2 = fmaf(w, L[h][2], o2); o3 = fmaf(w, L[h][3], o3);
        }
        float4 st = {o0, o1, o2, o3};
        *(float4*)(attn + (((size_t)(b*NH+g))*NSEQ + n)*NSEQ + m) = st;
        float a = (o0+o1)+(o2+o3);
        float c = o0*o0+o1*o1+o2*o2+o3*o3;
        #pragma unroll
        for (int o = 16; o; o >>= 1) {
            a += __shfl_xor_sync(0xffffffffu, a, o);
            c += __shfl_xor_sync(0xffffffffu, c, o);
        }
        if (lane == 0) { atomicAdd(&sm1[g], a); atomicAdd(&sm2[g], c); }
    }
    __syncthreads();
    if (t < NH) {
        atomicAdd(&g_s1[t], (double)sm1[t]);
        atomicAdd(&g_s2[t], (double)sm2[t]);
    }
}

// ---------------- BN finalize (double precision) -----------------------------
__global__ void k_bnfin(const float* __restrict__ gamma, const float* __restrict__ beta) {
    int g = threadIdx.x;
    if (g < NH) {
        double cnt = (double)BB * NSEQ * NSEQ;
        double mean = g_s1[g] / cnt;
        double var  = g_s2[g] / cnt - mean * mean;
        float a = (float)((double)gamma[g] / sqrt(var + (double)BNEPS));
        g_bna[g] = a;
        g_bnc[g] = beta[g] - a * (float)mean;
    }
}

// ---------------- launcher ----------------------------------------------------
extern "C" void kernel_launch(void* const* d_in, const int* in_sizes, int n_in,
                              void* d_out, int out_size) {
    const float* x    = (const float*)d_in[0];
    const float* wqkv = (const float*)d_in[1];
    const float* bqkv = (const float*)d_in[2];
    const float* wre  = (const float*)d_in[3];
    const float* bre  = (const float*)d_in[4];
    const float* gam  = (const float*)d_in[5];
    const float* bet  = (const float*)d_in[6];
    const float* wp   = (const float*)d_in[7];
    const float* bp   = (const float*)d_in[8];
    float* out = (float*)d_out;

    const int SM3 = 3 * (128 + 64) * 20 * 8;   // 92160 (3-stage cp.async)
    const int SM2 = 2 * (128 + 64) * 20 * 8;   // 61440 (MODE 2 double buffer)
    cudaFuncSetAttribute(gemm_h<0>, cudaFuncAttributeMaxDynamicSharedMemorySize, SM3);
    cudaFuncSetAttribute(gemm_h<1>, cudaFuncAttributeMaxDynamicSharedMemorySize, SM3);
    cudaFuncSetAttribute(gemm_h<2>, cudaFuncAttributeMaxDynamicSharedMemorySize, SM2);
    cudaFuncSetAttribute(gemm_h<3>, cudaFuncAttributeMaxDynamicSharedMemorySize, SM3);

    k_init<<<96, 1024>>>();                                           // 1
    k_split<<<12288, 256>>>(x,    3145728, 16.f,   0);                // 2: x -> g_xs
    k_split<<<3456,  256>>>(wqkv,  884736, 1024.f, 1);                // 3: w_qkv -> g_wqs
    gemm_h<0><<<dim3(36, 64, 1), 256, SM3>>>(bqkv, nullptr);          // 4: qkv (PROFILED)
    k_split<<<1152,  256>>>(wp,    294912, 1024.f, 2);                // 5: w_proj -> g_wps
    k_split<<<12288, 256>>>(nullptr, 3145728, 32.f, 3);               // 6: g_vt -> g_vts
    gemm_h<1><<<dim3(16, 8, 96), 256, SM3>>>(nullptr, nullptr);       // 7: qk -> exp+rowsum
    k_mix<<<8192, 256>>>(wre, bre, out);                              // 8: mixed -> d_out
    k_bnfin<<<1, 32>>>(gam, bet);                                     // 9
    gemm_h<2><<<dim3(1, 8, 96),  256, SM2>>>(nullptr, out + OUT_OFF); // 10: av + norm
    gemm_h<3><<<dim3(12, 64, 1), 256, SM3>>>(bp, out);                // 11: proj
}

// round 9
// speedup vs baseline: 1.7045x; 1.1027x over previous
#include <cuda_runtime.h>
#include <cuda_fp16.h>
#include <math.h>
#include <stdint.h>

#define BB 8
#define NSEQ 1024
#define CDIM 768
#define NH 12
#define HD 64
#define SCALE 0.125f
#define BNEPS 1e-5f
#define OUT_OFF (BB*NSEQ*CDIM)
#define NN ((size_t)NSEQ*NSEQ)

// ---------------- scratch: separate hi/lo half planes --------------------------
__device__ __half g_xh [BB*NSEQ*CDIM],  g_xl [BB*NSEQ*CDIM];    // x * 16
__device__ __half g_wqh[3*CDIM*CDIM],   g_wql[3*CDIM*CDIM];     // w_qkv * 1024
__device__ __half g_wph[CDIM*CDIM],     g_wpl[CDIM*CDIM];       // w_proj * 1024
__device__ __half g_qh [BB*NH*NSEQ*HD], g_ql [BB*NH*NSEQ*HD];   // q * 32
__device__ __half g_kh [BB*NH*NSEQ*HD], g_kl [BB*NH*NSEQ*HD];   // k * 32
__device__ __half g_vth[BB*NH*HD*NSEQ], g_vtl[BB*NH*HD*NSEQ];   // v^T * 32 [bh][d][m]
__device__ __half g_gh [BB*NSEQ*CDIM],  g_gl [BB*NSEQ*CDIM];    // attn@v [b*N+n][c]
__device__ float  g_vt [BB*NH*HD*NSEQ];                          // raw v^T
__device__ float  g_logits[BB*NH*NSEQ*NSEQ];                     // exp(SCALE*q.k)
__device__ float  g_rs[BB*NH*NSEQ];
__device__ double g_s1[NH];
__device__ double g_s2[NH];
__device__ float  g_bna[NH];
__device__ float  g_bnc[NH];

// ---------------- helpers -------------------------------------------------------
__device__ __forceinline__ uint32_t s2u(const void* p){
    uint32_t a;
    asm("{ .reg .u64 t; cvta.to.shared.u64 t, %1; cvt.u32.u64 %0, t; }" : "=r"(a) : "l"(p));
    return a;
}
__device__ __forceinline__ uint2 split2(float x0, float x1, float s){
    x0 *= s; x1 *= s;
    __half h0 = __float2half_rn(x0), h1 = __float2half_rn(x1);
    __half g0 = __float2half_rn(x0 - __half2float(h0));
    __half g1 = __float2half_rn(x1 - __half2float(h1));
    __half2 hh = __halves2half2(h0, h1), ll = __halves2half2(g0, g1);
    uint2 r;
    r.x = *(uint32_t*)&hh; r.y = *(uint32_t*)&ll;
    return r;
}
__device__ __forceinline__ void mma16f(float* c, const uint32_t* a, const uint32_t* b){
    asm volatile("mma.sync.aligned.m16n8k16.row.col.f32.f16.f16.f32 "
        "{%0,%1,%2,%3}, {%4,%5,%6,%7}, {%8,%9}, {%0,%1,%2,%3};"
        : "+f"(c[0]), "+f"(c[1]), "+f"(c[2]), "+f"(c[3])
        : "r"(a[0]), "r"(a[1]), "r"(a[2]), "r"(a[3]), "r"(b[0]), "r"(b[1]));
}
__device__ __forceinline__ void mma16h(uint32_t* c, const uint32_t* a, const uint32_t* b){
    asm volatile("mma.sync.aligned.m16n8k16.row.col.f16.f16.f16.f16 "
        "{%0,%1}, {%2,%3,%4,%5}, {%6,%7}, {%0,%1};"
        : "+r"(c[0]), "+r"(c[1])
        : "r"(a[0]), "r"(a[1]), "r"(a[2]), "r"(a[3]), "r"(b[0]), "r"(b[1]));
}
__device__ __forceinline__ void ldsm4(uint32_t& r0, uint32_t& r1, uint32_t& r2,
                                      uint32_t& r3, uint32_t addr){
    asm volatile("ldmatrix.sync.aligned.m8n8.x4.shared.b16 {%0,%1,%2,%3}, [%4];"
        : "=r"(r0), "=r"(r1), "=r"(r2), "=r"(r3) : "r"(addr));
}
__device__ __forceinline__ void cpa16(uint32_t dst, const void* src){
    asm volatile("cp.async.cg.shared.global [%0], [%1], 16;" :: "r"(dst), "l"(src));
}
#define CPA_COMMIT() asm volatile("cp.async.commit_group;" ::: "memory")
// swizzled byte offset of 16B unit (row, kg) inside a [rows][64B] plane
#define USWZ(row, kg) ((row)*64 + (((kg) ^ (((row)>>1)&3)) << 4))

// ---------------- init ----------------------------------------------------------
__global__ void k_init(){
    int i = blockIdx.x * blockDim.x + threadIdx.x;
    if (i < BB*NH*NSEQ) g_rs[i] = 0.f;
    if (i < NH) { g_s1[i] = 0.0; g_s2[i] = 0.0; }
}

// ---------------- pre-split: fp32 -> hi/lo half planes ---------------------------
__global__ void k_split(const float* __restrict__ src, int n8, float s, int sel){
    int i = blockIdx.x * blockDim.x + threadIdx.x;
    if (i >= n8) return;
    const float* p = (sel == 3) ? g_vt : src;
    float4 a = *(const float4*)(p + 8*(size_t)i);
    float4 b = *(const float4*)(p + 8*(size_t)i + 4);
    uint2 u0 = split2(a.x, a.y, s), u1 = split2(a.z, a.w, s);
    uint2 u2 = split2(b.x, b.y, s), u3 = split2(b.z, b.w, s);
    __half* dh = (sel==0) ? g_xh : (sel==1) ? g_wqh : (sel==2) ? g_wph : g_vth;
    __half* dl = (sel==0) ? g_xl : (sel==1) ? g_wql : (sel==2) ? g_wpl : g_vtl;
    uint4 vh = {u0.x, u1.x, u2.x, u3.x};
    uint4 vl = {u0.y, u1.y, u2.y, u3.y};
    *(uint4*)(dh + 8*(size_t)i) = vh;
    *(uint4*)(dl + 8*(size_t)i) = vl;
}

// ---------------- ldmatrix MMA core: one k32 chunk -------------------------------
// planes: A [128][64B], B [64][64B]; hh fp32-acc, (lh + hl) fp16-acc
template<int NT, int MT>
__device__ __forceinline__ void mma_chunk_p(
    uint32_t ah_b, uint32_t al_b, uint32_t bh_b, uint32_t bl_b,
    const int* rba, const int* swa, int kha,
    const int* rbb, const int* swb, int khb,
    float accf[MT][NT][4], uint32_t acch[MT][NT][2])
{
    #pragma unroll
    for (int ks = 0; ks < 2; ks++) {
        uint32_t ah[MT][4], al[MT][4];
        #pragma unroll
        for (int i = 0; i < MT; i++) {
            int kg = ks*2 + kha;
            uint32_t off = rba[i] + (((uint32_t)(kg ^ swa[i])) << 4);
            ldsm4(ah[i][0], ah[i][1], ah[i][2], ah[i][3], ah_b + off);
            ldsm4(al[i][0], al[i][1], al[i][2], al[i][3], al_b + off);
        }
        #pragma unroll
        for (int grp = 0; grp < NT/2; grp++) {
            int kg = ks*2 + khb;
            uint32_t off = rbb[grp] + (((uint32_t)(kg ^ swb[grp])) << 4);
            uint32_t bh4[4], bl4[4];
            ldsm4(bh4[0], bh4[1], bh4[2], bh4[3], bh_b + off);
            ldsm4(bl4[0], bl4[1], bl4[2], bl4[3], bl_b + off);
            #pragma unroll
            for (int jj = 0; jj < 2; jj++) {
                int j = grp*2 + jj;
                uint32_t bh2[2] = {bh4[jj*2], bh4[jj*2+1]};
                uint32_t bl2[2] = {bl4[jj*2], bl4[jj*2+1]};
                #pragma unroll
                for (int i = 0; i < MT; i++) {
                    mma16f(accf[i][j], ah[i], bh2);
                    mma16h(acch[i][j], al[i], bh2);
                    mma16h(acch[i][j], ah[i], bl2);
                }
            }
        }
    }
}

// ---------------- fp16x3 GEMM ----------------------------------------------------
// MODE 0: qkv  A=g_x*  B=g_wq* K=768  -> q,k planes + raw v^T (UN 2^-14, +bias)
// MODE 1: qk   A=g_q*  B=g_k*  K=64   -> exp(SCALE*logit) + row-sum atomics
// MODE 2: av   A=d_out attn (normalize in place) B=g_vt* K=1024 -> g_g* planes
// MODE 3: proj A=g_g*  B=g_wp* K=768  -> d_out (UN 2^-10, +bias)
template<int MODE>
__global__ __launch_bounds__(256, 2) void gemm_h(
    const float* __restrict__ bias, float* __restrict__ pC)
{
    constexpr int BM = 128, BN = 64;
    constexpr int NT = 4, MT = 2;
    constexpr int K   = (MODE==1) ? 64 : (MODE==2) ? 1024 : 768;
    constexpr int NC  = K / 32;
    // stage layout (modes 0/1/3): Ah 0, Al 8192, Bh 16384, Bl 20480 ; 24576 total
    constexpr int STG = 24576;

    extern __shared__ __align__(16) char smem[];

    const int tid  = threadIdx.x;
    const int lane = tid & 31, warp = tid >> 5;
    const int wm = warp >> 1, wn = warp & 1;
    const int gid = lane >> 2, tig = lane & 3;
    const int Mblk = blockIdx.y * BM;
    const int Nblk = blockIdx.x * BN;
    const int bh   = blockIdx.z;
    const uint32_t sb = s2u(smem);

    // per-lane ldmatrix address components
    int rba[MT], swa[MT], rbb[NT/2], swb[NT/2];
    const int rA  = (lane & 7) + ((lane & 8) ? 8 : 0);
    const int kha = (lane >> 4) & 1;
    #pragma unroll
    for (int i = 0; i < MT; i++) {
        int row = wm*32 + i*16 + rA;
        rba[i] = row*64; swa[i] = (row>>1)&3;
    }
    const int rB  = (lane & 7) + ((lane & 16) ? 8 : 0);
    const int khb = (lane >> 3) & 1;
    #pragma unroll
    for (int g = 0; g < NT/2; g++) {
        int row = wn*32 + g*16 + rB;
        rbb[g] = row*64; swb[g] = (row>>1)&3;
    }

    const __half *Ah_g = nullptr, *Al_g = nullptr, *Bh_g, *Bl_g;
    if constexpr (MODE == 0)      { Ah_g=g_xh; Al_g=g_xl; Bh_g=g_wqh; Bl_g=g_wql; }
    else if constexpr (MODE == 1) { size_t o=(size_t)bh*NSEQ*HD;
                                    Ah_g=g_qh+o; Al_g=g_ql+o; Bh_g=g_kh+o; Bl_g=g_kl+o; }
    else if constexpr (MODE == 2) { size_t o=(size_t)bh*HD*NSEQ;
                                    Bh_g=g_vth+o; Bl_g=g_vtl+o; }
    else                          { Ah_g=g_gh; Al_g=g_gl; Bh_g=g_wph; Bl_g=g_wpl; }

    float accf[MT][NT][4] = {};
    uint32_t acch[MT][NT][2] = {};

    if constexpr (MODE != 2) {
        // ======== 3-stage cp.async pipeline, one barrier per chunk ========
        const int r0 = tid >> 2, kg = tid & 3;
        auto issue = [&](int ch, int s) {
            uint32_t base = sb + s*STG;
            #pragma unroll
            for (int i = 0; i < 2; i++) {
                int r = r0 + i*64;
                uint32_t d = base + USWZ(r, kg);
                const size_t so = (size_t)(Mblk + r)*K + ch*32 + kg*8;
                cpa16(d,        Ah_g + so);
                cpa16(d + 8192, Al_g + so);
            }
            {
                uint32_t d = base + 16384 + USWZ(r0, kg);
                const size_t so = (size_t)(Nblk + r0)*K + ch*32 + kg*8;
                cpa16(d,        Bh_g + so);
                cpa16(d + 4096, Bl_g + so);
            }
            CPA_COMMIT();
        };
        issue(0, 0);
        if (NC > 1) issue(1, 1);
        int s_cur = 0, s_nxt2 = 2;
        for (int ch = 0; ch < NC; ch++) {
            if (ch < NC - 1) {
                asm volatile("cp.async.wait_group 1;" ::: "memory");
            } else {
                asm volatile("cp.async.wait_group 0;" ::: "memory");
            }
            __syncthreads();
            if (ch + 2 < NC) issue(ch + 2, s_nxt2);
            uint32_t base = sb + s_cur*STG;
            mma_chunk_p<NT, MT>(base, base+8192, base+16384, base+20480,
                                rba, swa, kha, rbb, swb, khb, accf, acch);
            s_cur = (s_cur == 2) ? 0 : s_cur + 1;
            s_nxt2 = (s_nxt2 == 2) ? 0 : s_nxt2 + 1;
        }
        __syncthreads();
    } else {
        // ======== AV: A manual (normalize+writeback+split STS, double buffer),
        //              B cp.async (triple buffer); one barrier per chunk ========
        float* Abuf = pC + (size_t)bh*NN;            // pC = d_out + OUT_OFF
        const int gg = bh % NH;
        const float na = g_bna[gg], ncs = g_bnc[gg];
        const int pr = tid >> 3, pq = tid & 7;       // row slice / float4 slot
        const int rb0 = tid >> 2, kgB = tid & 3;

        auto issueB = [&](int ch, int s) {
            uint32_t d = sb + 32768 + s*8192 + USWZ(rb0, kgB);
            const size_t so = (size_t)rb0*1024 + ch*32 + kgB*8;
            cpa16(d,        Bh_g + so);
            cpa16(d + 4096, Bl_g + so);
            CPA_COMMIT();
        };
        float4 fa[4];
        #pragma unroll
        for (int i = 0; i < 4; i++) {
            int r = pr + i*32;
            float* p = Abuf + (size_t)(Mblk + r)*1024 + pq*4;
            float4 v = __ldcs((const float4*)p);
            v.x = fmaf(na, v.x, ncs); v.y = fmaf(na, v.y, ncs);
            v.z = fmaf(na, v.z, ncs); v.w = fmaf(na, v.w, ncs);
            __stcs((float4*)p, v);
            fa[i] = v;
        }
        issueB(0, 0);
        int sB = 0, sBn = 1;
        for (int ch = 0; ch < NC; ch++) {
            // STS A(ch) into A-stage ch&1 (plane layout, swizzled)
            const int kgA = pq >> 1, hA = pq & 1;
            #pragma unroll
            for (int i = 0; i < 4; i++) {
                int r = pr + i*32;
                uint2 u01 = split2(fa[i].x, fa[i].y, 16.f);
                uint2 u23 = split2(fa[i].z, fa[i].w, 16.f);
                uint32_t off = (uint32_t)((ch & 1)*16384) + USWZ(r, kgA) + hA*8;
                uint2 sh = {u01.x, u23.x};
                uint2 sl = {u01.y, u23.y};
                *(uint2*)(smem + off)        = sh;
                *(uint2*)(smem + off + 8192) = sl;
            }
            if (ch + 1 < NC) {
                issueB(ch + 1, sBn);
                const int kf = (ch + 1) * 32;
                #pragma unroll
                for (int i = 0; i < 4; i++) {
                    int r = pr + i*32;
                    float* p = Abuf + (size_t)(Mblk + r)*1024 + kf + pq*4;
                    float4 v = __ldcs((const float4*)p);
                    v.x = fmaf(na, v.x, ncs); v.y = fmaf(na, v.y, ncs);
                    v.z = fmaf(na, v.z, ncs); v.w = fmaf(na, v.w, ncs);
                    __stcs((float4*)p, v);
                    fa[i] = v;
                }
                asm volatile("cp.async.wait_group 1;" ::: "memory");
            } else {
                asm volatile("cp.async.wait_group 0;" ::: "memory");
            }
            __syncthreads();
            uint32_t ab = sb + (ch & 1)*16384;
            uint32_t bb = sb + 32768 + sB*8192;
            mma_chunk_p<NT, MT>(ab, ab+8192, bb, bb+4096,
                                rba, swa, kha, rbb, swb, khb, accf, acch);
            sB = (sB == 2) ? 0 : sB + 1;
            sBn = (sBn == 2) ? 0 : sBn + 1;
        }
    }

    // ----------------- epilogue -----------------
    constexpr float UN = (MODE==0) ? (1.f/16384.f) : (MODE==2) ? (1.f/512.f) : (1.f/1024.f);
    if constexpr (MODE == 1) {
        #pragma unroll
        for (int i = 0; i < MT; i++) {
            #pragma unroll
            for (int p = 0; p < 2; p++) {
                const int row = Mblk + wm*32 + i*16 + gid + p*8;
                float rsum = 0.f;
                #pragma unroll
                for (int j = 0; j < NT; j++) {
                    __half2 q = *(__half2*)&acch[i][j][p];
                    float2 cc = __half22float2(q);
                    float v0 = (accf[i][j][p*2+0] + cc.x) * UN;
                    float v1 = (accf[i][j][p*2+1] + cc.y) * UN;
                    float e0 = __expf(SCALE * v0);
                    float e1 = __expf(SCALE * v1);
                    int c0 = Nblk + wn*32 + j*8 + tig*2;
                    __stcs((float2*)(g_logits + (size_t)bh*NN + (size_t)row*NSEQ + c0),
                           make_float2(e0, e1));
                    rsum += e0 + e1;
                }
                rsum += __shfl_xor_sync(0xffffffffu, rsum, 1);
                rsum += __shfl_xor_sync(0xffffffffu, rsum, 2);
                if (tig == 0)
                    atomicAdd(&g_rs[(size_t)bh*NSEQ + row], rsum);
            }
        }
    } else {
        #pragma unroll
        for (int i = 0; i < MT; i++) {
            #pragma unroll
            for (int j = 0; j < NT; j++) {
                __half2 q0 = *(__half2*)&acch[i][j][0];
                __half2 q1 = *(__half2*)&acch[i][j][1];
                float2 c01 = __half22float2(q0);
                float2 c23 = __half22float2(q1);
                float cv[4] = {accf[i][j][0] + c01.x, accf[i][j][1] + c01.y,
                               accf[i][j][2] + c23.x, accf[i][j][3] + c23.y};
                int r0 = Mblk + wm*32 + i*16 + gid;
                int c0 = Nblk + wn*32 + j*8 + tig*2;
                #pragma unroll
                for (int p = 0; p < 2; p++) {
                    int row = r0 + p*8;
                    float v0 = cv[p*2+0] * UN, v1 = cv[p*2+1] * UN;
                    if constexpr (MODE == 0) {
                        int t3 = c0 / CDIM; int rem = c0 - t3*CDIM;
                        int h = rem >> 6, d = rem & 63;
                        int b = row >> 10, n = row & (NSEQ - 1);
                        v0 += bias[c0]; v1 += bias[c0+1];
                        if (t3 < 2) {
                            uint2 sp = split2(v0, v1, 32.f);
                            size_t idx = ((((size_t)(b*NH+h))*NSEQ + n) << 6) + d;
                            if (t3 == 0) {
                                *(uint32_t*)(g_qh + idx) = sp.x;
                                *(uint32_t*)(g_ql + idx) = sp.y;
                            } else {
                                *(uint32_t*)(g_kh + idx) = sp.x;
                                *(uint32_t*)(g_kl + idx) = sp.y;
                            }
                        } else {
                            size_t base = (((size_t)(b*NH+h))*HD + d)*NSEQ + n;
                            g_vt[base]        = v0;
                            g_vt[base + NSEQ] = v1;
                        }
                    } else if constexpr (MODE == 2) {
                        int b = bh / NH, g = bh % NH;
                        uint2 sp = split2(v0, v1, 1.f);
                        size_t idx = ((size_t)(b*NSEQ + row))*CDIM + g*HD + c0;
                        *(uint32_t*)(g_gh + idx) = sp.x;
                        *(uint32_t*)(g_gl + idx) = sp.y;
                    } else {
                        float2 s = make_float2(v0 + bias[c0], v1 + bias[c0+1]);
                        *(float2*)(pC + (size_t)row*CDIM + c0) = s;
                    }
                }
            }
        }
    }
}

// ---------------- streaming softmax-finish + head mix + BN stats ---------------
__global__ void k_mix(const float* __restrict__ w_re, const float* __restrict__ b_re,
                      float* __restrict__ dout) {
    __shared__ float wre[NH][NH];
    __shared__ float bre[NH], sinv[NH];
    __shared__ float sm1[NH], sm2[NH];
    const int b = blockIdx.x >> 10;
    const int n = blockIdx.x & 1023;
    const int t = threadIdx.x;               // 256
    const int lane = t & 31;
    if (t < NH*NH) wre[t/NH][t%NH] = w_re[t];
    if (t < NH) {
        bre[t] = b_re[t];
        sinv[t] = 1.0f / g_rs[((size_t)(b*NH + t))*NSEQ + n];
        sm1[t] = 0.f; sm2[t] = 0.f;
    }
    __syncthreads();
    const int m = t << 2;
    float L[NH][4];
    #pragma unroll
    for (int h = 0; h < NH; h++) {
        float4 e = *(const float4*)(g_logits + (((size_t)(b*NH+h))*NSEQ + n)*NSEQ + m);
        float si = sinv[h];
        L[h][0] = e.x*si; L[h][1] = e.y*si; L[h][2] = e.z*si; L[h][3] = e.w*si;
    }
    float* attn = dout + OUT_OFF;
    #pragma unroll
    for (int g = 0; g < NH; g++) {
        float o0=bre[g], o1=bre[g], o2=bre[g], o3=bre[g];
        #pragma unroll
        for (int h = 0; h < NH; h++) {
            float w = wre[g][h];
            o0 = fmaf(w, L[h][0], o0); o1 = fmaf(w, L[h][1], o1);
            o2 = fmaf(w, L[h][2], o2); o3 = fmaf(w, L[h][3], o3);
        }
        float4 st = {o0, o1, o2, o3};
        *(float4*)(attn + (((size_t)(b*NH+g))*NSEQ + n)*NSEQ + m) = st;
        float a = (o0+o1)+(o2+o3);
        float c = o0*o0+o1*o1+o2*o2+o3*o3;
        #pragma unroll
        for (int o = 16; o; o >>= 1) {
            a += __shfl_xor_sync(0xffffffffu, a, o);
            c += __shfl_xor_sync(0xffffffffu, c, o);
        }
        if (lane == 0) { atomicAdd(&sm1[g], a); atomicAdd(&sm2[g], c); }
    }
    __syncthreads();
    if (t < NH) {
        atomicAdd(&g_s1[t], (double)sm1[t]);
        atomicAdd(&g_s2[t], (double)sm2[t]);
    }
}

// ---------------- BN finalize (double precision) --------------------------------
__global__ void k_bnfin(const float* __restrict__ gamma, const float* __restrict__ beta) {
    int g = threadIdx.x;
    if (g < NH) {
        double cnt = (double)BB * NSEQ * NSEQ;
        double mean = g_s1[g] / cnt;
        double var  = g_s2[g] / cnt - mean * mean;
        float a = (float)((double)gamma[g] / sqrt(var + (double)BNEPS));
        g_bna[g] = a;
        g_bnc[g] = beta[g] - a * (float)mean;
    }
}

// ---------------- launcher --------------------------------------------------------
extern "C" void kernel_launch(void* const* d_in, const int* in_sizes, int n_in,
                              void* d_out, int out_size) {
    const float* x    = (const float*)d_in[0];
    const float* wqkv = (const float*)d_in[1];
    const float* bqkv = (const float*)d_in[2];
    const float* wre  = (const float*)d_in[3];
    const float* bre  = (const float*)d_in[4];
    const float* gam  = (const float*)d_in[5];
    const float* bet  = (const float*)d_in[6];
    const float* wp   = (const float*)d_in[7];
    const float* bp   = (const float*)d_in[8];
    float* out = (float*)d_out;

    const int SM3 = 3 * 24576;                 // 73728
    const int SM2m = 2*16384 + 3*8192;         // 57344 (MODE 2)
    cudaFuncSetAttribute(gemm_h<0>, cudaFuncAttributeMaxDynamicSharedMemorySize, SM3);
    cudaFuncSetAttribute(gemm_h<1>, cudaFuncAttributeMaxDynamicSharedMemorySize, SM3);
    cudaFuncSetAttribute(gemm_h<2>, cudaFuncAttributeMaxDynamicSharedMemorySize, SM2m);
    cudaFuncSetAttribute(gemm_h<3>, cudaFuncAttributeMaxDynamicSharedMemorySize, SM3);

    k_init<<<96, 1024>>>();                                           // 1
    k_split<<<3072, 256>>>(x,    786432, 16.f,   0);                  // 2: x
    k_split<<<864,  256>>>(wqkv, 221184, 1024.f, 1);                  // 3: w_qkv
    gemm_h<0><<<dim3(36, 64, 1), 256, SM3>>>(bqkv, nullptr);          // 4: qkv (PROFILED)
    k_split<<<288,  256>>>(wp,    73728, 1024.f, 2);                  // 5: w_proj
    k_split<<<3072, 256>>>(nullptr, 786432, 32.f, 3);                 // 6: v^T
    gemm_h<1><<<dim3(16, 8, 96), 256, SM3>>>(nullptr, nullptr);       // 7: qk
    k_mix<<<8192, 256>>>(wre, bre, out);                              // 8: mix
    k_bnfin<<<1, 32>>>(gam, bet);                                     // 9
    gemm_h<2><<<dim3(1, 8, 96),  256, SM2m>>>(nullptr, out + OUT_OFF);// 10: av + norm
    gemm_h<3><<<dim3(12, 64, 1), 256, SM3>>>(bp, out);                // 11: proj
}

// round 10
// speedup vs baseline: 1.7500x; 1.0267x over previous
#include <cuda_runtime.h>
#include <cuda_fp16.h>
#include <math.h>
#include <stdint.h>

#define BB 8
#define NSEQ 1024
#define CDIM 768
#define NH 12
#define HD 64
#define SCALE 0.125f
#define BNEPS 1e-5f
#define OUT_OFF (BB*NSEQ*CDIM)
#define NN ((size_t)NSEQ*NSEQ)

// plane sizes (hi plane at [0], lo plane at [OFF])
#define XOFF  (BB*NSEQ*CDIM)      // 6291456
#define WQOFF (3*CDIM*CDIM)       // 1769472
#define WPOFF (CDIM*CDIM)         // 589824
#define QOFF  (BB*NH*NSEQ*HD)     // 6291456
#define VOFF  (BB*NH*HD*NSEQ)     // 6291456
#define GOFF  (BB*NSEQ*CDIM)      // 6291456

// ---------------- scratch: merged hi/lo half planes ----------------------------
__device__ __half g_x  [2*XOFF];    // x * 16
__device__ __half g_wq [2*WQOFF];   // w_qkv * 1024
__device__ __half g_wp [2*WPOFF];   // w_proj * 1024
__device__ __half g_q  [2*QOFF];    // q * 32
__device__ __half g_k  [2*QOFF];    // k * 32
__device__ __half g_vts[2*VOFF];    // v^T * 32 [bh][d][m]
__device__ __half g_g  [2*GOFF];    // attn@v [b*N+n][c]
__device__ float  g_vt [VOFF];      // raw v^T
__device__ float  g_logits[BB*NH*NSEQ*NSEQ];   // exp(SCALE*q.k)
__device__ float  g_rs[BB*NH*NSEQ];
__device__ double g_s1[NH];
__device__ double g_s2[NH];
__device__ float  g_bna[NH];
__device__ float  g_bnc[NH];

// ---------------- helpers -------------------------------------------------------
__device__ __forceinline__ uint32_t s2u(const void* p){
    uint32_t a;
    asm("{ .reg .u64 t; cvta.to.shared.u64 t, %1; cvt.u32.u64 %0, t; }" : "=r"(a) : "l"(p));
    return a;
}
__device__ __forceinline__ uint2 split2(float x0, float x1, float s){
    x0 *= s; x1 *= s;
    __half h0 = __float2half_rn(x0), h1 = __float2half_rn(x1);
    __half g0 = __float2half_rn(x0 - __half2float(h0));
    __half g1 = __float2half_rn(x1 - __half2float(h1));
    __half2 hh = __halves2half2(h0, h1), ll = __halves2half2(g0, g1);
    uint2 r;
    r.x = *(uint32_t*)&hh; r.y = *(uint32_t*)&ll;
    return r;
}
__device__ __forceinline__ void mma16f(float* c, const uint32_t* a, const uint32_t* b){
    asm volatile("mma.sync.aligned.m16n8k16.row.col.f32.f16.f16.f32 "
        "{%0,%1,%2,%3}, {%4,%5,%6,%7}, {%8,%9}, {%0,%1,%2,%3};"
        : "+f"(c[0]), "+f"(c[1]), "+f"(c[2]), "+f"(c[3])
        : "r"(a[0]), "r"(a[1]), "r"(a[2]), "r"(a[3]), "r"(b[0]), "r"(b[1]));
}
__device__ __forceinline__ void mma16h(uint32_t* c, const uint32_t* a, const uint32_t* b){
    asm volatile("mma.sync.aligned.m16n8k16.row.col.f16.f16.f16.f16 "
        "{%0,%1}, {%2,%3,%4,%5}, {%6,%7}, {%0,%1};"
        : "+r"(c[0]), "+r"(c[1])
        : "r"(a[0]), "r"(a[1]), "r"(a[2]), "r"(a[3]), "r"(b[0]), "r"(b[1]));
}
__device__ __forceinline__ void ldsm4(uint32_t& r0, uint32_t& r1, uint32_t& r2,
                                      uint32_t& r3, uint32_t addr){
    asm volatile("ldmatrix.sync.aligned.m8n8.x4.shared.b16 {%0,%1,%2,%3}, [%4];"
        : "=r"(r0), "=r"(r1), "=r"(r2), "=r"(r3) : "r"(addr));
}
__device__ __forceinline__ void cpa16(uint32_t dst, const void* src){
    asm volatile("cp.async.cg.shared.global [%0], [%1], 16;" :: "r"(dst), "l"(src));
}
#define CPA_COMMIT() asm volatile("cp.async.commit_group;" ::: "memory")
// swizzled byte offset of 16B unit (row, kg) inside a [rows][64B] plane
#define USWZ(row, kg) ((row)*64 + (((kg) ^ (((row)>>1)&3)) << 4))

// ---------------- init ----------------------------------------------------------
__global__ void k_init(){
    int i = blockIdx.x * blockDim.x + threadIdx.x;
    if (i < BB*NH*NSEQ) g_rs[i] = 0.f;
    if (i < NH) { g_s1[i] = 0.0; g_s2[i] = 0.0; }
}

// ---------------- pre-split: fp32 -> hi/lo half planes ---------------------------
__global__ void k_split(const float* __restrict__ src, int n8, float s, int sel){
    int i = blockIdx.x * blockDim.x + threadIdx.x;
    if (i >= n8) return;
    const float* p = (sel == 3) ? g_vt : src;
    float4 a = *(const float4*)(p + 8*(size_t)i);
    float4 b = *(const float4*)(p + 8*(size_t)i + 4);
    uint2 u0 = split2(a.x, a.y, s), u1 = split2(a.z, a.w, s);
    uint2 u2 = split2(b.x, b.y, s), u3 = split2(b.z, b.w, s);
    __half* dh; size_t off;
    if (sel == 0)      { dh = g_x;   off = XOFF; }
    else if (sel == 1) { dh = g_wq;  off = WQOFF; }
    else if (sel == 2) { dh = g_wp;  off = WPOFF; }
    else               { dh = g_vts; off = VOFF; }
    uint4 vh = {u0.x, u1.x, u2.x, u3.x};
    uint4 vl = {u0.y, u1.y, u2.y, u3.y};
    *(uint4*)(dh + 8*(size_t)i)       = vh;
    *(uint4*)(dh + off + 8*(size_t)i) = vl;
}

// ---------------- ldmatrix MMA core: one k32 chunk -------------------------------
// planes in smem: Ah at ah_b, Al at ah_b+8192, Bh at bh_b, Bl at bh_b+blo
template<int NT, int MT>
__device__ __forceinline__ void mma_chunk_p(
    uint32_t ah_b, uint32_t bh_b, uint32_t blo,
    const int* rba, const int* swa, int kha,
    const int* rbb, const int* swb, int khb,
    float accf[MT][NT][4], uint32_t acch[MT][NT][2])
{
    #pragma unroll
    for (int ks = 0; ks < 2; ks++) {
        uint32_t ah[MT][4], al[MT][4], bh4[NT/2][4], bl4[NT/2][4];
        #pragma unroll
        for (int i = 0; i < MT; i++) {
            int kg = ks*2 + kha;
            uint32_t off = rba[i] + (((uint32_t)(kg ^ swa[i])) << 4);
            ldsm4(ah[i][0], ah[i][1], ah[i][2], ah[i][3], ah_b + off);
            ldsm4(al[i][0], al[i][1], al[i][2], al[i][3], ah_b + 8192 + off);
        }
        #pragma unroll
        for (int g = 0; g < NT/2; g++) {
            int kg = ks*2 + khb;
            uint32_t off = rbb[g] + (((uint32_t)(kg ^ swb[g])) << 4);
            ldsm4(bh4[g][0], bh4[g][1], bh4[g][2], bh4[g][3], bh_b + off);
            ldsm4(bl4[g][0], bl4[g][1], bl4[g][2], bl4[g][3], bh_b + blo + off);
        }
        #pragma unroll
        for (int g = 0; g < NT/2; g++) {
            #pragma unroll
            for (int jj = 0; jj < 2; jj++) {
                int j = g*2 + jj;
                uint32_t bh2[2] = {bh4[g][jj*2], bh4[g][jj*2+1]};
                uint32_t bl2[2] = {bl4[g][jj*2], bl4[g][jj*2+1]};
                #pragma unroll
                for (int i = 0; i < MT; i++) {
                    mma16f(accf[i][j], ah[i], bh2);
                    mma16h(acch[i][j], al[i], bh2);
                    mma16h(acch[i][j], ah[i], bl2);
                }
            }
        }
    }
}

// ---------------- fp16x3 GEMM ----------------------------------------------------
// MODE 0: qkv  A=g_x  B=g_wq K=768  -> q,k planes + raw v^T (UN 2^-14, +bias)
// MODE 1: qk   A=g_q  B=g_k  K=64   -> exp(SCALE*logit) + row-sum atomics
// MODE 2: av   A=d_out attn (normalize in place) B=g_vts K=1024 -> g_g planes
// MODE 3: proj A=g_g  B=g_wp K=768  -> d_out (UN 2^-10, +bias)
template<int MODE>
__global__ __launch_bounds__(256, (MODE==2) ? 2 : 3) void gemm_h(
    const float* __restrict__ bias, float* __restrict__ pC)
{
    constexpr int BM = 128, BN = 64;
    constexpr int NT = 4, MT = 2;
    constexpr int K   = (MODE==1) ? 64 : (MODE==2) ? 1024 : 768;
    constexpr int NC  = K / 32;
    constexpr int STG = 24576;  // Ah 0, Al 8192, Bh 16384, Bl 20480

    extern __shared__ __align__(16) char smem[];

    const int tid  = threadIdx.x;
    const int lane = tid & 31, warp = tid >> 5;
    const int wm = warp >> 1, wn = warp & 1;
    const int gid = lane >> 2, tig = lane & 3;
    const int Mblk = blockIdx.y * BM;
    const int Nblk = blockIdx.x * BN;
    const int bh   = blockIdx.z;
    const uint32_t sb = s2u(smem);

    // per-lane ldmatrix address components
    int rba[MT], swa[MT], rbb[NT/2], swb[NT/2];
    const int rA  = (lane & 7) + ((lane & 8) ? 8 : 0);
    const int kha = (lane >> 4) & 1;
    #pragma unroll
    for (int i = 0; i < MT; i++) {
        int row = wm*32 + i*16 + rA;
        rba[i] = row*64; swa[i] = (row>>1)&3;
    }
    const int rB  = (lane & 7) + ((lane & 16) ? 8 : 0);
    const int khb = (lane >> 3) & 1;
    #pragma unroll
    for (int g = 0; g < NT/2; g++) {
        int row = wn*32 + g*16 + rB;
        rbb[g] = row*64; swb[g] = (row>>1)&3;
    }

    const __half *Ah_g = nullptr, *Bh_g;
    constexpr size_t ALO = (MODE==0) ? XOFF : (MODE==1) ? QOFF : (MODE==3) ? GOFF : 0;
    constexpr size_t BLO = (MODE==0) ? WQOFF : (MODE==1) ? QOFF :
                           (MODE==2) ? VOFF : WPOFF;
    if constexpr (MODE == 0)      { Ah_g = g_x; Bh_g = g_wq; }
    else if constexpr (MODE == 1) { size_t o = (size_t)bh*NSEQ*HD;
                                    Ah_g = g_q + o; Bh_g = g_k + o; }
    else if constexpr (MODE == 2) { Bh_g = g_vts + (size_t)bh*HD*NSEQ; }
    else                          { Ah_g = g_g; Bh_g = g_wp; }

    float accf[MT][NT][4] = {};
    uint32_t acch[MT][NT][2] = {};

    if constexpr (MODE != 2) {
        // ======== 3-stage cp.async pipeline, one barrier per chunk ========
        const int r0 = tid >> 2, kg = tid & 3;
        auto issue = [&](int ch, int s) {
            uint32_t base = sb + s*STG;
            #pragma unroll
            for (int i = 0; i < 2; i++) {
                int r = r0 + i*64;
                uint32_t d = base + USWZ(r, kg);
                const __half* src = Ah_g + (size_t)(Mblk + r)*K + ch*32 + kg*8;
                cpa16(d,        src);
                cpa16(d + 8192, src + ALO);
            }
            {
                uint32_t d = base + 16384 + USWZ(r0, kg);
                const __half* src = Bh_g + (size_t)(Nblk + r0)*K + ch*32 + kg*8;
                cpa16(d,        src);
                cpa16(d + 4096, src + BLO);
            }
            CPA_COMMIT();
        };
        issue(0, 0);
        if (NC > 1) issue(1, 1);
        int s_cur = 0, s_nxt2 = 2;
        for (int ch = 0; ch < NC; ch++) {
            if (ch < NC - 1) {
                asm volatile("cp.async.wait_group 1;" ::: "memory");
            } else {
                asm volatile("cp.async.wait_group 0;" ::: "memory");
            }
            __syncthreads();
            if (ch + 2 < NC) issue(ch + 2, s_nxt2);
            uint32_t base = sb + s_cur*STG;
            mma_chunk_p<NT, MT>(base, base+16384, 4096,
                                rba, swa, kha, rbb, swb, khb, accf, acch);
            s_cur = (s_cur == 2) ? 0 : s_cur + 1;
            s_nxt2 = (s_nxt2 == 2) ? 0 : s_nxt2 + 1;
        }
        __syncthreads();
    } else {
        // ======== AV: A manual (normalize+writeback+split STS, double buffer),
        //              B cp.async (triple buffer); one barrier per chunk ========
        float* Abuf = pC + (size_t)bh*NN;            // pC = d_out + OUT_OFF
        const int gg = bh % NH;
        const float na = g_bna[gg], ncs = g_bnc[gg];
        const int pr = tid >> 3, pq = tid & 7;       // row slice / float4 slot
        const int rb0 = tid >> 2, kgB = tid & 3;

        auto issueB = [&](int ch, int s) {
            uint32_t d = sb + 32768 + s*8192 + USWZ(rb0, kgB);
            const __half* src = Bh_g + (size_t)rb0*1024 + ch*32 + kgB*8;
            cpa16(d,        src);
            cpa16(d + 4096, src + BLO);
            CPA_COMMIT();
        };
        float4 fa[4];
        #pragma unroll
        for (int i = 0; i < 4; i++) {
            int r = pr + i*32;
            float* p = Abuf + (size_t)(Mblk + r)*1024 + pq*4;
            float4 v = __ldcs((const float4*)p);
            v.x = fmaf(na, v.x, ncs); v.y = fmaf(na, v.y, ncs);
            v.z = fmaf(na, v.z, ncs); v.w = fmaf(na, v.w, ncs);
            __stcs((float4*)p, v);
            fa[i] = v;
        }
        issueB(0, 0);
        int sB = 0, sBn = 1;
        for (int ch = 0; ch < NC; ch++) {
            const int kgA = pq >> 1, hA = pq & 1;
            #pragma unroll
            for (int i = 0; i < 4; i++) {
                int r = pr + i*32;
                uint2 u01 = split2(fa[i].x, fa[i].y, 16.f);
                uint2 u23 = split2(fa[i].z, fa[i].w, 16.f);
                uint32_t off = (uint32_t)((ch & 1)*16384) + USWZ(r, kgA) + hA*8;
                uint2 sh = {u01.x, u23.x};
                uint2 sl = {u01.y, u23.y};
                *(uint2*)(smem + off)        = sh;
                *(uint2*)(smem + off + 8192) = sl;
            }
            if (ch + 1 < NC) {
                issueB(ch + 1, sBn);
                const int kf = (ch + 1) * 32;
                #pragma unroll
                for (int i = 0; i < 4; i++) {
                    int r = pr + i*32;
                    float* p = Abuf + (size_t)(Mblk + r)*1024 + kf + pq*4;
                    float4 v = __ldcs((const float4*)p);
                    v.x = fmaf(na, v.x, ncs); v.y = fmaf(na, v.y, ncs);
                    v.z = fmaf(na, v.z, ncs); v.w = fmaf(na, v.w, ncs);
                    __stcs((float4*)p, v);
                    fa[i] = v;
                }
                asm volatile("cp.async.wait_group 1;" ::: "memory");
            } else {
                asm volatile("cp.async.wait_group 0;" ::: "memory");
            }
            __syncthreads();
            uint32_t ab = sb + (ch & 1)*16384;
            uint32_t bb = sb + 32768 + sB*8192;
            mma_chunk_p<NT, MT>(ab, bb, 4096,
                                rba, swa, kha, rbb, swb, khb, accf, acch);
            sB = (sB == 2) ? 0 : sB + 1;
            sBn = (sBn == 2) ? 0 : sBn + 1;
        }
    }

    // ----------------- epilogue -----------------
    constexpr float UN = (MODE==0) ? (1.f/16384.f) : (MODE==2) ? (1.f/512.f) : (1.f/1024.f);
    if constexpr (MODE == 1) {
        #pragma unroll
        for (int i = 0; i < MT; i++) {
            #pragma unroll
            for (int p = 0; p < 2; p++) {
                const int row = Mblk + wm*32 + i*16 + gid + p*8;
                float rsum = 0.f;
                #pragma unroll
                for (int j = 0; j < NT; j++) {
                    __half2 q = *(__half2*)&acch[i][j][p];
                    float2 cc = __half22float2(q);
                    float v0 = (accf[i][j][p*2+0] + cc.x) * UN;
                    float v1 = (accf[i][j][p*2+1] + cc.y) * UN;
                    float e0 = __expf(SCALE * v0);
                    float e1 = __expf(SCALE * v1);
                    int c0 = Nblk + wn*32 + j*8 + tig*2;
                    __stcs((float2*)(g_logits + (size_t)bh*NN + (size_t)row*NSEQ + c0),
                           make_float2(e0, e1));
                    rsum += e0 + e1;
                }
                rsum += __shfl_xor_sync(0xffffffffu, rsum, 1);
                rsum += __shfl_xor_sync(0xffffffffu, rsum, 2);
                if (tig == 0)
                    atomicAdd(&g_rs[(size_t)bh*NSEQ + row], rsum);
            }
        }
    } else {
        #pragma unroll
        for (int i = 0; i < MT; i++) {
            #pragma unroll
            for (int j = 0; j < NT; j++) {
                __half2 q0 = *(__half2*)&acch[i][j][0];
                __half2 q1 = *(__half2*)&acch[i][j][1];
                float2 c01 = __half22float2(q0);
                float2 c23 = __half22float2(q1);
                float cv[4] = {accf[i][j][0] + c01.x, accf[i][j][1] + c01.y,
                               accf[i][j][2] + c23.x, accf[i][j][3] + c23.y};
                int r0 = Mblk + wm*32 + i*16 + gid;
                int c0 = Nblk + wn*32 + j*8 + tig*2;
                #pragma unroll
                for (int p = 0; p < 2; p++) {
                    int row = r0 + p*8;
                    float v0 = cv[p*2+0] * UN, v1 = cv[p*2+1] * UN;
                    if constexpr (MODE == 0) {
                        int t3 = c0 / CDIM; int rem = c0 - t3*CDIM;
                        int h = rem >> 6, d = rem & 63;
                        int b = row >> 10, n = row & (NSEQ - 1);
                        v0 += bias[c0]; v1 += bias[c0+1];
                        if (t3 < 2) {
                            uint2 sp = split2(v0, v1, 32.f);
                            size_t idx = ((((size_t)(b*NH+h))*NSEQ + n) << 6) + d;
                            __half* dst = (t3 == 0) ? g_q : g_k;
                            *(uint32_t*)(dst + idx)        = sp.x;
                            *(uint32_t*)(dst + QOFF + idx) = sp.y;
                        } else {
                            size_t base = (((size_t)(b*NH+h))*HD + d)*NSEQ + n;
                            g_vt[base]        = v0;
                            g_vt[base + NSEQ] = v1;
                        }
                    } else if constexpr (MODE == 2) {
                        int b = bh / NH, g = bh % NH;
                        uint2 sp = split2(v0, v1, 1.f);
                        size_t idx = ((size_t)(b*NSEQ + row))*CDIM + g*HD + c0;
                        *(uint32_t*)(g_g + idx)        = sp.x;
                        *(uint32_t*)(g_g + GOFF + idx) = sp.y;
                    } else {
                        float2 s = make_float2(v0 + bias[c0], v1 + bias[c0+1]);
                        *(float2*)(pC + (size_t)row*CDIM + c0) = s;
                    }
                }
            }
        }
    }
}

// ---------------- streaming softmax-finish + head mix + BN stats ---------------
__global__ void k_mix(const float* __restrict__ w_re, const float* __restrict__ b_re,
                      float* __restrict__ dout) {
    __shared__ float wre[NH][NH];
    __shared__ float bre[NH], sinv[NH];
    __shared__ float sm1[NH], sm2[NH];
    const int b = blockIdx.x >> 10;
    const int n = blockIdx.x & 1023;
    const int t = threadIdx.x;               // 256
    const int lane = t & 31;
    if (t < NH*NH) wre[t/NH][t%NH] = w_re[t];
    if (t < NH) {
        bre[t] = b_re[t];
        sinv[t] = 1.0f / g_rs[((size_t)(b*NH + t))*NSEQ + n];
        sm1[t] = 0.f; sm2[t] = 0.f;
    }
    __syncthreads();
    const int m = t << 2;
    float L[NH][4];
    #pragma unroll
    for (int h = 0; h < NH; h++) {
        float4 e = *(const float4*)(g_logits + (((size_t)(b*NH+h))*NSEQ + n)*NSEQ + m);
        float si = sinv[h];
        L[h][0] = e.x*si; L[h][1] = e.y*si; L[h][2] = e.z*si; L[h][3] = e.w*si;
    }
    float* attn = dout + OUT_OFF;
    #pragma unroll
    for (int g = 0; g < NH; g++) {
        float o0=bre[g], o1=bre[g], o2=bre[g], o3=bre[g];
        #pragma unroll
        for (int h = 0; h < NH; h++) {
            float w = wre[g][h];
            o0 = fmaf(w, L[h][0], o0); o1 = fmaf(w, L[h][1], o1);
            o2 = fmaf(w, L[h][2], o2); o3 = fmaf(w, L[h][3], o3);
        }
        float4 st = {o0, o1, o2, o3};
        *(float4*)(attn + (((size_t)(b*NH+g))*NSEQ + n)*NSEQ + m) = st;
        float a = (o0+o1)+(o2+o3);
        float c = o0*o0+o1*o1+o2*o2+o3*o3;
        #pragma unroll
        for (int o = 16; o; o >>= 1) {
            a += __shfl_xor_sync(0xffffffffu, a, o);
            c += __shfl_xor_sync(0xffffffffu, c, o);
        }
        if (lane == 0) { atomicAdd(&sm1[g], a); atomicAdd(&sm2[g], c); }
    }
    __syncthreads();
    if (t < NH) {
        atomicAdd(&g_s1[t], (double)sm1[t]);
        atomicAdd(&g_s2[t], (double)sm2[t]);
    }
}

// ---------------- BN finalize (double precision) --------------------------------
__global__ void k_bnfin(const float* __restrict__ gamma, const float* __restrict__ beta) {
    int g = threadIdx.x;
    if (g < NH) {
        double cnt = (double)BB * NSEQ * NSEQ;
        double mean = g_s1[g] / cnt;
        double var  = g_s2[g] / cnt - mean * mean;
        float a = (float)((double)gamma[g] / sqrt(var + (double)BNEPS));
        g_bna[g] = a;
        g_bnc[g] = beta[g] - a * (float)mean;
    }
}

// ---------------- launcher --------------------------------------------------------
extern "C" void kernel_launch(void* const* d_in, const int* in_sizes, int n_in,
                              void* d_out, int out_size) {
    const float* x    = (const float*)d_in[0];
    const float* wqkv = (const float*)d_in[1];
    const float* bqkv = (const float*)d_in[2];
    const float* wre  = (const float*)d_in[3];
    const float* bre  = (const float*)d_in[4];
    const float* gam  = (const float*)d_in[5];
    const float* bet  = (const float*)d_in[6];
    const float* wp   = (const float*)d_in[7];
    const float* bp   = (const float*)d_in[8];
    float* out = (float*)d_out;

    const int SM3 = 3 * 24576;                 // 73728
    const int SM2m = 2*16384 + 3*8192;         // 57344 (MODE 2)
    cudaFuncSetAttribute(gemm_h<0>, cudaFuncAttributeMaxDynamicSharedMemorySize, SM3);
    cudaFuncSetAttribute(gemm_h<1>, cudaFuncAttributeMaxDynamicSharedMemorySize, SM3);
    cudaFuncSetAttribute(gemm_h<2>, cudaFuncAttributeMaxDynamicSharedMemorySize, SM2m);
    cudaFuncSetAttribute(gemm_h<3>, cudaFuncAttributeMaxDynamicSharedMemorySize, SM3);

    k_init<<<96, 1024>>>();                                           // 1
    k_split<<<3072, 256>>>(x,    786432, 16.f,   0);                  // 2: x
    k_split<<<864,  256>>>(wqkv, 221184, 1024.f, 1);                  // 3: w_qkv
    gemm_h<0><<<dim3(36, 64, 1), 256, SM3>>>(bqkv, nullptr);          // 4: qkv (PROFILED)
    k_split<<<288,  256>>>(wp,    73728, 1024.f, 2);                  // 5: w_proj
    k_split<<<3072, 256>>>(nullptr, 786432, 32.f, 3);                 // 6: v^T
    gemm_h<1><<<dim3(16, 8, 96), 256, SM3>>>(nullptr, nullptr);       // 7: qk
    k_mix<<<8192, 256>>>(wre, bre, out);                              // 8: mix
    k_bnfin<<<1, 32>>>(gam, bet);                                     // 9
    gemm_h<2><<<dim3(1, 8, 96),  256, SM2m>>>(nullptr, out + OUT_OFF);// 10: av + norm
    gemm_h<3><<<dim3(12, 64, 1), 256, SM3>>>(bp, out);                // 11: proj
}

// round 11
// speedup vs baseline: 1.9318x; 1.1038x over previous
#include <cuda_runtime.h>
#include <cuda_fp16.h>
#include <math.h>
#include <stdint.h>

#define BB 8
#define NSEQ 1024
#define CDIM 768
#define NH 12
#define HD 64
#define SCALE 0.125f
#define BNEPS 1e-5f
#define OUT_OFF (BB*NSEQ*CDIM)
#define NN ((size_t)NSEQ*NSEQ)

// plane sizes (hi plane at [0], lo plane at [OFF])
#define XOFF  (BB*NSEQ*CDIM)      // 6291456
#define WQOFF (3*CDIM*CDIM)       // 1769472
#define WPOFF (CDIM*CDIM)         // 589824
#define QOFF  (BB*NH*NSEQ*HD)     // 6291456
#define VOFF  (BB*NH*HD*NSEQ)     // 6291456
#define GOFF  (BB*NSEQ*CDIM)      // 6291456
#define MXOFF ((size_t)BB*NH*NSEQ*NSEQ)   // 100663296

// ---------------- scratch: merged hi/lo half planes ----------------------------
__device__ __half g_x  [2*XOFF];    // x * 16
__device__ __half g_wq [2*WQOFF];   // w_qkv * 1024
__device__ __half g_wp [2*WPOFF];   // w_proj * 1024
__device__ __half g_q  [2*QOFF];    // q * 32
__device__ __half g_k  [2*QOFF];    // k * 32
__device__ __half g_vts[2*VOFF];    // v^T * 32 [bh][d][m]
__device__ __half g_g  [2*GOFF];    // attn@v [b*N+n][c]
__device__ __half g_mx [2*MXOFF];   // raw mixed attn * 4096 [bh][n][m]
__device__ float  g_vt [VOFF];      // raw v^T
__device__ float  g_vc [BB*NH*HD];  // colsum of v per (bh, d)
__device__ float  g_logits[BB*NH*NSEQ*NSEQ];   // exp(SCALE*q.k)
__device__ float  g_rs[BB*NH*NSEQ];
__device__ double g_s1[NH];
__device__ double g_s2[NH];
__device__ float  g_bna[NH];
__device__ float  g_bnc[NH];

// ---------------- helpers -------------------------------------------------------
__device__ __forceinline__ uint32_t s2u(const void* p){
    uint32_t a;
    asm("{ .reg .u64 t; cvta.to.shared.u64 t, %1; cvt.u32.u64 %0, t; }" : "=r"(a) : "l"(p));
    return a;
}
__device__ __forceinline__ uint2 split2(float x0, float x1, float s){
    x0 *= s; x1 *= s;
    __half h0 = __float2half_rn(x0), h1 = __float2half_rn(x1);
    __half g0 = __float2half_rn(x0 - __half2float(h0));
    __half g1 = __float2half_rn(x1 - __half2float(h1));
    __half2 hh = __halves2half2(h0, h1), ll = __halves2half2(g0, g1);
    uint2 r;
    r.x = *(uint32_t*)&hh; r.y = *(uint32_t*)&ll;
    return r;
}
__device__ __forceinline__ void mma16f(float* c, const uint32_t* a, const uint32_t* b){
    asm volatile("mma.sync.aligned.m16n8k16.row.col.f32.f16.f16.f32 "
        "{%0,%1,%2,%3}, {%4,%5,%6,%7}, {%8,%9}, {%0,%1,%2,%3};"
        : "+f"(c[0]), "+f"(c[1]), "+f"(c[2]), "+f"(c[3])
        : "r"(a[0]), "r"(a[1]), "r"(a[2]), "r"(a[3]), "r"(b[0]), "r"(b[1]));
}
__device__ __forceinline__ void mma16h(uint32_t* c, const uint32_t* a, const uint32_t* b){
    asm volatile("mma.sync.aligned.m16n8k16.row.col.f16.f16.f16.f16 "
        "{%0,%1}, {%2,%3,%4,%5}, {%6,%7}, {%0,%1};"
        : "+r"(c[0]), "+r"(c[1])
        : "r"(a[0]), "r"(a[1]), "r"(a[2]), "r"(a[3]), "r"(b[0]), "r"(b[1]));
}
__device__ __forceinline__ void ldsm4(uint32_t& r0, uint32_t& r1, uint32_t& r2,
                                      uint32_t& r3, uint32_t addr){
    asm volatile("ldmatrix.sync.aligned.m8n8.x4.shared.b16 {%0,%1,%2,%3}, [%4];"
        : "=r"(r0), "=r"(r1), "=r"(r2), "=r"(r3) : "r"(addr));
}
__device__ __forceinline__ void cpa16(uint32_t dst, const void* src){
    asm volatile("cp.async.cg.shared.global [%0], [%1], 16;" :: "r"(dst), "l"(src));
}
#define CPA_COMMIT() asm volatile("cp.async.commit_group;" ::: "memory")
#define USWZ(row, kg) ((row)*64 + (((kg) ^ (((row)>>1)&3)) << 4))

// ---------------- init ----------------------------------------------------------
__global__ void k_init(){
    int i = blockIdx.x * blockDim.x + threadIdx.x;
    if (i < BB*NH*NSEQ) g_rs[i] = 0.f;
    if (i < BB*NH*HD)   g_vc[i] = 0.f;
    if (i < NH) { g_s1[i] = 0.0; g_s2[i] = 0.0; }
}

// ---------------- pre-split: fp32 -> hi/lo half planes ---------------------------
__global__ void k_split(const float* __restrict__ src, int n8, float s, int sel){
    int i = blockIdx.x * blockDim.x + threadIdx.x;
    if (i >= n8) return;
    const float* p = (sel == 3) ? g_vt : src;
    float4 a = *(const float4*)(p + 8*(size_t)i);
    float4 b = *(const float4*)(p + 8*(size_t)i + 4);
    uint2 u0 = split2(a.x, a.y, s), u1 = split2(a.z, a.w, s);
    uint2 u2 = split2(b.x, b.y, s), u3 = split2(b.z, b.w, s);
    __half* dh; size_t off;
    if (sel == 0)      { dh = g_x;   off = XOFF; }
    else if (sel == 1) { dh = g_wq;  off = WQOFF; }
    else if (sel == 2) { dh = g_wp;  off = WPOFF; }
    else               { dh = g_vts; off = VOFF; }
    uint4 vh = {u0.x, u1.x, u2.x, u3.x};
    uint4 vl = {u0.y, u1.y, u2.y, u3.y};
    *(uint4*)(dh + 8*(size_t)i)       = vh;
    *(uint4*)(dh + off + 8*(size_t)i) = vl;
    if (sel == 3) {
        // colsum of raw v per (bh, d): g_vt rows are m-major, length 1024
        float cs = (a.x+a.y+a.z+a.w) + (b.x+b.y+b.z+b.w);
        atomicAdd(&g_vc[(8*(size_t)i) >> 10], cs);
    }
}

// ---------------- ldmatrix MMA core: one k32 chunk -------------------------------
template<int NT, int MT>
__device__ __forceinline__ void mma_chunk_p(
    uint32_t ah_b, uint32_t bh_b, uint32_t blo,
    const int* rba, const int* swa, int kha,
    const int* rbb, const int* swb, int khb,
    float accf[MT][NT][4], uint32_t acch[MT][NT][2])
{
    #pragma unroll
    for (int ks = 0; ks < 2; ks++) {
        uint32_t ah[MT][4], al[MT][4], bh4[NT/2][4], bl4[NT/2][4];
        #pragma unroll
        for (int i = 0; i < MT; i++) {
            int kg = ks*2 + kha;
            uint32_t off = rba[i] + (((uint32_t)(kg ^ swa[i])) << 4);
            ldsm4(ah[i][0], ah[i][1], ah[i][2], ah[i][3], ah_b + off);
            ldsm4(al[i][0], al[i][1], al[i][2], al[i][3], ah_b + 8192 + off);
        }
        #pragma unroll
        for (int g = 0; g < NT/2; g++) {
            int kg = ks*2 + khb;
            uint32_t off = rbb[g] + (((uint32_t)(kg ^ swb[g])) << 4);
            ldsm4(bh4[g][0], bh4[g][1], bh4[g][2], bh4[g][3], bh_b + off);
            ldsm4(bl4[g][0], bl4[g][1], bl4[g][2], bl4[g][3], bh_b + blo + off);
        }
        #pragma unroll
        for (int g = 0; g < NT/2; g++) {
            #pragma unroll
            for (int jj = 0; jj < 2; jj++) {
                int j = g*2 + jj;
                uint32_t bh2[2] = {bh4[g][jj*2], bh4[g][jj*2+1]};
                uint32_t bl2[2] = {bl4[g][jj*2], bl4[g][jj*2+1]};
                #pragma unroll
                for (int i = 0; i < MT; i++) {
                    mma16f(accf[i][j], ah[i], bh2);
                    mma16h(acch[i][j], al[i], bh2);
                    mma16h(acch[i][j], ah[i], bl2);
                }
            }
        }
    }
}

// ---------------- fp16x3 GEMM ----------------------------------------------------
// MODE 0: qkv  A=g_x   B=g_wq  K=768  -> q,k planes + raw v^T (UN 2^-14, +bias)
// MODE 1: qk   A=g_q   B=g_k   K=64   -> exp(SCALE*logit) + row-sum atomics
// MODE 2: av   A=g_mx  B=g_vts K=1024 -> g_g planes (affine w/ bna/bnc + vc)
// MODE 3: proj A=g_g   B=g_wp  K=768  -> d_out (UN 2^-10, +bias)
template<int MODE>
__global__ __launch_bounds__(256, (MODE==1) ? 3 : 2) void gemm_h(
    const float* __restrict__ bias, float* __restrict__ pC)
{
    constexpr int BM = 128, BN = 64;
    constexpr int NT = 4, MT = 2;
    constexpr int K   = (MODE==1) ? 64 : (MODE==2) ? 1024 : 768;
    constexpr int NC  = K / 32;
    constexpr int STG = 24576;  // Ah 0, Al 8192, Bh 16384, Bl 20480

    extern __shared__ __align__(16) char smem[];

    const int tid  = threadIdx.x;
    const int lane = tid & 31, warp = tid >> 5;
    const int wm = warp >> 1, wn = warp & 1;
    const int gid = lane >> 2, tig = lane & 3;
    const int Mblk = blockIdx.y * BM;
    const int Nblk = blockIdx.x * BN;
    const int bh   = blockIdx.z;
    const uint32_t sb = s2u(smem);

    // per-lane ldmatrix address components
    int rba[MT], swa[MT], rbb[NT/2], swb[NT/2];
    const int rA  = (lane & 7) + ((lane & 8) ? 8 : 0);
    const int kha = (lane >> 4) & 1;
    #pragma unroll
    for (int i = 0; i < MT; i++) {
        int row = wm*32 + i*16 + rA;
        rba[i] = row*64; swa[i] = (row>>1)&3;
    }
    const int rB  = (lane & 7) + ((lane & 16) ? 8 : 0);
    const int khb = (lane >> 3) & 1;
    #pragma unroll
    for (int g = 0; g < NT/2; g++) {
        int row = wn*32 + g*16 + rB;
        rbb[g] = row*64; swb[g] = (row>>1)&3;
    }

    const __half *Ah_g, *Bh_g;
    constexpr size_t ALO = (MODE==0) ? XOFF : (MODE==1) ? QOFF :
                           (MODE==2) ? MXOFF : GOFF;
    constexpr size_t BLO = (MODE==0) ? WQOFF : (MODE==1) ? QOFF :
                           (MODE==2) ? VOFF : WPOFF;
    if constexpr (MODE == 0)      { Ah_g = g_x; Bh_g = g_wq; }
    else if constexpr (MODE == 1) { size_t o = (size_t)bh*NSEQ*HD;
                                    Ah_g = g_q + o; Bh_g = g_k + o; }
    else if constexpr (MODE == 2) { Ah_g = g_mx + (size_t)bh*NN;
                                    Bh_g = g_vts + (size_t)bh*HD*NSEQ; }
    else                          { Ah_g = g_g; Bh_g = g_wp; }

    float accf[MT][NT][4] = {};
    uint32_t acch[MT][NT][2] = {};

    // ======== 3-stage cp.async pipeline, one barrier per chunk ========
    {
        const int r0 = tid >> 2, kg = tid & 3;
        auto issue = [&](int ch, int s) {
            uint32_t base = sb + s*STG;
            #pragma unroll
            for (int i = 0; i < 2; i++) {
                int r = r0 + i*64;
                uint32_t d = base + USWZ(r, kg);
                const __half* src = Ah_g + (size_t)(Mblk + r)*K + ch*32 + kg*8;
                cpa16(d,        src);
                cpa16(d + 8192, src + ALO);
            }
            {
                uint32_t d = base + 16384 + USWZ(r0, kg);
                const __half* src = Bh_g + (size_t)(Nblk + r0)*K + ch*32 + kg*8;
                cpa16(d,        src);
                cpa16(d + 4096, src + BLO);
            }
            CPA_COMMIT();
        };
        issue(0, 0);
        if (NC > 1) issue(1, 1);
        int s_cur = 0, s_nxt2 = 2;
        for (int ch = 0; ch < NC; ch++) {
            if (ch < NC - 1) {
                asm volatile("cp.async.wait_group 1;" ::: "memory");
            } else {
                asm volatile("cp.async.wait_group 0;" ::: "memory");
            }
            __syncthreads();
            if (ch + 2 < NC) issue(ch + 2, s_nxt2);
            uint32_t base = sb + s_cur*STG;
            mma_chunk_p<NT, MT>(base, base+16384, 4096,
                                rba, swa, kha, rbb, swb, khb, accf, acch);
            s_cur = (s_cur == 2) ? 0 : s_cur + 1;
            s_nxt2 = (s_nxt2 == 2) ? 0 : s_nxt2 + 1;
        }
        __syncthreads();
    }

    // ----------------- epilogue -----------------
    // UN: qkv 2^-14 (16*1024); qk 2^-10 (32*32); av 2^-17 (4096*32); proj 2^-10
    constexpr float UN = (MODE==0) ? (1.f/16384.f) : (MODE==2) ? (1.f/131072.f)
                                                               : (1.f/1024.f);
    float na = 0.f, ncs = 0.f;
    if constexpr (MODE == 2) { int gg = bh % NH; na = g_bna[gg]; ncs = g_bnc[gg]; }

    if constexpr (MODE == 1) {
        #pragma unroll
        for (int i = 0; i < MT; i++) {
            #pragma unroll
            for (int p = 0; p < 2; p++) {
                const int row = Mblk + wm*32 + i*16 + gid + p*8;
                float rsum = 0.f;
                #pragma unroll
                for (int j = 0; j < NT; j++) {
                    __half2 q = *(__half2*)&acch[i][j][p];
                    float2 cc = __half22float2(q);
                    float v0 = (accf[i][j][p*2+0] + cc.x) * UN;
                    float v1 = (accf[i][j][p*2+1] + cc.y) * UN;
                    float e0 = __expf(SCALE * v0);
                    float e1 = __expf(SCALE * v1);
                    int c0 = Nblk + wn*32 + j*8 + tig*2;
                    __stcs((float2*)(g_logits + (size_t)bh*NN + (size_t)row*NSEQ + c0),
                           make_float2(e0, e1));
                    rsum += e0 + e1;
                }
                rsum += __shfl_xor_sync(0xffffffffu, rsum, 1);
                rsum += __shfl_xor_sync(0xffffffffu, rsum, 2);
                if (tig == 0)
                    atomicAdd(&g_rs[(size_t)bh*NSEQ + row], rsum);
            }
        }
    } else {
        #pragma unroll
        for (int i = 0; i < MT; i++) {
            #pragma unroll
            for (int j = 0; j < NT; j++) {
                __half2 q0 = *(__half2*)&acch[i][j][0];
                __half2 q1 = *(__half2*)&acch[i][j][1];
                float2 c01 = __half22float2(q0);
                float2 c23 = __half22float2(q1);
                float cv[4] = {accf[i][j][0] + c01.x, accf[i][j][1] + c01.y,
                               accf[i][j][2] + c23.x, accf[i][j][3] + c23.y};
                int r0 = Mblk + wm*32 + i*16 + gid;
                int c0 = Nblk + wn*32 + j*8 + tig*2;
                #pragma unroll
                for (int p = 0; p < 2; p++) {
                    int row = r0 + p*8;
                    float v0 = cv[p*2+0] * UN, v1 = cv[p*2+1] * UN;
                    if constexpr (MODE == 0) {
                        int t3 = c0 / CDIM; int rem = c0 - t3*CDIM;
                        int h = rem >> 6, d = rem & 63;
                        int b = row >> 10, n = row & (NSEQ - 1);
                        v0 += bias[c0]; v1 += bias[c0+1];
                        if (t3 < 2) {
                            uint2 sp = split2(v0, v1, 32.f);
                            size_t idx = ((((size_t)(b*NH+h))*NSEQ + n) << 6) + d;
                            __half* dst = (t3 == 0) ? g_q : g_k;
                            *(uint32_t*)(dst + idx)        = sp.x;
                            *(uint32_t*)(dst + QOFF + idx) = sp.y;
                        } else {
                            size_t base = (((size_t)(b*NH+h))*HD + d)*NSEQ + n;
                            g_vt[base]        = v0;
                            g_vt[base + NSEQ] = v1;
                        }
                    } else if constexpr (MODE == 2) {
                        // out = bna*(mix@v) + bnc*colsum(v) ; d = c0 (Nblk=0)
                        int b = bh / NH, g = bh % NH;
                        float w0 = fmaf(na, v0, ncs * g_vc[bh*HD + c0]);
                        float w1 = fmaf(na, v1, ncs * g_vc[bh*HD + c0 + 1]);
                        uint2 sp = split2(w0, w1, 1.f);
                        size_t idx = ((size_t)(b*NSEQ + row))*CDIM + g*HD + c0;
                        *(uint32_t*)(g_g + idx)        = sp.x;
                        *(uint32_t*)(g_g + GOFF + idx) = sp.y;
                    } else {
                        float2 s = make_float2(v0 + bias[c0], v1 + bias[c0+1]);
                        *(float2*)(pC + (size_t)row*CDIM + c0) = s;
                    }
                }
            }
        }
    }
}

// ---------------- streaming softmax-finish + head mix + BN stats ---------------
// writes raw mixed attn as SPLIT fp16 planes (x4096) into g_mx
__global__ void k_mix(const float* __restrict__ w_re, const float* __restrict__ b_re) {
    __shared__ float wre[NH][NH];
    __shared__ float bre[NH], sinv[NH];
    __shared__ float sm1[NH], sm2[NH];
    const int b = blockIdx.x >> 10;
    const int n = blockIdx.x & 1023;
    const int t = threadIdx.x;               // 256
    const int lane = t & 31;
    if (t < NH*NH) wre[t/NH][t%NH] = w_re[t];
    if (t < NH) {
        bre[t] = b_re[t];
        sinv[t] = 1.0f / g_rs[((size_t)(b*NH + t))*NSEQ + n];
        sm1[t] = 0.f; sm2[t] = 0.f;
    }
    __syncthreads();
    const int m = t << 2;
    float L[NH][4];
    #pragma unroll
    for (int h = 0; h < NH; h++) {
        float4 e = *(const float4*)(g_logits + (((size_t)(b*NH+h))*NSEQ + n)*NSEQ + m);
        float si = sinv[h];
        L[h][0] = e.x*si; L[h][1] = e.y*si; L[h][2] = e.z*si; L[h][3] = e.w*si;
    }
    #pragma unroll
    for (int g = 0; g < NH; g++) {
        float o0=bre[g], o1=bre[g], o2=bre[g], o3=bre[g];
        #pragma unroll
        for (int h = 0; h < NH; h++) {
            float w = wre[g][h];
            o0 = fmaf(w, L[h][0], o0); o1 = fmaf(w, L[h][1], o1);
            o2 = fmaf(w, L[h][2], o2); o3 = fmaf(w, L[h][3], o3);
        }
        size_t idx = (((size_t)(b*NH+g))*NSEQ + n)*NSEQ + m;
        uint2 u01 = split2(o0, o1, 4096.f);
        uint2 u23 = split2(o2, o3, 4096.f);
        uint2 sh = {u01.x, u23.x};
        uint2 sl = {u01.y, u23.y};
        __stcs((uint2*)(g_mx + idx), sh);
        __stcs((uint2*)(g_mx + MXOFF + idx), sl);
        float a = (o0+o1)+(o2+o3);
        float c = o0*o0+o1*o1+o2*o2+o3*o3;
        #pragma unroll
        for (int o = 16; o; o >>= 1) {
            a += __shfl_xor_sync(0xffffffffu, a, o);
            c += __shfl_xor_sync(0xffffffffu, c, o);
        }
        if (lane == 0) { atomicAdd(&sm1[g], a); atomicAdd(&sm2[g], c); }
    }
    __syncthreads();
    if (t < NH) {
        atomicAdd(&g_s1[t], (double)sm1[t]);
        atomicAdd(&g_s2[t], (double)sm2[t]);
    }
}

// ---------------- BN finalize (double precision) --------------------------------
__global__ void k_bnfin(const float* __restrict__ gamma, const float* __restrict__ beta) {
    int g = threadIdx.x;
    if (g < NH) {
        double cnt = (double)BB * NSEQ * NSEQ;
        double mean = g_s1[g] / cnt;
        double var  = g_s2[g] / cnt - mean * mean;
        float a = (float)((double)gamma[g] / sqrt(var + (double)BNEPS));
        g_bna[g] = a;
        g_bnc[g] = beta[g] - a * (float)mean;
    }
}

// ---------------- normalized attn output: a*mix + c -> d_out --------------------
__global__ void k_norm(float* __restrict__ dout) {
    size_t i = (size_t)blockIdx.x * blockDim.x + threadIdx.x;  // 8 elems/thread
    size_t base = i * 8;
    int g = (int)((base >> 20) % NH);            // NN = 2^20
    float a = g_bna[g] * (1.f / 4096.f);
    float c = g_bnc[g];
    uint4 vh = __ldcs((const uint4*)(g_mx + base));
    uint4 vl = __ldcs((const uint4*)(g_mx + MXOFF + base));
    float* o = dout + OUT_OFF + base;
    float2 h, l; float4 r;
    h = __half22float2(*(__half2*)&vh.x); l = __half22float2(*(__half2*)&vl.x);
    r.x = fmaf(a, h.x + l.x, c); r.y = fmaf(a, h.y + l.y, c);
    h = __half22float2(*(__half2*)&vh.y); l = __half22float2(*(__half2*)&vl.y);
    r.z = fmaf(a, h.x + l.x, c); r.w = fmaf(a, h.y + l.y, c);
    __stcs((float4*)o, r);
    h = __half22float2(*(__half2*)&vh.z); l = __half22float2(*(__half2*)&vl.z);
    r.x = fmaf(a, h.x + l.x, c); r.y = fmaf(a, h.y + l.y, c);
    h = __half22float2(*(__half2*)&vh.w); l = __half22float2(*(__half2*)&vl.w);
    r.z = fmaf(a, h.x + l.x, c); r.w = fmaf(a, h.y + l.y, c);
    __stcs((float4*)(o + 4), r);
}

// ---------------- launcher --------------------------------------------------------
extern "C" void kernel_launch(void* const* d_in, const int* in_sizes, int n_in,
                              void* d_out, int out_size) {
    const float* x    = (const float*)d_in[0];
    const float* wqkv = (const float*)d_in[1];
    const float* bqkv = (const float*)d_in[2];
    const float* wre  = (const float*)d_in[3];
    const float* bre  = (const float*)d_in[4];
    const float* gam  = (const float*)d_in[5];
    const float* bet  = (const float*)d_in[6];
    const float* wp   = (const float*)d_in[7];
    const float* bp   = (const float*)d_in[8];
    float* out = (float*)d_out;

    const int SM3 = 3 * 24576;                 // 73728
    cudaFuncSetAttribute(gemm_h<0>, cudaFuncAttributeMaxDynamicSharedMemorySize, SM3);
    cudaFuncSetAttribute(gemm_h<1>, cudaFuncAttributeMaxDynamicSharedMemorySize, SM3);
    cudaFuncSetAttribute(gemm_h<2>, cudaFuncAttributeMaxDynamicSharedMemorySize, SM3);
    cudaFuncSetAttribute(gemm_h<3>, cudaFuncAttributeMaxDynamicSharedMemorySize, SM3);

    k_init<<<96, 1024>>>();                                           // 1
    k_split<<<3072, 256>>>(x,    786432, 16.f,   0);                  // 2: x
    k_split<<<864,  256>>>(wqkv, 221184, 1024.f, 1);                  // 3: w_qkv
    gemm_h<0><<<dim3(36, 64, 1), 256, SM3>>>(bqkv, nullptr);          // 4: qkv (PROFILED)
    k_split<<<288,  256>>>(wp,    73728, 1024.f, 2);                  // 5: w_proj
    k_split<<<3072, 256>>>(nullptr, 786432, 32.f, 3);                 // 6: v^T + colsum
    gemm_h<1><<<dim3(16, 8, 96), 256, SM3>>>(nullptr, nullptr);       // 7: qk
    k_mix<<<8192, 256>>>(wre, bre);                                   // 8: mix -> planes
    k_bnfin<<<1, 32>>>(gam, bet);                                     // 9
    gemm_h<2><<<dim3(1, 8, 96),  256, SM3>>>(nullptr, nullptr);       // 10: av (pure GEMM)
    k_norm<<<49152, 256>>>(out);                                      // 11: attn output
    gemm_h<3><<<dim3(12, 64, 1), 256, SM3>>>(bp, out);                // 12: proj
}

// round 12
// speedup vs baseline: 2.0043x; 1.0375x over previous
#include <cuda_runtime.h>
#include <cuda_fp16.h>
#include <math.h>
#include <stdint.h>

#define BB 8
#define NSEQ 1024
#define CDIM 768
#define NH 12
#define HD 64
#define SCALE 0.125f
#define BNEPS 1e-5f
#define OUT_OFF (BB*NSEQ*CDIM)
#define NN ((size_t)NSEQ*NSEQ)

// plane sizes (hi plane at [0], lo plane at [OFF])
#define XOFF  (BB*NSEQ*CDIM)      // 6291456
#define WQOFF (3*CDIM*CDIM)       // 1769472
#define WPOFF (CDIM*CDIM)         // 589824
#define QOFF  (BB*NH*NSEQ*HD)     // 6291456
#define VOFF  (BB*NH*HD*NSEQ)     // 6291456
#define GOFF  (BB*NSEQ*CDIM)      // 6291456
#define MXOFF ((size_t)BB*NH*NSEQ*NSEQ)   // 100663296

// ---------------- scratch: merged hi/lo half planes ----------------------------
__device__ __half g_x  [2*XOFF];    // x * 16
__device__ __half g_wq [2*WQOFF];   // w_qkv * 1024
__device__ __half g_wp [2*WPOFF];   // w_proj * 1024
__device__ __half g_q  [2*QOFF];    // q * 32
__device__ __half g_k  [2*QOFF];    // k * 32
__device__ __half g_vts[2*VOFF];    // v^T * 32 [bh][d][m]
__device__ __half g_g  [2*GOFF];    // attn@v [b*N+n][c]
__device__ __half g_mx [2*MXOFF];   // raw mixed attn * 4096 [bh][n][m]
__device__ float  g_vt [VOFF];      // raw v^T
__device__ float  g_vc [BB*NH*HD];  // colsum of v per (bh, d)
__device__ float  g_logits[BB*NH*NSEQ*NSEQ];   // exp(SCALE*q.k)
__device__ float  g_rs[BB*NH*NSEQ];
__device__ double g_s1[NH];
__device__ double g_s2[NH];
__device__ float  g_bna[NH];
__device__ float  g_bnc[NH];

// ---------------- helpers -------------------------------------------------------
__device__ __forceinline__ uint32_t s2u(const void* p){
    uint32_t a;
    asm("{ .reg .u64 t; cvta.to.shared.u64 t, %1; cvt.u32.u64 %0, t; }" : "=r"(a) : "l"(p));
    return a;
}
__device__ __forceinline__ uint2 split2(float x0, float x1, float s){
    x0 *= s; x1 *= s;
    __half h0 = __float2half_rn(x0), h1 = __float2half_rn(x1);
    __half g0 = __float2half_rn(x0 - __half2float(h0));
    __half g1 = __float2half_rn(x1 - __half2float(h1));
    __half2 hh = __halves2half2(h0, h1), ll = __halves2half2(g0, g1);
    uint2 r;
    r.x = *(uint32_t*)&hh; r.y = *(uint32_t*)&ll;
    return r;
}
__device__ __forceinline__ void mma16f(float* c, const uint32_t* a, const uint32_t* b){
    asm volatile("mma.sync.aligned.m16n8k16.row.col.f32.f16.f16.f32 "
        "{%0,%1,%2,%3}, {%4,%5,%6,%7}, {%8,%9}, {%0,%1,%2,%3};"
        : "+f"(c[0]), "+f"(c[1]), "+f"(c[2]), "+f"(c[3])
        : "r"(a[0]), "r"(a[1]), "r"(a[2]), "r"(a[3]), "r"(b[0]), "r"(b[1]));
}
__device__ __forceinline__ void mma16h(uint32_t* c, const uint32_t* a, const uint32_t* b){
    asm volatile("mma.sync.aligned.m16n8k16.row.col.f16.f16.f16.f16 "
        "{%0,%1}, {%2,%3,%4,%5}, {%6,%7}, {%0,%1};"
        : "+r"(c[0]), "+r"(c[1])
        : "r"(a[0]), "r"(a[1]), "r"(a[2]), "r"(a[3]), "r"(b[0]), "r"(b[1]));
}
__device__ __forceinline__ void ldsm4(uint32_t& r0, uint32_t& r1, uint32_t& r2,
                                      uint32_t& r3, uint32_t addr){
    asm volatile("ldmatrix.sync.aligned.m8n8.x4.shared.b16 {%0,%1,%2,%3}, [%4];"
        : "=r"(r0), "=r"(r1), "=r"(r2), "=r"(r3) : "r"(addr));
}
__device__ __forceinline__ void cpa16(uint32_t dst, const void* src){
    asm volatile("cp.async.cg.shared.global [%0], [%1], 16;" :: "r"(dst), "l"(src));
}
#define CPA_COMMIT() asm volatile("cp.async.commit_group;" ::: "memory")
#define USWZ(row, kg) ((row)*64 + (((kg) ^ (((row)>>1)&3)) << 4))

// ---------------- init ----------------------------------------------------------
__global__ void k_init(){
    int i = blockIdx.x * blockDim.x + threadIdx.x;
    if (i < BB*NH*NSEQ) g_rs[i] = 0.f;
    if (i < BB*NH*HD)   g_vc[i] = 0.f;
    if (i < NH) { g_s1[i] = 0.0; g_s2[i] = 0.0; }
}

// ---------------- pre-split: fp32 -> hi/lo half planes ---------------------------
__global__ void k_split(const float* __restrict__ src, int n8, float s, int sel){
    int i = blockIdx.x * blockDim.x + threadIdx.x;
    if (i >= n8) return;
    const float* p = (sel == 3) ? g_vt : src;
    float4 a = *(const float4*)(p + 8*(size_t)i);
    float4 b = *(const float4*)(p + 8*(size_t)i + 4);
    uint2 u0 = split2(a.x, a.y, s), u1 = split2(a.z, a.w, s);
    uint2 u2 = split2(b.x, b.y, s), u3 = split2(b.z, b.w, s);
    __half* dh; size_t off;
    if (sel == 0)      { dh = g_x;   off = XOFF; }
    else if (sel == 1) { dh = g_wq;  off = WQOFF; }
    else if (sel == 2) { dh = g_wp;  off = WPOFF; }
    else               { dh = g_vts; off = VOFF; }
    uint4 vh = {u0.x, u1.x, u2.x, u3.x};
    uint4 vl = {u0.y, u1.y, u2.y, u3.y};
    *(uint4*)(dh + 8*(size_t)i)       = vh;
    *(uint4*)(dh + off + 8*(size_t)i) = vl;
    if (sel == 3) {
        float cs = (a.x+a.y+a.z+a.w) + (b.x+b.y+b.z+b.w);
        atomicAdd(&g_vc[(8*(size_t)i) >> 10], cs);
    }
}

// ---------------- ldmatrix MMA core: one k32 chunk -------------------------------
template<int NT, int MT>
__device__ __forceinline__ void mma_chunk_p(
    uint32_t ah_b, uint32_t bh_b, uint32_t blo,
    const int* rba, const int* swa, int kha,
    const int* rbb, const int* swb, int khb,
    float accf[MT][NT][4], uint32_t acch[MT][NT][2])
{
    #pragma unroll
    for (int ks = 0; ks < 2; ks++) {
        uint32_t ah[MT][4], al[MT][4], bh4[NT/2][4], bl4[NT/2][4];
        #pragma unroll
        for (int i = 0; i < MT; i++) {
            int kg = ks*2 + kha;
            uint32_t off = rba[i] + (((uint32_t)(kg ^ swa[i])) << 4);
            ldsm4(ah[i][0], ah[i][1], ah[i][2], ah[i][3], ah_b + off);
            ldsm4(al[i][0], al[i][1], al[i][2], al[i][3], ah_b + 8192 + off);
        }
        #pragma unroll
        for (int g = 0; g < NT/2; g++) {
            int kg = ks*2 + khb;
            uint32_t off = rbb[g] + (((uint32_t)(kg ^ swb[g])) << 4);
            ldsm4(bh4[g][0], bh4[g][1], bh4[g][2], bh4[g][3], bh_b + off);
            ldsm4(bl4[g][0], bl4[g][1], bl4[g][2], bl4[g][3], bh_b + blo + off);
        }
        #pragma unroll
        for (int g = 0; g < NT/2; g++) {
            #pragma unroll
            for (int jj = 0; jj < 2; jj++) {
                int j = g*2 + jj;
                uint32_t bh2[2] = {bh4[g][jj*2], bh4[g][jj*2+1]};
                uint32_t bl2[2] = {bl4[g][jj*2], bl4[g][jj*2+1]};
                #pragma unroll
                for (int i = 0; i < MT; i++) {
                    mma16f(accf[i][j], ah[i], bh2);
                    mma16h(acch[i][j], al[i], bh2);
                    mma16h(acch[i][j], ah[i], bl2);
                }
            }
        }
    }
}

// ---------------- fp16x3 GEMM ----------------------------------------------------
// MODE 0: qkv  A=g_x   B=g_wq  K=768  -> q,k planes + raw v^T (UN 2^-14, +bias)
// MODE 1: qk   A=g_q   B=g_k   K=64   -> exp(SCALE*logit) + row-sum atomics
// MODE 2: av   A=g_mx  B=g_vts K=1024 -> g_g planes + FUSED normalized attn -> d_out
// MODE 3: proj A=g_g   B=g_wp  K=768  -> d_out (UN 2^-10, +bias)
template<int MODE>
__global__ __launch_bounds__(256, (MODE==1) ? 3 : 2) void gemm_h(
    const float* __restrict__ bias, float* __restrict__ pC)
{
    constexpr int BM = 128, BN = 64;
    constexpr int NT = 4, MT = 2;
    constexpr int K   = (MODE==1) ? 64 : (MODE==2) ? 1024 : 768;
    constexpr int NC  = K / 32;
    constexpr int STG = 24576;  // Ah 0, Al 8192, Bh 16384, Bl 20480

    extern __shared__ __align__(16) char smem[];

    const int tid  = threadIdx.x;
    const int lane = tid & 31, warp = tid >> 5;
    const int wm = warp >> 1, wn = warp & 1;
    const int gid = lane >> 2, tig = lane & 3;
    const int Mblk = blockIdx.y * BM;
    const int Nblk = blockIdx.x * BN;
    const int bh   = blockIdx.z;
    const uint32_t sb = s2u(smem);

    // per-lane ldmatrix address components
    int rba[MT], swa[MT], rbb[NT/2], swb[NT/2];
    const int rA  = (lane & 7) + ((lane & 8) ? 8 : 0);
    const int kha = (lane >> 4) & 1;
    #pragma unroll
    for (int i = 0; i < MT; i++) {
        int row = wm*32 + i*16 + rA;
        rba[i] = row*64; swa[i] = (row>>1)&3;
    }
    const int rB  = (lane & 7) + ((lane & 16) ? 8 : 0);
    const int khb = (lane >> 3) & 1;
    #pragma unroll
    for (int g = 0; g < NT/2; g++) {
        int row = wn*32 + g*16 + rB;
        rbb[g] = row*64; swb[g] = (row>>1)&3;
    }

    const __half *Ah_g, *Bh_g;
    constexpr size_t ALO = (MODE==0) ? XOFF : (MODE==1) ? QOFF :
                           (MODE==2) ? MXOFF : GOFF;
    constexpr size_t BLO = (MODE==0) ? WQOFF : (MODE==1) ? QOFF :
                           (MODE==2) ? VOFF : WPOFF;
    if constexpr (MODE == 0)      { Ah_g = g_x; Bh_g = g_wq; }
    else if constexpr (MODE == 1) { size_t o = (size_t)bh*NSEQ*HD;
                                    Ah_g = g_q + o; Bh_g = g_k + o; }
    else if constexpr (MODE == 2) { Ah_g = g_mx + (size_t)bh*NN;
                                    Bh_g = g_vts + (size_t)bh*HD*NSEQ; }
    else                          { Ah_g = g_g; Bh_g = g_wp; }

    // BN affine constants (MODE 2 only)
    float na = 0.f, ncs = 0.f, an = 0.f;
    if constexpr (MODE == 2) {
        int gg = bh % NH;
        na = g_bna[gg]; ncs = g_bnc[gg];
        an = na * (1.f / 4096.f);
    }

    float accf[MT][NT][4] = {};
    uint32_t acch[MT][NT][2] = {};

    // ======== 3-stage cp.async pipeline, one barrier per chunk ========
    {
        const int r0 = tid >> 2, kg = tid & 3;
        auto issue = [&](int ch, int s) {
            uint32_t base = sb + s*STG;
            #pragma unroll
            for (int i = 0; i < 2; i++) {
                int r = r0 + i*64;
                uint32_t d = base + USWZ(r, kg);
                const __half* src = Ah_g + (size_t)(Mblk + r)*K + ch*32 + kg*8;
                cpa16(d,        src);
                cpa16(d + 8192, src + ALO);
            }
            {
                uint32_t d = base + 16384 + USWZ(r0, kg);
                const __half* src = Bh_g + (size_t)(Nblk + r0)*K + ch*32 + kg*8;
                cpa16(d,        src);
                cpa16(d + 4096, src + BLO);
            }
            CPA_COMMIT();
        };
        issue(0, 0);
        if (NC > 1) issue(1, 1);
        int s_cur = 0, s_nxt2 = 2;
        for (int ch = 0; ch < NC; ch++) {
            if (ch < NC - 1) {
                asm volatile("cp.async.wait_group 1;" ::: "memory");
            } else {
                asm volatile("cp.async.wait_group 0;" ::: "memory");
            }
            __syncthreads();
            if (ch + 2 < NC) issue(ch + 2, s_nxt2);
            uint32_t base = sb + s_cur*STG;
            if constexpr (MODE == 2) {
                // FUSED attn output: read back staged A tile (hi+lo), apply
                // bna/4096*(hi+lo)+bnc, stream to d_out attn slot.
                // thread t: row rr = t>>1, kg pair kp = (t&1)*2 (16 m-values)
                const int rr = tid >> 1;
                const int kp = (tid & 1) * 2;
                uint32_t o0 = base + USWZ(rr, kp);
                uint32_t o1 = base + USWZ(rr, kp + 1);
                uint4 h0 = *(const uint4*)(smem + (o0 - sb));
                uint4 h1 = *(const uint4*)(smem + (o1 - sb));
                uint4 l0 = *(const uint4*)(smem + (o0 - sb) + 8192);
                uint4 l1 = *(const uint4*)(smem + (o1 - sb) + 8192);
                float* dst = pC + OUT_OFF + (size_t)bh*NN
                           + (size_t)(Mblk + rr)*1024 + ch*32 + kp*8;
                #pragma unroll
                for (int u = 0; u < 2; u++) {
                    const uint4& hv = u ? h1 : h0;
                    const uint4& lv = u ? l1 : l0;
                    const uint32_t hw[4] = {hv.x, hv.y, hv.z, hv.w};
                    const uint32_t lw[4] = {lv.x, lv.y, lv.z, lv.w};
                    #pragma unroll
                    for (int q = 0; q < 2; q++) {
                        float4 r;
                        float2 a0 = __half22float2(*(__half2*)&hw[q*2+0]);
                        float2 b0 = __half22float2(*(__half2*)&lw[q*2+0]);
                        float2 a1 = __half22float2(*(__half2*)&hw[q*2+1]);
                        float2 b1 = __half22float2(*(__half2*)&lw[q*2+1]);
                        r.x = fmaf(an, a0.x + b0.x, ncs);
                        r.y = fmaf(an, a0.y + b0.y, ncs);
                        r.z = fmaf(an, a1.x + b1.x, ncs);
                        r.w = fmaf(an, a1.y + b1.y, ncs);
                        __stcs((float4*)(dst + u*8 + q*4), r);
                    }
                }
            }
            mma_chunk_p<NT, MT>(base, base+16384, 4096,
                                rba, swa, kha, rbb, swb, khb, accf, acch);
            s_cur = (s_cur == 2) ? 0 : s_cur + 1;
            s_nxt2 = (s_nxt2 == 2) ? 0 : s_nxt2 + 1;
        }
        __syncthreads();
    }

    // ----------------- epilogue -----------------
    // UN: qkv 2^-14 (16*1024); qk 2^-10 (32*32); av 2^-17 (4096*32); proj 2^-10
    constexpr float UN = (MODE==0) ? (1.f/16384.f) : (MODE==2) ? (1.f/131072.f)
                                                               : (1.f/1024.f);
    if constexpr (MODE == 1) {
        #pragma unroll
        for (int i = 0; i < MT; i++) {
            #pragma unroll
            for (int p = 0; p < 2; p++) {
                const int row = Mblk + wm*32 + i*16 + gid + p*8;
                float rsum = 0.f;
                #pragma unroll
                for (int j = 0; j < NT; j++) {
                    __half2 q = *(__half2*)&acch[i][j][p];
                    float2 cc = __half22float2(q);
                    float v0 = (accf[i][j][p*2+0] + cc.x) * UN;
                    float v1 = (accf[i][j][p*2+1] + cc.y) * UN;
                    float e0 = __expf(SCALE * v0);
                    float e1 = __expf(SCALE * v1);
                    int c0 = Nblk + wn*32 + j*8 + tig*2;
                    __stcs((float2*)(g_logits + (size_t)bh*NN + (size_t)row*NSEQ + c0),
                           make_float2(e0, e1));
                    rsum += e0 + e1;
                }
                rsum += __shfl_xor_sync(0xffffffffu, rsum, 1);
                rsum += __shfl_xor_sync(0xffffffffu, rsum, 2);
                if (tig == 0)
                    atomicAdd(&g_rs[(size_t)bh*NSEQ + row], rsum);
            }
        }
    } else {
        #pragma unroll
        for (int i = 0; i < MT; i++) {
            #pragma unroll
            for (int j = 0; j < NT; j++) {
                __half2 q0 = *(__half2*)&acch[i][j][0];
                __half2 q1 = *(__half2*)&acch[i][j][1];
                float2 c01 = __half22float2(q0);
                float2 c23 = __half22float2(q1);
                float cv[4] = {accf[i][j][0] + c01.x, accf[i][j][1] + c01.y,
                               accf[i][j][2] + c23.x, accf[i][j][3] + c23.y};
                int r0 = Mblk + wm*32 + i*16 + gid;
                int c0 = Nblk + wn*32 + j*8 + tig*2;
                #pragma unroll
                for (int p = 0; p < 2; p++) {
                    int row = r0 + p*8;
                    float v0 = cv[p*2+0] * UN, v1 = cv[p*2+1] * UN;
                    if constexpr (MODE == 0) {
                        int t3 = c0 / CDIM; int rem = c0 - t3*CDIM;
                        int h = rem >> 6, d = rem & 63;
                        int b = row >> 10, n = row & (NSEQ - 1);
                        v0 += bias[c0]; v1 += bias[c0+1];
                        if (t3 < 2) {
                            uint2 sp = split2(v0, v1, 32.f);
                            size_t idx = ((((size_t)(b*NH+h))*NSEQ + n) << 6) + d;
                            __half* dst = (t3 == 0) ? g_q : g_k;
                            *(uint32_t*)(dst + idx)        = sp.x;
                            *(uint32_t*)(dst + QOFF + idx) = sp.y;
                        } else {
                            size_t base = (((size_t)(b*NH+h))*HD + d)*NSEQ + n;
                            g_vt[base]        = v0;
                            g_vt[base + NSEQ] = v1;
                        }
                    } else if constexpr (MODE == 2) {
                        // out = bna*(mix@v) + bnc*colsum(v)
                        int b = bh / NH, g = bh % NH;
                        float w0 = fmaf(na, v0, ncs * g_vc[bh*HD + c0]);
                        float w1 = fmaf(na, v1, ncs * g_vc[bh*HD + c0 + 1]);
                        uint2 sp = split2(w0, w1, 1.f);
                        size_t idx = ((size_t)(b*NSEQ + row))*CDIM + g*HD + c0;
                        *(uint32_t*)(g_g + idx)        = sp.x;
                        *(uint32_t*)(g_g + GOFF + idx) = sp.y;
                    } else {
                        float2 s = make_float2(v0 + bias[c0], v1 + bias[c0+1]);
                        *(float2*)(pC + (size_t)row*CDIM + c0) = s;
                    }
                }
            }
        }
    }
}

// ---------------- streaming softmax-finish + head mix + BN stats ---------------
// writes raw mixed attn as SPLIT fp16 planes (x4096) into g_mx
__global__ void k_mix(const float* __restrict__ w_re, const float* __restrict__ b_re) {
    __shared__ float wre[NH][NH];
    __shared__ float bre[NH], sinv[NH];
    __shared__ float sm1[NH], sm2[NH];
    const int b = blockIdx.x >> 10;
    const int n = blockIdx.x & 1023;
    const int t = threadIdx.x;               // 256
    const int lane = t & 31;
    if (t < NH*NH) wre[t/NH][t%NH] = w_re[t];
    if (t < NH) {
        bre[t] = b_re[t];
        sinv[t] = 1.0f / g_rs[((size_t)(b*NH + t))*NSEQ + n];
        sm1[t] = 0.f; sm2[t] = 0.f;
    }
    __syncthreads();
    const int m = t << 2;
    float L[NH][4];
    #pragma unroll
    for (int h = 0; h < NH; h++) {
        float4 e = *(const float4*)(g_logits + (((size_t)(b*NH+h))*NSEQ + n)*NSEQ + m);
        float si = sinv[h];
        L[h][0] = e.x*si; L[h][1] = e.y*si; L[h][2] = e.z*si; L[h][3] = e.w*si;
    }
    #pragma unroll
    for (int g = 0; g < NH; g++) {
        float o0=bre[g], o1=bre[g], o2=bre[g], o3=bre[g];
        #pragma unroll
        for (int h = 0; h < NH; h++) {
            float w = wre[g][h];
            o0 = fmaf(w, L[h][0], o0); o1 = fmaf(w, L[h][1], o1);
            o2 = fmaf(w, L[h][2], o2); o3 = fmaf(w, L[h][3], o3);
        }
        size_t idx = (((size_t)(b*NH+g))*NSEQ + n)*NSEQ + m;
        uint2 u01 = split2(o0, o1, 4096.f);
        uint2 u23 = split2(o2, o3, 4096.f);
        uint2 sh = {u01.x, u23.x};
        uint2 sl = {u01.y, u23.y};
        __stcs((uint2*)(g_mx + idx), sh);
        __stcs((uint2*)(g_mx + MXOFF + idx), sl);
        float a = (o0+o1)+(o2+o3);
        float c = o0*o0+o1*o1+o2*o2+o3*o3;
        #pragma unroll
        for (int o = 16; o; o >>= 1) {
            a += __shfl_xor_sync(0xffffffffu, a, o);
            c += __shfl_xor_sync(0xffffffffu, c, o);
        }
        if (lane == 0) { atomicAdd(&sm1[g], a); atomicAdd(&sm2[g], c); }
    }
    __syncthreads();
    if (t < NH) {
        atomicAdd(&g_s1[t], (double)sm1[t]);
        atomicAdd(&g_s2[t], (double)sm2[t]);
    }
}

// ---------------- BN finalize (double precision) --------------------------------
__global__ void k_bnfin(const float* __restrict__ gamma, const float* __restrict__ beta) {
    int g = threadIdx.x;
    if (g < NH) {
        double cnt = (double)BB * NSEQ * NSEQ;
        double mean = g_s1[g] / cnt;
        double var  = g_s2[g] / cnt - mean * mean;
        float a = (float)((double)gamma[g] / sqrt(var + (double)BNEPS));
        g_bna[g] = a;
        g_bnc[g] = beta[g] - a * (float)mean;
    }
}

// ---------------- launcher --------------------------------------------------------
extern "C" void kernel_launch(void* const* d_in, const int* in_sizes, int n_in,
                              void* d_out, int out_size) {
    const float* x    = (const float*)d_in[0];
    const float* wqkv = (const float*)d_in[1];
    const float* bqkv = (const float*)d_in[2];
    const float* wre  = (const float*)d_in[3];
    const float* bre  = (const float*)d_in[4];
    const float* gam  = (const float*)d_in[5];
    const float* bet  = (const float*)d_in[6];
    const float* wp   = (const float*)d_in[7];
    const float* bp   = (const float*)d_in[8];
    float* out = (float*)d_out;

    const int SM3 = 3 * 24576;                 // 73728
    cudaFuncSetAttribute(gemm_h<0>, cudaFuncAttributeMaxDynamicSharedMemorySize, SM3);
    cudaFuncSetAttribute(gemm_h<1>, cudaFuncAttributeMaxDynamicSharedMemorySize, SM3);
    cudaFuncSetAttribute(gemm_h<2>, cudaFuncAttributeMaxDynamicSharedMemorySize, SM3);
    cudaFuncSetAttribute(gemm_h<3>, cudaFuncAttributeMaxDynamicSharedMemorySize, SM3);

    k_init<<<96, 1024>>>();                                           // 1
    k_split<<<3072, 256>>>(x,    786432, 16.f,   0);                  // 2: x
    k_split<<<864,  256>>>(wqkv, 221184, 1024.f, 1);                  // 3: w_qkv
    gemm_h<0><<<dim3(36, 64, 1), 256, SM3>>>(bqkv, nullptr);          // 4: qkv (PROFILED)
    k_split<<<288,  256>>>(wp,    73728, 1024.f, 2);                  // 5: w_proj
    k_split<<<3072, 256>>>(nullptr, 786432, 32.f, 3);                 // 6: v^T + colsum
    gemm_h<1><<<dim3(16, 8, 96), 256, SM3>>>(nullptr, nullptr);       // 7: qk
    k_mix<<<8192, 256>>>(wre, bre);                                   // 8: mix -> planes
    k_bnfin<<<1, 32>>>(gam, bet);                                     // 9
    gemm_h<2><<<dim3(1, 8, 96),  256, SM3>>>(nullptr, out);           // 10: av + attn out
    gemm_h<3><<<dim3(12, 64, 1), 256, SM3>>>(bp, out);                // 11: proj
}

// round 13
// speedup vs baseline: 2.0592x; 1.0274x over previous
#include <cuda_runtime.h>
#include <cuda_fp16.h>
#include <math.h>
#include <stdint.h>

#define BB 8
#define NSEQ 1024
#define CDIM 768
#define NH 12
#define HD 64
#define SCALE 0.125f
#define BNEPS 1e-5f
#define OUT_OFF (BB*NSEQ*CDIM)
#define NN ((size_t)NSEQ*NSEQ)

// plane sizes (hi plane at [0], lo plane at [OFF])
#define XOFF  (BB*NSEQ*CDIM)      // 6291456
#define WQOFF (3*CDIM*CDIM)       // 1769472
#define WPOFF (CDIM*CDIM)         // 589824
#define QOFF  (BB*NH*NSEQ*HD)     // 6291456
#define VOFF  (BB*NH*HD*NSEQ)     // 6291456
#define GOFF  (BB*NSEQ*CDIM)      // 6291456
#define MXOFF ((size_t)BB*NH*NSEQ*NSEQ)   // 100663296

// ---------------- scratch: merged hi/lo half planes ----------------------------
__device__ __half g_x  [2*XOFF];    // x * 16
__device__ __half g_wq [2*WQOFF];   // w_qkv * 1024
__device__ __half g_wp [2*WPOFF];   // w_proj * 1024
__device__ __half g_q  [2*QOFF];    // q * 32
__device__ __half g_k  [2*QOFF];    // k * 32
__device__ __half g_vts[2*VOFF];    // v^T * 32 [bh][d][m]
__device__ __half g_g  [2*GOFF];    // attn@v [b*N+n][c]
__device__ __half g_mx [2*MXOFF];   // raw mixed attn * 4096 [bh][n][m]
__device__ float  g_vt [VOFF];      // raw v^T
__device__ float  g_vc [BB*NH*HD];  // colsum of v per (bh, d)
__device__ float  g_logits[BB*NH*NSEQ*NSEQ];   // exp(SCALE*q.k)
__device__ float  g_rs[BB*NH*NSEQ];
__device__ double g_s1[NH];
__device__ double g_s2[NH];
__device__ float  g_bna[NH];
__device__ float  g_bnc[NH];

// ---------------- helpers -------------------------------------------------------
__device__ __forceinline__ uint32_t s2u(const void* p){
    uint32_t a;
    asm("{ .reg .u64 t; cvta.to.shared.u64 t, %1; cvt.u32.u64 %0, t; }" : "=r"(a) : "l"(p));
    return a;
}
__device__ __forceinline__ uint2 split2(float x0, float x1, float s){
    x0 *= s; x1 *= s;
    __half h0 = __float2half_rn(x0), h1 = __float2half_rn(x1);
    __half g0 = __float2half_rn(x0 - __half2float(h0));
    __half g1 = __float2half_rn(x1 - __half2float(h1));
    __half2 hh = __halves2half2(h0, h1), ll = __halves2half2(g0, g1);
    uint2 r;
    r.x = *(uint32_t*)&hh; r.y = *(uint32_t*)&ll;
    return r;
}
__device__ __forceinline__ void mma16f(float* c, const uint32_t* a, const uint32_t* b){
    asm volatile("mma.sync.aligned.m16n8k16.row.col.f32.f16.f16.f32 "
        "{%0,%1,%2,%3}, {%4,%5,%6,%7}, {%8,%9}, {%0,%1,%2,%3};"
        : "+f"(c[0]), "+f"(c[1]), "+f"(c[2]), "+f"(c[3])
        : "r"(a[0]), "r"(a[1]), "r"(a[2]), "r"(a[3]), "r"(b[0]), "r"(b[1]));
}
__device__ __forceinline__ void mma16h(uint32_t* c, const uint32_t* a, const uint32_t* b){
    asm volatile("mma.sync.aligned.m16n8k16.row.col.f16.f16.f16.f16 "
        "{%0,%1}, {%2,%3,%4,%5}, {%6,%7}, {%0,%1};"
        : "+r"(c[0]), "+r"(c[1])
        : "r"(a[0]), "r"(a[1]), "r"(a[2]), "r"(a[3]), "r"(b[0]), "r"(b[1]));
}
__device__ __forceinline__ void ldsm4(uint32_t& r0, uint32_t& r1, uint32_t& r2,
                                      uint32_t& r3, uint32_t addr){
    asm volatile("ldmatrix.sync.aligned.m8n8.x4.shared.b16 {%0,%1,%2,%3}, [%4];"
        : "=r"(r0), "=r"(r1), "=r"(r2), "=r"(r3) : "r"(addr));
}
__device__ __forceinline__ void cpa16(uint32_t dst, const void* src){
    asm volatile("cp.async.cg.shared.global [%0], [%1], 16;" :: "r"(dst), "l"(src));
}
#define CPA_COMMIT() asm volatile("cp.async.commit_group;" ::: "memory")
#define USWZ(row, kg) ((row)*64 + (((kg) ^ (((row)>>1)&3)) << 4))

// ---------------- init ----------------------------------------------------------
__global__ void k_init(){
    int i = blockIdx.x * blockDim.x + threadIdx.x;
    if (i < BB*NH*NSEQ) g_rs[i] = 0.f;
    if (i < BB*NH*HD)   g_vc[i] = 0.f;
    if (i < NH) { g_s1[i] = 0.0; g_s2[i] = 0.0; }
}

// ---------------- pre-split: fp32 -> hi/lo half planes ---------------------------
__global__ void k_split(const float* __restrict__ src, int n8, float s, int sel){
    int i = blockIdx.x * blockDim.x + threadIdx.x;
    if (i >= n8) return;
    const float* p = (sel == 3) ? g_vt : src;
    float4 a = *(const float4*)(p + 8*(size_t)i);
    float4 b = *(const float4*)(p + 8*(size_t)i + 4);
    uint2 u0 = split2(a.x, a.y, s), u1 = split2(a.z, a.w, s);
    uint2 u2 = split2(b.x, b.y, s), u3 = split2(b.z, b.w, s);
    __half* dh; size_t off;
    if (sel == 0)      { dh = g_x;   off = XOFF; }
    else if (sel == 1) { dh = g_wq;  off = WQOFF; }
    else if (sel == 2) { dh = g_wp;  off = WPOFF; }
    else               { dh = g_vts; off = VOFF; }
    uint4 vh = {u0.x, u1.x, u2.x, u3.x};
    uint4 vl = {u0.y, u1.y, u2.y, u3.y};
    *(uint4*)(dh + 8*(size_t)i)       = vh;
    *(uint4*)(dh + off + 8*(size_t)i) = vl;
    if (sel == 3) {
        float cs = (a.x+a.y+a.z+a.w) + (b.x+b.y+b.z+b.w);
        atomicAdd(&g_vc[(8*(size_t)i) >> 10], cs);
    }
}

// ---------------- ldmatrix MMA core: one k32 chunk -------------------------------
template<int NT, int MT>
__device__ __forceinline__ void mma_chunk_p(
    uint32_t ah_b, uint32_t alo, uint32_t bh_b, uint32_t blo,
    const int* rba, const int* swa, int kha,
    const int* rbb, const int* swb, int khb,
    float accf[MT][NT][4], uint32_t acch[MT][NT][2])
{
    #pragma unroll
    for (int ks = 0; ks < 2; ks++) {
        uint32_t ah[MT][4], al[MT][4], bh4[NT/2][4], bl4[NT/2][4];
        #pragma unroll
        for (int i = 0; i < MT; i++) {
            int kg = ks*2 + kha;
            uint32_t off = rba[i] + (((uint32_t)(kg ^ swa[i])) << 4);
            ldsm4(ah[i][0], ah[i][1], ah[i][2], ah[i][3], ah_b + off);
            ldsm4(al[i][0], al[i][1], al[i][2], al[i][3], ah_b + alo + off);
        }
        #pragma unroll
        for (int g = 0; g < NT/2; g++) {
            int kg = ks*2 + khb;
            uint32_t off = rbb[g] + (((uint32_t)(kg ^ swb[g])) << 4);
            ldsm4(bh4[g][0], bh4[g][1], bh4[g][2], bh4[g][3], bh_b + off);
            ldsm4(bl4[g][0], bl4[g][1], bl4[g][2], bl4[g][3], bh_b + blo + off);
        }
        #pragma unroll
        for (int g = 0; g < NT/2; g++) {
            #pragma unroll
            for (int jj = 0; jj < 2; jj++) {
                int j = g*2 + jj;
                uint32_t bh2[2] = {bh4[g][jj*2], bh4[g][jj*2+1]};
                uint32_t bl2[2] = {bl4[g][jj*2], bl4[g][jj*2+1]};
                #pragma unroll
                for (int i = 0; i < MT; i++) {
                    mma16f(accf[i][j], ah[i], bh2);
                    mma16h(acch[i][j], al[i], bh2);
                    mma16h(acch[i][j], ah[i], bl2);
                }
            }
        }
    }
}

// ---------------- fp16x3 GEMM ----------------------------------------------------
// MODE 0: qkv  A=g_x   B=g_wq  K=768  BM=128 -> q,k planes + raw v^T
// MODE 1: qk   A=g_q   B=g_k   K=64   BM=128 -> exp(SCALE*logit) + row-sum atomics
// MODE 2: av   A=g_mx  B=g_vts K=1024 BM=64  -> g_g planes + FUSED attn -> d_out
// MODE 3: proj A=g_g   B=g_wp  K=768  BM=128 -> d_out (+bias)
template<int MODE>
__global__ __launch_bounds__(256, (MODE==1 || MODE==2) ? 3 : 2) void gemm_h(
    const float* __restrict__ bias, float* __restrict__ pC)
{
    constexpr int BM = (MODE==2) ? 64 : 128;
    constexpr int BN = 64;
    constexpr int NT = 4, MT = BM / 64;
    constexpr int K   = (MODE==1) ? 64 : (MODE==2) ? 1024 : 768;
    constexpr int NC  = K / 32;
    constexpr int APL = BM * 64;            // bytes per A plane
    constexpr int BPL = BN * 64;            // bytes per B plane
    constexpr int STG = 2*APL + 2*BPL;      // stage size (24576 or 16384)

    extern __shared__ __align__(16) char smem[];

    const int tid  = threadIdx.x;
    const int lane = tid & 31, warp = tid >> 5;
    const int wm = warp >> 1, wn = warp & 1;
    const int gid = lane >> 2, tig = lane & 3;
    const int Mblk = blockIdx.y * BM;
    const int Nblk = blockIdx.x * BN;
    const int bh   = blockIdx.z;
    const uint32_t sb = s2u(smem);

    // per-lane ldmatrix address components
    int rba[MT], swa[MT], rbb[NT/2], swb[NT/2];
    const int rA  = (lane & 7) + ((lane & 8) ? 8 : 0);
    const int kha = (lane >> 4) & 1;
    #pragma unroll
    for (int i = 0; i < MT; i++) {
        int row = wm*(MT*16) + i*16 + rA;
        rba[i] = row*64; swa[i] = (row>>1)&3;
    }
    const int rB  = (lane & 7) + ((lane & 16) ? 8 : 0);
    const int khb = (lane >> 3) & 1;
    #pragma unroll
    for (int g = 0; g < NT/2; g++) {
        int row = wn*32 + g*16 + rB;
        rbb[g] = row*64; swb[g] = (row>>1)&3;
    }

    const __half *Ah_g, *Bh_g;
    constexpr size_t ALO = (MODE==0) ? XOFF : (MODE==1) ? QOFF :
                           (MODE==2) ? MXOFF : GOFF;
    constexpr size_t BLO = (MODE==0) ? WQOFF : (MODE==1) ? QOFF :
                           (MODE==2) ? VOFF : WPOFF;
    if constexpr (MODE == 0)      { Ah_g = g_x; Bh_g = g_wq; }
    else if constexpr (MODE == 1) { size_t o = (size_t)bh*NSEQ*HD;
                                    Ah_g = g_q + o; Bh_g = g_k + o; }
    else if constexpr (MODE == 2) { Ah_g = g_mx + (size_t)bh*NN;
                                    Bh_g = g_vts + (size_t)bh*HD*NSEQ; }
    else                          { Ah_g = g_g; Bh_g = g_wp; }

    // BN affine constants (MODE 2 only)
    float na = 0.f, ncs = 0.f, an = 0.f;
    if constexpr (MODE == 2) {
        int gg = bh % NH;
        na = g_bna[gg]; ncs = g_bnc[gg];
        an = na * (1.f / 4096.f);
    }

    float accf[MT][NT][4] = {};
    uint32_t acch[MT][NT][2] = {};

    // ======== 3-stage cp.async pipeline, one barrier per chunk ========
    {
        const int r0 = tid >> 2, kg = tid & 3;
        auto issue = [&](int ch, int s) {
            uint32_t base = sb + s*STG;
            #pragma unroll
            for (int i = 0; i < BM/64; i++) {
                int r = r0 + i*64;
                uint32_t d = base + USWZ(r, kg);
                const __half* src = Ah_g + (size_t)(Mblk + r)*K + ch*32 + kg*8;
                cpa16(d,       src);
                cpa16(d + APL, src + ALO);
            }
            {
                uint32_t d = base + 2*APL + USWZ(r0, kg);
                const __half* src = Bh_g + (size_t)(Nblk + r0)*K + ch*32 + kg*8;
                cpa16(d,       src);
                cpa16(d + BPL, src + BLO);
            }
            CPA_COMMIT();
        };
        issue(0, 0);
        if (NC > 1) issue(1, 1);
        int s_cur = 0, s_nxt2 = 2;
        for (int ch = 0; ch < NC; ch++) {
            if (ch < NC - 1) {
                asm volatile("cp.async.wait_group 1;" ::: "memory");
            } else {
                asm volatile("cp.async.wait_group 0;" ::: "memory");
            }
            __syncthreads();
            if (ch + 2 < NC) issue(ch + 2, s_nxt2);
            uint32_t base = sb + s_cur*STG;
            if constexpr (MODE == 2) {
                // FUSED attn output: read staged A tile (hi+lo) back, apply
                // bna/4096*(hi+lo)+bnc, stream to d_out attn slot.
                // thread t: row rr = t>>2 (0..63), kg unit kp = t&3 (8 m each)
                const int rr = tid >> 2;
                const int kp = tid & 3;
                uint32_t o0 = base + USWZ(rr, kp);
                uint4 hv = *(const uint4*)(smem + (o0 - sb));
                uint4 lv = *(const uint4*)(smem + (o0 - sb) + APL);
                float* dst = pC + OUT_OFF + (size_t)bh*NN
                           + (size_t)(Mblk + rr)*1024 + ch*32 + kp*8;
                const uint32_t hw[4] = {hv.x, hv.y, hv.z, hv.w};
                const uint32_t lw[4] = {lv.x, lv.y, lv.z, lv.w};
                #pragma unroll
                for (int q = 0; q < 2; q++) {
                    float4 r;
                    float2 a0 = __half22float2(*(__half2*)&hw[q*2+0]);
                    float2 b0 = __half22float2(*(__half2*)&lw[q*2+0]);
                    float2 a1 = __half22float2(*(__half2*)&hw[q*2+1]);
                    float2 b1 = __half22float2(*(__half2*)&lw[q*2+1]);
                    r.x = fmaf(an, a0.x + b0.x, ncs);
                    r.y = fmaf(an, a0.y + b0.y, ncs);
                    r.z = fmaf(an, a1.x + b1.x, ncs);
                    r.w = fmaf(an, a1.y + b1.y, ncs);
                    __stcs((float4*)(dst + q*4), r);
                }
            }
            mma_chunk_p<NT, MT>(base, APL, base + 2*APL, BPL,
                                rba, swa, kha, rbb, swb, khb, accf, acch);
            s_cur = (s_cur == 2) ? 0 : s_cur + 1;
            s_nxt2 = (s_nxt2 == 2) ? 0 : s_nxt2 + 1;
        }
        __syncthreads();
    }

    // ----------------- epilogue -----------------
    // UN: qkv 2^-14 (16*1024); qk 2^-10 (32*32); av 2^-17 (4096*32); proj 2^-10
    constexpr float UN = (MODE==0) ? (1.f/16384.f) : (MODE==2) ? (1.f/131072.f)
                                                               : (1.f/1024.f);
    if constexpr (MODE == 1) {
        #pragma unroll
        for (int i = 0; i < MT; i++) {
            #pragma unroll
            for (int p = 0; p < 2; p++) {
                const int row = Mblk + wm*(MT*16) + i*16 + gid + p*8;
                float rsum = 0.f;
                #pragma unroll
                for (int j = 0; j < NT; j++) {
                    __half2 q = *(__half2*)&acch[i][j][p];
                    float2 cc = __half22float2(q);
                    float v0 = (accf[i][j][p*2+0] + cc.x) * UN;
                    float v1 = (accf[i][j][p*2+1] + cc.y) * UN;
                    float e0 = __expf(SCALE * v0);
                    float e1 = __expf(SCALE * v1);
                    int c0 = Nblk + wn*32 + j*8 + tig*2;
                    __stcs((float2*)(g_logits + (size_t)bh*NN + (size_t)row*NSEQ + c0),
                           make_float2(e0, e1));
                    rsum += e0 + e1;
                }
                rsum += __shfl_xor_sync(0xffffffffu, rsum, 1);
                rsum += __shfl_xor_sync(0xffffffffu, rsum, 2);
                if (tig == 0)
                    atomicAdd(&g_rs[(size_t)bh*NSEQ + row], rsum);
            }
        }
    } else {
        #pragma unroll
        for (int i = 0; i < MT; i++) {
            #pragma unroll
            for (int j = 0; j < NT; j++) {
                __half2 q0 = *(__half2*)&acch[i][j][0];
                __half2 q1 = *(__half2*)&acch[i][j][1];
                float2 c01 = __half22float2(q0);
                float2 c23 = __half22float2(q1);
                float cv[4] = {accf[i][j][0] + c01.x, accf[i][j][1] + c01.y,
                               accf[i][j][2] + c23.x, accf[i][j][3] + c23.y};
                int r0 = Mblk + wm*(MT*16) + i*16 + gid;
                int c0 = Nblk + wn*32 + j*8 + tig*2;
                #pragma unroll
                for (int p = 0; p < 2; p++) {
                    int row = r0 + p*8;
                    float v0 = cv[p*2+0] * UN, v1 = cv[p*2+1] * UN;
                    if constexpr (MODE == 0) {
                        int t3 = c0 / CDIM; int rem = c0 - t3*CDIM;
                        int h = rem >> 6, d = rem & 63;
                        int b = row >> 10, n = row & (NSEQ - 1);
                        v0 += bias[c0]; v1 += bias[c0+1];
                        if (t3 < 2) {
                            uint2 sp = split2(v0, v1, 32.f);
                            size_t idx = ((((size_t)(b*NH+h))*NSEQ + n) << 6) + d;
                            __half* dst = (t3 == 0) ? g_q : g_k;
                            *(uint32_t*)(dst + idx)        = sp.x;
                            *(uint32_t*)(dst + QOFF + idx) = sp.y;
                        } else {
                            size_t base = (((size_t)(b*NH+h))*HD + d)*NSEQ + n;
                            g_vt[base]        = v0;
                            g_vt[base + NSEQ] = v1;
                        }
                    } else if constexpr (MODE == 2) {
                        // out = bna*(mix@v) + bnc*colsum(v)
                        int b = bh / NH, g = bh % NH;
                        float w0 = fmaf(na, v0, ncs * g_vc[bh*HD + c0]);
                        float w1 = fmaf(na, v1, ncs * g_vc[bh*HD + c0 + 1]);
                        uint2 sp = split2(w0, w1, 1.f);
                        size_t idx = ((size_t)(b*NSEQ + row))*CDIM + g*HD + c0;
                        *(uint32_t*)(g_g + idx)        = sp.x;
                        *(uint32_t*)(g_g + GOFF + idx) = sp.y;
                    } else {
                        float2 s = make_float2(v0 + bias[c0], v1 + bias[c0+1]);
                        *(float2*)(pC + (size_t)row*CDIM + c0) = s;
                    }
                }
            }
        }
    }
}

// ---------------- streaming softmax-finish + head mix + BN stats ---------------
// writes raw mixed attn as SPLIT fp16 planes (x4096) into g_mx
__global__ void k_mix(const float* __restrict__ w_re, const float* __restrict__ b_re) {
    __shared__ float wre[NH][NH];
    __shared__ float bre[NH], sinv[NH];
    __shared__ float sm1[NH], sm2[NH];
    const int b = blockIdx.x >> 10;
    const int n = blockIdx.x & 1023;
    const int t = threadIdx.x;               // 256
    const int lane = t & 31;
    if (t < NH*NH) wre[t/NH][t%NH] = w_re[t];
    if (t < NH) {
        bre[t] = b_re[t];
        sinv[t] = 1.0f / g_rs[((size_t)(b*NH + t))*NSEQ + n];
        sm1[t] = 0.f; sm2[t] = 0.f;
    }
    __syncthreads();
    const int m = t << 2;
    float L[NH][4];
    #pragma unroll
    for (int h = 0; h < NH; h++) {
        float4 e = __ldcs((const float4*)(g_logits +
                      (((size_t)(b*NH+h))*NSEQ + n)*NSEQ + m));
        float si = sinv[h];
        L[h][0] = e.x*si; L[h][1] = e.y*si; L[h][2] = e.z*si; L[h][3] = e.w*si;
    }
    #pragma unroll
    for (int g = 0; g < NH; g++) {
        float o0=bre[g], o1=bre[g], o2=bre[g], o3=bre[g];
        #pragma unroll
        for (int h = 0; h < NH; h++) {
            float w = wre[g][h];
            o0 = fmaf(w, L[h][0], o0); o1 = fmaf(w, L[h][1], o1);
            o2 = fmaf(w, L[h][2], o2); o3 = fmaf(w, L[h][3], o3);
        }
        size_t idx = (((size_t)(b*NH+g))*NSEQ + n)*NSEQ + m;
        uint2 u01 = split2(o0, o1, 4096.f);
        uint2 u23 = split2(o2, o3, 4096.f);
        uint2 sh = {u01.x, u23.x};
        uint2 sl = {u01.y, u23.y};
        __stcs((uint2*)(g_mx + idx), sh);
        __stcs((uint2*)(g_mx + MXOFF + idx), sl);
        float a = (o0+o1)+(o2+o3);
        float c = o0*o0+o1*o1+o2*o2+o3*o3;
        #pragma unroll
        for (int o = 16; o; o >>= 1) {
            a += __shfl_xor_sync(0xffffffffu, a, o);
            c += __shfl_xor_sync(0xffffffffu, c, o);
        }
        if (lane == 0) { atomicAdd(&sm1[g], a); atomicAdd(&sm2[g], c); }
    }
    __syncthreads();
    if (t < NH) {
        atomicAdd(&g_s1[t], (double)sm1[t]);
        atomicAdd(&g_s2[t], (double)sm2[t]);
    }
}

// ---------------- BN finalize (double precision) --------------------------------
__global__ void k_bnfin(const float* __restrict__ gamma, const float* __restrict__ beta) {
    int g = threadIdx.x;
    if (g < NH) {
        double cnt = (double)BB * NSEQ * NSEQ;
        double mean = g_s1[g] / cnt;
        double var  = g_s2[g] / cnt - mean * mean;
        float a = (float)((double)gamma[g] / sqrt(var + (double)BNEPS));
        g_bna[g] = a;
        g_bnc[g] = beta[g] - a * (float)mean;
    }
}

// ---------------- launcher --------------------------------------------------------
extern "C" void kernel_launch(void* const* d_in, const int* in_sizes, int n_in,
                              void* d_out, int out_size) {
    const float* x    = (const float*)d_in[0];
    const float* wqkv = (const float*)d_in[1];
    const float* bqkv = (const float*)d_in[2];
    const float* wre  = (const float*)d_in[3];
    const float* bre  = (const float*)d_in[4];
    const float* gam  = (const float*)d_in[5];
    const float* bet  = (const float*)d_in[6];
    const float* wp   = (const float*)d_in[7];
    const float* bp   = (const float*)d_in[8];
    float* out = (float*)d_out;

    const int SMA = 3 * 24576;                 // 73728 (BM=128 modes)
    const int SMB = 3 * 16384;                 // 49152 (BM=64 mode 2)
    cudaFuncSetAttribute(gemm_h<0>, cudaFuncAttributeMaxDynamicSharedMemorySize, SMA);
    cudaFuncSetAttribute(gemm_h<1>, cudaFuncAttributeMaxDynamicSharedMemorySize, SMA);
    cudaFuncSetAttribute(gemm_h<2>, cudaFuncAttributeMaxDynamicSharedMemorySize, SMB);
    cudaFuncSetAttribute(gemm_h<3>, cudaFuncAttributeMaxDynamicSharedMemorySize, SMA);

    k_init<<<96, 1024>>>();                                           // 1
    k_split<<<3072, 256>>>(x,    786432, 16.f,   0);                  // 2: x
    k_split<<<864,  256>>>(wqkv, 221184, 1024.f, 1);                  // 3: w_qkv
    gemm_h<0><<<dim3(36, 64, 1), 256, SMA>>>(bqkv, nullptr);          // 4: qkv (PROFILED)
    k_split<<<288,  256>>>(wp,    73728, 1024.f, 2);                  // 5: w_proj
    k_split<<<3072, 256>>>(nullptr, 786432, 32.f, 3);                 // 6: v^T + colsum
    gemm_h<1><<<dim3(16, 8, 96), 256, SMA>>>(nullptr, nullptr);       // 7: qk
    k_mix<<<8192, 256>>>(wre, bre);                                   // 8: mix -> planes
    k_bnfin<<<1, 32>>>(gam, bet);                                     // 9
    gemm_h<2><<<dim3(1, 16, 96), 256, SMB>>>(nullptr, out);           // 10: av + attn out
    gemm_h<3><<<dim3(12, 64, 1), 256, SMA>>>(bp, out);                // 11: proj
}

// round 14
// speedup vs baseline: 2.1032x; 1.0214x over previous
#include <cuda_runtime.h>
#include <cuda_fp16.h>
#include <math.h>
#include <stdint.h>

#define BB 8
#define NSEQ 1024
#define CDIM 768
#define NH 12
#define HD 64
#define SCALE 0.125f
#define BNEPS 1e-5f
#define OUT_OFF (BB*NSEQ*CDIM)
#define NN ((size_t)NSEQ*NSEQ)

// plane sizes (hi plane at [0], lo plane at [OFF])
#define XOFF  (BB*NSEQ*CDIM)      // 6291456
#define WQOFF (3*CDIM*CDIM)       // 1769472
#define WPOFF (CDIM*CDIM)         // 589824
#define QOFF  (BB*NH*NSEQ*HD)     // 6291456
#define VOFF  (BB*NH*HD*NSEQ)     // 6291456
#define GOFF  (BB*NSEQ*CDIM)      // 6291456
#define MXOFF ((size_t)BB*NH*NSEQ*NSEQ)   // 100663296

// ---------------- scratch: merged hi/lo half planes ----------------------------
__device__ __half g_x  [2*XOFF];    // x * 16
__device__ __half g_wq [2*WQOFF];   // w_qkv * 1024
__device__ __half g_wp [2*WPOFF];   // w_proj * 1024
__device__ __half g_q  [2*QOFF];    // q * 32
__device__ __half g_k  [2*QOFF];    // k * 32
__device__ __half g_vts[2*VOFF];    // v^T * 32 [bh][d][m]
__device__ __half g_g  [2*GOFF];    // attn@v [b*N+n][c]
__device__ __half g_mx [2*MXOFF];   // raw mixed attn * 4096 [bh][n][m]
__device__ float  g_vt [VOFF];      // raw v^T
__device__ float  g_vc [BB*NH*HD];  // colsum of v per (bh, d)
__device__ float  g_logits[BB*NH*NSEQ*NSEQ];   // exp(SCALE*q.k)
__device__ float  g_rs[BB*NH*NSEQ];
__device__ double g_s1[NH];
__device__ double g_s2[NH];
__device__ float  g_bna[NH];
__device__ float  g_bnc[NH];

// ---------------- helpers -------------------------------------------------------
__device__ __forceinline__ uint32_t s2u(const void* p){
    uint32_t a;
    asm("{ .reg .u64 t; cvta.to.shared.u64 t, %1; cvt.u32.u64 %0, t; }" : "=r"(a) : "l"(p));
    return a;
}
__device__ __forceinline__ uint2 split2(float x0, float x1, float s){
    x0 *= s; x1 *= s;
    __half h0 = __float2half_rn(x0), h1 = __float2half_rn(x1);
    __half g0 = __float2half_rn(x0 - __half2float(h0));
    __half g1 = __float2half_rn(x1 - __half2float(h1));
    __half2 hh = __halves2half2(h0, h1), ll = __halves2half2(g0, g1);
    uint2 r;
    r.x = *(uint32_t*)&hh; r.y = *(uint32_t*)&ll;
    return r;
}
__device__ __forceinline__ void mma16f(float* c, const uint32_t* a, const uint32_t* b){
    asm volatile("mma.sync.aligned.m16n8k16.row.col.f32.f16.f16.f32 "
        "{%0,%1,%2,%3}, {%4,%5,%6,%7}, {%8,%9}, {%0,%1,%2,%3};"
        : "+f"(c[0]), "+f"(c[1]), "+f"(c[2]), "+f"(c[3])
        : "r"(a[0]), "r"(a[1]), "r"(a[2]), "r"(a[3]), "r"(b[0]), "r"(b[1]));
}
__device__ __forceinline__ void mma16h(uint32_t* c, const uint32_t* a, const uint32_t* b){
    asm volatile("mma.sync.aligned.m16n8k16.row.col.f16.f16.f16.f16 "
        "{%0,%1}, {%2,%3,%4,%5}, {%6,%7}, {%0,%1};"
        : "+r"(c[0]), "+r"(c[1])
        : "r"(a[0]), "r"(a[1]), "r"(a[2]), "r"(a[3]), "r"(b[0]), "r"(b[1]));
}
__device__ __forceinline__ void ldsm4(uint32_t& r0, uint32_t& r1, uint32_t& r2,
                                      uint32_t& r3, uint32_t addr){
    asm volatile("ldmatrix.sync.aligned.m8n8.x4.shared.b16 {%0,%1,%2,%3}, [%4];"
        : "=r"(r0), "=r"(r1), "=r"(r2), "=r"(r3) : "r"(addr));
}
__device__ __forceinline__ void cpa16(uint32_t dst, const void* src){
    asm volatile("cp.async.cg.shared.global [%0], [%1], 16;" :: "r"(dst), "l"(src));
}
#define CPA_COMMIT() asm volatile("cp.async.commit_group;" ::: "memory")
#define USWZ(row, kg) ((row)*64 + (((kg) ^ (((row)>>1)&3)) << 4))

// ---------------- init ----------------------------------------------------------
__global__ void k_init(){
    int i = blockIdx.x * blockDim.x + threadIdx.x;
    if (i < BB*NH*NSEQ) g_rs[i] = 0.f;
    if (i < BB*NH*HD)   g_vc[i] = 0.f;
    if (i < NH) { g_s1[i] = 0.0; g_s2[i] = 0.0; }
}

// ---------------- pre-split: fp32 -> hi/lo half planes ---------------------------
__global__ void k_split(const float* __restrict__ src, int n8, float s, int sel){
    int i = blockIdx.x * blockDim.x + threadIdx.x;
    if (i >= n8) return;
    const float* p = (sel == 3) ? g_vt : src;
    float4 a = *(const float4*)(p + 8*(size_t)i);
    float4 b = *(const float4*)(p + 8*(size_t)i + 4);
    uint2 u0 = split2(a.x, a.y, s), u1 = split2(a.z, a.w, s);
    uint2 u2 = split2(b.x, b.y, s), u3 = split2(b.z, b.w, s);
    __half* dh; size_t off;
    if (sel == 0)      { dh = g_x;   off = XOFF; }
    else if (sel == 1) { dh = g_wq;  off = WQOFF; }
    else if (sel == 2) { dh = g_wp;  off = WPOFF; }
    else               { dh = g_vts; off = VOFF; }
    uint4 vh = {u0.x, u1.x, u2.x, u3.x};
    uint4 vl = {u0.y, u1.y, u2.y, u3.y};
    *(uint4*)(dh + 8*(size_t)i)       = vh;
    *(uint4*)(dh + off + 8*(size_t)i) = vl;
    if (sel == 3) {
        float cs = (a.x+a.y+a.z+a.w) + (b.x+b.y+b.z+b.w);
        atomicAdd(&g_vc[(8*(size_t)i) >> 10], cs);
    }
}

// ---------------- ldmatrix MMA core: one k32 chunk -------------------------------
template<int NT, int MT>
__device__ __forceinline__ void mma_chunk_p(
    uint32_t ah_b, uint32_t alo, uint32_t bh_b, uint32_t blo,
    const int* rba, const int* swa, int kha,
    const int* rbb, const int* swb, int khb,
    float accf[MT][NT][4], uint32_t acch[MT][NT][2])
{
    #pragma unroll
    for (int ks = 0; ks < 2; ks++) {
        uint32_t ah[MT][4], al[MT][4], bh4[NT/2][4], bl4[NT/2][4];
        #pragma unroll
        for (int i = 0; i < MT; i++) {
            int kg = ks*2 + kha;
            uint32_t off = rba[i] + (((uint32_t)(kg ^ swa[i])) << 4);
            ldsm4(ah[i][0], ah[i][1], ah[i][2], ah[i][3], ah_b + off);
            ldsm4(al[i][0], al[i][1], al[i][2], al[i][3], ah_b + alo + off);
        }
        #pragma unroll
        for (int g = 0; g < NT/2; g++) {
            int kg = ks*2 + khb;
            uint32_t off = rbb[g] + (((uint32_t)(kg ^ swb[g])) << 4);
            ldsm4(bh4[g][0], bh4[g][1], bh4[g][2], bh4[g][3], bh_b + off);
            ldsm4(bl4[g][0], bl4[g][1], bl4[g][2], bl4[g][3], bh_b + blo + off);
        }
        #pragma unroll
        for (int g = 0; g < NT/2; g++) {
            #pragma unroll
            for (int jj = 0; jj < 2; jj++) {
                int j = g*2 + jj;
                uint32_t bh2[2] = {bh4[g][jj*2], bh4[g][jj*2+1]};
                uint32_t bl2[2] = {bl4[g][jj*2], bl4[g][jj*2+1]};
                #pragma unroll
                for (int i = 0; i < MT; i++) {
                    mma16f(accf[i][j], ah[i], bh2);
                    mma16h(acch[i][j], al[i], bh2);
                    mma16h(acch[i][j], ah[i], bl2);
                }
            }
        }
    }
}

// ---------------- fp16x3 GEMM ----------------------------------------------------
// MODE 0: qkv  A=g_x   B=g_wq  K=768  BM=128 pipelined -> q,k planes + raw v^T
// MODE 1: qk   A=g_q   B=g_k   K=64   BM=128 SINGLE-SHOT -> exp + row-sum atomics
// MODE 2: av   A=g_mx  B=g_vts K=1024 BM=64 pipelined -> g_g + FUSED attn -> d_out
// MODE 3: proj A=g_g   B=g_wp  K=768  BM=64 pipelined -> d_out (+bias)
template<int MODE>
__global__ __launch_bounds__(256, (MODE==0) ? 2 : 3) void gemm_h(
    const float* __restrict__ bias, float* __restrict__ pC)
{
    constexpr int BM = (MODE==2 || MODE==3) ? 64 : 128;
    constexpr int BN = 64;
    constexpr int NT = 4, MT = BM / 64;
    constexpr int K   = (MODE==1) ? 64 : (MODE==2) ? 1024 : 768;
    constexpr int NC  = K / 32;
    constexpr int APL = BM * 64;            // bytes per A plane
    constexpr int BPL = BN * 64;            // bytes per B plane
    constexpr int STG = 2*APL + 2*BPL;      // stage size

    extern __shared__ __align__(16) char smem[];

    const int tid  = threadIdx.x;
    const int lane = tid & 31, warp = tid >> 5;
    const int wm = warp >> 1, wn = warp & 1;
    const int gid = lane >> 2, tig = lane & 3;
    const int Mblk = blockIdx.y * BM;
    const int Nblk = blockIdx.x * BN;
    const int bh   = blockIdx.z;
    const uint32_t sb = s2u(smem);

    // per-lane ldmatrix address components
    int rba[MT], swa[MT], rbb[NT/2], swb[NT/2];
    const int rA  = (lane & 7) + ((lane & 8) ? 8 : 0);
    const int kha = (lane >> 4) & 1;
    #pragma unroll
    for (int i = 0; i < MT; i++) {
        int row = wm*(MT*16) + i*16 + rA;
        rba[i] = row*64; swa[i] = (row>>1)&3;
    }
    const int rB  = (lane & 7) + ((lane & 16) ? 8 : 0);
    const int khb = (lane >> 3) & 1;
    #pragma unroll
    for (int g = 0; g < NT/2; g++) {
        int row = wn*32 + g*16 + rB;
        rbb[g] = row*64; swb[g] = (row>>1)&3;
    }

    const __half *Ah_g, *Bh_g;
    constexpr size_t ALO = (MODE==0) ? XOFF : (MODE==1) ? QOFF :
                           (MODE==2) ? MXOFF : GOFF;
    constexpr size_t BLO = (MODE==0) ? WQOFF : (MODE==1) ? QOFF :
                           (MODE==2) ? VOFF : WPOFF;
    if constexpr (MODE == 0)      { Ah_g = g_x; Bh_g = g_wq; }
    else if constexpr (MODE == 1) { size_t o = (size_t)bh*NSEQ*HD;
                                    Ah_g = g_q + o; Bh_g = g_k + o; }
    else if constexpr (MODE == 2) { Ah_g = g_mx + (size_t)bh*NN;
                                    Bh_g = g_vts + (size_t)bh*HD*NSEQ; }
    else                          { Ah_g = g_g; Bh_g = g_wp; }

    // BN affine constants (MODE 2 only)
    float na = 0.f, ncs = 0.f, an = 0.f;
    if constexpr (MODE == 2) {
        int gg = bh % NH;
        na = g_bna[gg]; ncs = g_bnc[gg];
        an = na * (1.f / 4096.f);
    }

    float accf[MT][NT][4] = {};
    uint32_t acch[MT][NT][2] = {};

    {
        const int r0 = tid >> 2, kg = tid & 3;
        auto issue = [&](int ch, int s) {
            uint32_t base = sb + s*STG;
            #pragma unroll
            for (int i = 0; i < BM/64; i++) {
                int r = r0 + i*64;
                uint32_t d = base + USWZ(r, kg);
                const __half* src = Ah_g + (size_t)(Mblk + r)*K + ch*32 + kg*8;
                cpa16(d,       src);
                cpa16(d + APL, src + ALO);
            }
            {
                uint32_t d = base + 2*APL + USWZ(r0, kg);
                const __half* src = Bh_g + (size_t)(Nblk + r0)*K + ch*32 + kg*8;
                cpa16(d,       src);
                cpa16(d + BPL, src + BLO);
            }
            CPA_COMMIT();
        };
        if constexpr (MODE == 1) {
            // ======== single-shot: both K-chunks resident, one barrier ========
            issue(0, 0);
            issue(1, 1);
            asm volatile("cp.async.wait_group 0;" ::: "memory");
            __syncthreads();
            mma_chunk_p<NT, MT>(sb,       APL, sb + 2*APL,       BPL,
                                rba, swa, kha, rbb, swb, khb, accf, acch);
            mma_chunk_p<NT, MT>(sb + STG, APL, sb + STG + 2*APL, BPL,
                                rba, swa, kha, rbb, swb, khb, accf, acch);
        } else {
            // ======== 3-stage cp.async pipeline, one barrier per chunk ========
            issue(0, 0);
            issue(1, 1);
            int s_cur = 0, s_nxt2 = 2;
            for (int ch = 0; ch < NC; ch++) {
                if (ch < NC - 1) {
                    asm volatile("cp.async.wait_group 1;" ::: "memory");
                } else {
                    asm volatile("cp.async.wait_group 0;" ::: "memory");
                }
                __syncthreads();
                if (ch + 2 < NC) issue(ch + 2, s_nxt2);
                uint32_t base = sb + s_cur*STG;
                if constexpr (MODE == 2) {
                    // FUSED attn output: read staged A tile (hi+lo), apply
                    // bna/4096*(hi+lo)+bnc, stream to d_out attn slot.
                    const int rr = tid >> 2;
                    const int kp = tid & 3;
                    uint32_t o0 = base + USWZ(rr, kp);
                    uint4 hv = *(const uint4*)(smem + (o0 - sb));
                    uint4 lv = *(const uint4*)(smem + (o0 - sb) + APL);
                    float* dst = pC + OUT_OFF + (size_t)bh*NN
                               + (size_t)(Mblk + rr)*1024 + ch*32 + kp*8;
                    const uint32_t hw[4] = {hv.x, hv.y, hv.z, hv.w};
                    const uint32_t lw[4] = {lv.x, lv.y, lv.z, lv.w};
                    #pragma unroll
                    for (int q = 0; q < 2; q++) {
                        float4 r;
                        float2 a0 = __half22float2(*(__half2*)&hw[q*2+0]);
                        float2 b0 = __half22float2(*(__half2*)&lw[q*2+0]);
                        float2 a1 = __half22float2(*(__half2*)&hw[q*2+1]);
                        float2 b1 = __half22float2(*(__half2*)&lw[q*2+1]);
                        r.x = fmaf(an, a0.x + b0.x, ncs);
                        r.y = fmaf(an, a0.y + b0.y, ncs);
                        r.z = fmaf(an, a1.x + b1.x, ncs);
                        r.w = fmaf(an, a1.y + b1.y, ncs);
                        __stcs((float4*)(dst + q*4), r);
                    }
                }
                mma_chunk_p<NT, MT>(base, APL, base + 2*APL, BPL,
                                    rba, swa, kha, rbb, swb, khb, accf, acch);
                s_cur = (s_cur == 2) ? 0 : s_cur + 1;
                s_nxt2 = (s_nxt2 == 2) ? 0 : s_nxt2 + 1;
            }
            __syncthreads();
        }
    }

    // ----------------- epilogue -----------------
    // UN: qkv 2^-14 (16*1024); qk 2^-10 (32*32); av 2^-17 (4096*32); proj 2^-10
    constexpr float UN = (MODE==0) ? (1.f/16384.f) : (MODE==2) ? (1.f/131072.f)
                                                               : (1.f/1024.f);
    if constexpr (MODE == 1) {
        #pragma unroll
        for (int i = 0; i < MT; i++) {
            #pragma unroll
            for (int p = 0; p < 2; p++) {
                const int row = Mblk + wm*(MT*16) + i*16 + gid + p*8;
                float rsum = 0.f;
                #pragma unroll
                for (int j = 0; j < NT; j++) {
                    __half2 q = *(__half2*)&acch[i][j][p];
                    float2 cc = __half22float2(q);
                    float v0 = (accf[i][j][p*2+0] + cc.x) * UN;
                    float v1 = (accf[i][j][p*2+1] + cc.y) * UN;
                    float e0 = __expf(SCALE * v0);
                    float e1 = __expf(SCALE * v1);
                    int c0 = Nblk + wn*32 + j*8 + tig*2;
                    __stcs((float2*)(g_logits + (size_t)bh*NN + (size_t)row*NSEQ + c0),
                           make_float2(e0, e1));
                    rsum += e0 + e1;
                }
                rsum += __shfl_xor_sync(0xffffffffu, rsum, 1);
                rsum += __shfl_xor_sync(0xffffffffu, rsum, 2);
                if (tig == 0)
                    atomicAdd(&g_rs[(size_t)bh*NSEQ + row], rsum);
            }
        }
    } else {
        #pragma unroll
        for (int i = 0; i < MT; i++) {
            #pragma unroll
            for (int j = 0; j < NT; j++) {
                __half2 q0 = *(__half2*)&acch[i][j][0];
                __half2 q1 = *(__half2*)&acch[i][j][1];
                float2 c01 = __half22float2(q0);
                float2 c23 = __half22float2(q1);
                float cv[4] = {accf[i][j][0] + c01.x, accf[i][j][1] + c01.y,
                               accf[i][j][2] + c23.x, accf[i][j][3] + c23.y};
                int r0 = Mblk + wm*(MT*16) + i*16 + gid;
                int c0 = Nblk + wn*32 + j*8 + tig*2;
                #pragma unroll
                for (int p = 0; p < 2; p++) {
                    int row = r0 + p*8;
                    float v0 = cv[p*2+0] * UN, v1 = cv[p*2+1] * UN;
                    if constexpr (MODE == 0) {
                        int t3 = c0 / CDIM; int rem = c0 - t3*CDIM;
                        int h = rem >> 6, d = rem & 63;
                        int b = row >> 10, n = row & (NSEQ - 1);
                        v0 += bias[c0]; v1 += bias[c0+1];
                        if (t3 < 2) {
                            uint2 sp = split2(v0, v1, 32.f);
                            size_t idx = ((((size_t)(b*NH+h))*NSEQ + n) << 6) + d;
                            __half* dst = (t3 == 0) ? g_q : g_k;
                            *(uint32_t*)(dst + idx)        = sp.x;
                            *(uint32_t*)(dst + QOFF + idx) = sp.y;
                        } else {
                            size_t base = (((size_t)(b*NH+h))*HD + d)*NSEQ + n;
                            g_vt[base]        = v0;
                            g_vt[base + NSEQ] = v1;
                        }
                    } else if constexpr (MODE == 2) {
                        // out = bna*(mix@v) + bnc*colsum(v)
                        int b = bh / NH, g = bh % NH;
                        float w0 = fmaf(na, v0, ncs * g_vc[bh*HD + c0]);
                        float w1 = fmaf(na, v1, ncs * g_vc[bh*HD + c0 + 1]);
                        uint2 sp = split2(w0, w1, 1.f);
                        size_t idx = ((size_t)(b*NSEQ + row))*CDIM + g*HD + c0;
                        *(uint32_t*)(g_g + idx)        = sp.x;
                        *(uint32_t*)(g_g + GOFF + idx) = sp.y;
                    } else {
                        float2 s = make_float2(v0 + bias[c0], v1 + bias[c0+1]);
                        *(float2*)(pC + (size_t)row*CDIM + c0) = s;
                    }
                }
            }
        }
    }
}

// ---------------- streaming softmax-finish + head mix + BN stats ---------------
// writes raw mixed attn as SPLIT fp16 planes (x4096) into g_mx
__global__ void k_mix(const float* __restrict__ w_re, const float* __restrict__ b_re) {
    __shared__ float wre[NH][NH];
    __shared__ float bre[NH], sinv[NH];
    __shared__ float sm1[NH], sm2[NH];
    const int b = blockIdx.x >> 10;
    const int n = blockIdx.x & 1023;
    const int t = threadIdx.x;               // 256
    const int lane = t & 31;
    if (t < NH*NH) wre[t/NH][t%NH] = w_re[t];
    if (t < NH) {
        bre[t] = b_re[t];
        sinv[t] = 1.0f / g_rs[((size_t)(b*NH + t))*NSEQ + n];
        sm1[t] = 0.f; sm2[t] = 0.f;
    }
    __syncthreads();
    const int m = t << 2;
    float L[NH][4];
    #pragma unroll
    for (int h = 0; h < NH; h++) {
        float4 e = __ldcs((const float4*)(g_logits +
                      (((size_t)(b*NH+h))*NSEQ + n)*NSEQ + m));
        float si = sinv[h];
        L[h][0] = e.x*si; L[h][1] = e.y*si; L[h][2] = e.z*si; L[h][3] = e.w*si;
    }
    #pragma unroll
    for (int g = 0; g < NH; g++) {
        float o0=bre[g], o1=bre[g], o2=bre[g], o3=bre[g];
        #pragma unroll
        for (int h = 0; h < NH; h++) {
            float w = wre[g][h];
            o0 = fmaf(w, L[h][0], o0); o1 = fmaf(w, L[h][1], o1);
            o2 = fmaf(w, L[h][2], o2); o3 = fmaf(w, L[h][3], o3);
        }
        size_t idx = (((size_t)(b*NH+g))*NSEQ + n)*NSEQ + m;
        uint2 u01 = split2(o0, o1, 4096.f);
        uint2 u23 = split2(o2, o3, 4096.f);
        uint2 sh = {u01.x, u23.x};
        uint2 sl = {u01.y, u23.y};
        __stcs((uint2*)(g_mx + idx), sh);
        __stcs((uint2*)(g_mx + MXOFF + idx), sl);
        float a = (o0+o1)+(o2+o3);
        float c = o0*o0+o1*o1+o2*o2+o3*o3;
        #pragma unroll
        for (int o = 16; o; o >>= 1) {
            a += __shfl_xor_sync(0xffffffffu, a, o);
            c += __shfl_xor_sync(0xffffffffu, c, o);
        }
        if (lane == 0) { atomicAdd(&sm1[g], a); atomicAdd(&sm2[g], c); }
    }
    __syncthreads();
    if (t < NH) {
        atomicAdd(&g_s1[t], (double)sm1[t]);
        atomicAdd(&g_s2[t], (double)sm2[t]);
    }
}

// ---------------- BN finalize (double precision) --------------------------------
__global__ void k_bnfin(const float* __restrict__ gamma, const float* __restrict__ beta) {
    int g = threadIdx.x;
    if (g < NH) {
        double cnt = (double)BB * NSEQ * NSEQ;
        double mean = g_s1[g] / cnt;
        double var  = g_s2[g] / cnt - mean * mean;
        float a = (float)((double)gamma[g] / sqrt(var + (double)BNEPS));
        g_bna[g] = a;
        g_bnc[g] = beta[g] - a * (float)mean;
    }
}

// ---------------- launcher --------------------------------------------------------
extern "C" void kernel_launch(void* const* d_in, const int* in_sizes, int n_in,
                              void* d_out, int out_size) {
    const float* x    = (const float*)d_in[0];
    const float* wqkv = (const float*)d_in[1];
    const float* bqkv = (const float*)d_in[2];
    const float* wre  = (const float*)d_in[3];
    const float* bre  = (const float*)d_in[4];
    const float* gam  = (const float*)d_in[5];
    const float* bet  = (const float*)d_in[6];
    const float* wp   = (const float*)d_in[7];
    const float* bp   = (const float*)d_in[8];
    float* out = (float*)d_out;

    const int SM0 = 3 * 24576;   // 73728 (mode 0: BM=128, 3-stage)
    const int SM1 = 2 * 24576;   // 49152 (mode 1: BM=128, single-shot 2 stages)
    const int SM2 = 3 * 16384;   // 49152 (mode 2: BM=64, 3-stage)
    const int SM3 = 3 * 16384;   // 49152 (mode 3: BM=64, 3-stage)
    cudaFuncSetAttribute(gemm_h<0>, cudaFuncAttributeMaxDynamicSharedMemorySize, SM0);
    cudaFuncSetAttribute(gemm_h<1>, cudaFuncAttributeMaxDynamicSharedMemorySize, SM1);
    cudaFuncSetAttribute(gemm_h<2>, cudaFuncAttributeMaxDynamicSharedMemorySize, SM2);
    cudaFuncSetAttribute(gemm_h<3>, cudaFuncAttributeMaxDynamicSharedMemorySize, SM3);

    k_init<<<96, 1024>>>();                                           // 1
    k_split<<<3072, 256>>>(x,    786432, 16.f,   0);                  // 2: x
    k_split<<<864,  256>>>(wqkv, 221184, 1024.f, 1);                  // 3: w_qkv
    gemm_h<0><<<dim3(36, 64, 1), 256, SM0>>>(bqkv, nullptr);          // 4: qkv (PROFILED)
    k_split<<<288,  256>>>(wp,    73728, 1024.f, 2);                  // 5: w_proj
    k_split<<<3072, 256>>>(nullptr, 786432, 32.f, 3);                 // 6: v^T + colsum
    gemm_h<1><<<dim3(16, 8, 96), 256, SM1>>>(nullptr, nullptr);       // 7: qk
    k_mix<<<8192, 256>>>(wre, bre);                                   // 8: mix -> planes
    k_bnfin<<<1, 32>>>(gam, bet);                                     // 9
    gemm_h<2><<<dim3(1, 16, 96), 256, SM2>>>(nullptr, out);           // 10: av + attn out
    gemm_h<3><<<dim3(12, 128, 1), 256, SM3>>>(bp, out);               // 11: proj
}